// round 2
// baseline (speedup 1.0000x reference)
#include <cuda_runtime.h>
#include <cuda_bf16.h>
#include <math.h>

// Problem constants
#define LL   2048
#define HH   24
#define DD   128
#define HID  3072
#define MLPD 12288
#define NN1  21504   // 3*HID + MLP
#define NN2  15360   // HID + MLP
#define EPSF 1e-6f

// ---------------- scratch (static device arrays; no allocs) ----------------
__device__ float g_mod[3 * HID];                       // shift|scale|gate
__device__ float g_xmod[(size_t)LL * HID];             // 25 MB
__device__ float g_h[(size_t)LL * NN1];                // 176 MB  (qkv | mlp)
__device__ float g_scores[(size_t)HH * LL * LL];       // 402 MB
__device__ float g_oc[(size_t)LL * NN2];               // 126 MB  (attn | gelu(mlp))

// ---------------- kernel 1: mod = silu(vec) @ mod_w + mod_b ----------------
__global__ void mod_gemv(const float* __restrict__ vec,
                         const float* __restrict__ mod_w,
                         const float* __restrict__ mod_b) {
    __shared__ float sv[HID];
    int tid = threadIdx.x;
    for (int i = tid; i < HID; i += blockDim.x) {
        float a = vec[i];
        sv[i] = a / (1.f + __expf(-a));
    }
    __syncthreads();
    int j = blockIdx.x * blockDim.x + tid;
    float acc = 0.f;
    #pragma unroll 4
    for (int k = 0; k < HID; k++)
        acc += sv[k] * mod_w[(size_t)k * (3 * HID) + j];
    g_mod[j] = acc + mod_b[j];
}

// ---------------- kernel 2: layernorm + modulation ----------------
__global__ void ln_mod_kernel(const float* __restrict__ x,
                              const float* __restrict__ gamma,
                              const float* __restrict__ beta) {
    __shared__ float red[32];
    int l = blockIdx.x;
    const float* xr = x + (size_t)l * HID;
    float s = 0.f, s2 = 0.f;
    for (int i = threadIdx.x; i < HID; i += 256) {
        float v = xr[i];
        s += v; s2 += v * v;
    }
    int lane = threadIdx.x & 31, wid = threadIdx.x >> 5;
    #pragma unroll
    for (int o = 16; o; o >>= 1) { s += __shfl_down_sync(~0u, s, o); s2 += __shfl_down_sync(~0u, s2, o); }
    if (lane == 0) { red[wid] = s; red[wid + 8] = s2; }
    __syncthreads();
    float ts = 0.f, ts2 = 0.f;
    if (threadIdx.x < 8) { ts = red[threadIdx.x]; ts2 = red[threadIdx.x + 8]; }
    #pragma unroll
    for (int o = 4; o; o >>= 1) { ts += __shfl_down_sync(0xff, ts, o); ts2 += __shfl_down_sync(0xff, ts2, o); }
    if (threadIdx.x == 0) { red[0] = ts; red[1] = ts2; }
    __syncthreads();
    float mu = red[0] / HID;
    float var = red[1] / HID - mu * mu;
    float rsig = rsqrtf(var + EPSF);
    for (int i = threadIdx.x; i < HID; i += 256) {
        float lnv = (xr[i] - mu) * rsig * gamma[i] + beta[i];
        g_xmod[(size_t)l * HID + i] = (1.f + g_mod[HID + i]) * lnv + g_mod[i];
    }
}

// ---------------- bf16-split tensor-core GEMM ----------------
// fp32 emulated via 3-term bf16: x = hi + lo; A k-layout [hi|lo|hi], B [hi|hi|lo]
// => hi*hi + lo*hi + hi*lo accumulated in one K-extended pass.
// CTA tile 128x128, K-step 16 (fp32) -> 48 bf16. 128 threads, 4 warps of 64x64.
// EPI: 0=none, 1=+bias[n], 2=*alpha, 3=resid[m*HID+n] + gate[n]*(acc+bias[n])

__device__ __forceinline__ void bsplit(float v, __nv_bfloat16& h, __nv_bfloat16& l) {
    h = __float2bfloat16(v);
    l = __float2bfloat16(v - __bfloat162float(h));
}

__device__ __forceinline__ void mma16816(float* c, const unsigned* a, unsigned b0, unsigned b1) {
    asm volatile(
        "mma.sync.aligned.m16n8k16.row.col.f32.bf16.bf16.f32 "
        "{%0,%1,%2,%3},{%4,%5,%6,%7},{%8,%9},{%0,%1,%2,%3};\n"
        : "+f"(c[0]), "+f"(c[1]), "+f"(c[2]), "+f"(c[3])
        : "r"(a[0]), "r"(a[1]), "r"(a[2]), "r"(a[3]), "r"(b0), "r"(b1));
}

#define AP 56   // smem row pitch (bf16 elems): conflict-free

template<bool TB, int EPI>
__global__ void __launch_bounds__(128) tgemm(
    const float* __restrict__ A, int lda, long sA,
    const float* __restrict__ B, int ldb, long sB,
    float* __restrict__ C, int ldc, long sC,
    int K,
    const float* __restrict__ bias, float alpha,
    const float* __restrict__ resid, const float* __restrict__ gate)
{
    A += (long)blockIdx.z * sA;
    B += (long)blockIdx.z * sB;
    C += (long)blockIdx.z * sC;
    __shared__ __nv_bfloat16 As[128][AP];   // [m][ hi16 | lo16 | hi16 ]
    __shared__ __nv_bfloat16 Bs[128][AP];   // [n][ hi16 | hi16 | lo16 ]
    const int tid  = threadIdx.x;
    const int row0 = blockIdx.y * 128;
    const int col0 = blockIdx.x * 128;

    float4 ar[4], br[4];
    // initial stage (k0 = 0)
    #pragma unroll
    for (int i = 0; i < 4; i++) {
        int s = tid + i * 128;
        int r = s >> 2, q = s & 3;
        ar[i] = *(const float4*)&A[(size_t)(row0 + r) * lda + q * 4];
    }
    #pragma unroll
    for (int i = 0; i < 4; i++) {
        int s = tid + i * 128;
        if (TB) { int r = s >> 2, q = s & 3;  br[i] = *(const float4*)&B[(size_t)(col0 + r) * ldb + q * 4]; }
        else    { int kr = s >> 5, nq = s & 31; br[i] = *(const float4*)&B[(size_t)kr * ldb + col0 + nq * 4]; }
    }

    float acc[4][8][4] = {};
    const int wid = tid >> 5, lane = tid & 31;
    const int wm0 = (wid >> 1) * 64, wn0 = (wid & 1) * 64;
    const int gr = lane >> 2, qp = (lane & 3) * 2;

    for (int k0 = 0; k0 < K; k0 += 16) {
        // -- convert + store staged tile to smem --
        #pragma unroll
        for (int i = 0; i < 4; i++) {
            int s = tid + i * 128;
            int r = s >> 2, q = s & 3, kb = q * 4;
            float4 v = ar[i];
            __nv_bfloat16 h0, h1, h2, h3, l0, l1, l2, l3;
            bsplit(v.x, h0, l0); bsplit(v.y, h1, l1);
            bsplit(v.z, h2, l2); bsplit(v.w, h3, l3);
            *(__nv_bfloat162*)&As[r][kb]          = __halves2bfloat162(h0, h1);
            *(__nv_bfloat162*)&As[r][kb + 2]      = __halves2bfloat162(h2, h3);
            *(__nv_bfloat162*)&As[r][16 + kb]     = __halves2bfloat162(l0, l1);
            *(__nv_bfloat162*)&As[r][16 + kb + 2] = __halves2bfloat162(l2, l3);
            *(__nv_bfloat162*)&As[r][32 + kb]     = __halves2bfloat162(h0, h1);
            *(__nv_bfloat162*)&As[r][32 + kb + 2] = __halves2bfloat162(h2, h3);
        }
        #pragma unroll
        for (int i = 0; i < 4; i++) {
            int s = tid + i * 128;
            float4 v = br[i];
            __nv_bfloat16 h0, h1, h2, h3, l0, l1, l2, l3;
            bsplit(v.x, h0, l0); bsplit(v.y, h1, l1);
            bsplit(v.z, h2, l2); bsplit(v.w, h3, l3);
            if (TB) {
                int r = s >> 2, kb = (s & 3) * 4;
                *(__nv_bfloat162*)&Bs[r][kb]          = __halves2bfloat162(h0, h1);
                *(__nv_bfloat162*)&Bs[r][kb + 2]      = __halves2bfloat162(h2, h3);
                *(__nv_bfloat162*)&Bs[r][16 + kb]     = __halves2bfloat162(h0, h1);
                *(__nv_bfloat162*)&Bs[r][16 + kb + 2] = __halves2bfloat162(h2, h3);
                *(__nv_bfloat162*)&Bs[r][32 + kb]     = __halves2bfloat162(l0, l1);
                *(__nv_bfloat162*)&Bs[r][32 + kb + 2] = __halves2bfloat162(l2, l3);
            } else {
                int kr = s >> 5, n0 = (s & 31) * 4;
                __nv_bfloat16 hh[4] = {h0, h1, h2, h3}, llv[4] = {l0, l1, l2, l3};
                #pragma unroll
                for (int j = 0; j < 4; j++) {
                    Bs[n0 + j][kr]      = hh[j];
                    Bs[n0 + j][16 + kr] = hh[j];
                    Bs[n0 + j][32 + kr] = llv[j];
                }
            }
        }
        __syncthreads();

        // -- prefetch next tile into regs --
        if (k0 + 16 < K) {
            int kn = k0 + 16;
            #pragma unroll
            for (int i = 0; i < 4; i++) {
                int s = tid + i * 128;
                int r = s >> 2, q = s & 3;
                ar[i] = *(const float4*)&A[(size_t)(row0 + r) * lda + kn + q * 4];
            }
            #pragma unroll
            for (int i = 0; i < 4; i++) {
                int s = tid + i * 128;
                if (TB) { int r = s >> 2, q = s & 3;  br[i] = *(const float4*)&B[(size_t)(col0 + r) * ldb + kn + q * 4]; }
                else    { int kr = s >> 5, nq = s & 31; br[i] = *(const float4*)&B[(size_t)(kn + kr) * ldb + col0 + nq * 4]; }
            }
        }

        // -- compute 3 k16 chunks --
        #pragma unroll
        for (int kt = 0; kt < 3; kt++) {
            const int kk = kt * 16 + qp;
            unsigned a[4][4];
            #pragma unroll
            for (int im = 0; im < 4; im++) {
                int r = wm0 + im * 16 + gr;
                a[im][0] = *(const unsigned*)&As[r][kk];
                a[im][1] = *(const unsigned*)&As[r + 8][kk];
                a[im][2] = *(const unsigned*)&As[r][kk + 8];
                a[im][3] = *(const unsigned*)&As[r + 8][kk + 8];
            }
            #pragma unroll
            for (int in = 0; in < 8; in++) {
                int c = wn0 + in * 8 + gr;
                unsigned b0 = *(const unsigned*)&Bs[c][kk];
                unsigned b1 = *(const unsigned*)&Bs[c][kk + 8];
                #pragma unroll
                for (int im = 0; im < 4; im++)
                    mma16816(acc[im][in], a[im], b0, b1);
            }
        }
        __syncthreads();
    }

    // -- epilogue --
    #pragma unroll
    for (int im = 0; im < 4; im++) {
        #pragma unroll
        for (int in = 0; in < 8; in++) {
            #pragma unroll
            for (int e = 0; e < 4; e++) {
                int m = row0 + wm0 + im * 16 + gr + ((e >> 1) ? 8 : 0);
                int n = col0 + wn0 + in * 8 + qp + (e & 1);
                float v = acc[im][in][e];
                if (EPI == 1)      v += bias[n];
                else if (EPI == 2) v *= alpha;
                else if (EPI == 3) v = resid[(size_t)m * HID + n] + gate[n] * (v + bias[n]);
                C[(size_t)m * ldc + n] = v;
            }
        }
    }
}

// ---------------- rmsnorm + rope on q,k (in place in g_h) ----------------
__global__ void rmsnorm_rope(const float* __restrict__ pe,
                             const float* __restrict__ q_scale,
                             const float* __restrict__ k_scale) {
    int l = blockIdx.x, hd = blockIdx.y, which = blockIdx.z;
    const float* sc = which ? k_scale : q_scale;
    size_t base = (size_t)l * NN1 + (size_t)which * HID + (size_t)hd * DD;
    int d = threadIdx.x;   // 128 threads
    float t = g_h[base + d];
    __shared__ float red[4];
    float v = t * t;
    #pragma unroll
    for (int o = 16; o; o >>= 1) v += __shfl_down_sync(~0u, v, o);
    if ((d & 31) == 0) red[d >> 5] = v;
    __syncthreads();
    float ss = red[0] + red[1] + red[2] + red[3];
    float r = rsqrtf(ss / DD + EPSF);
    __shared__ float s[DD];
    s[d] = t * r * sc[d];
    __syncthreads();
    int i = d >> 1, j = d & 1;
    const float* p = pe + (((size_t)l * (DD / 2) + i) * 2 + j) * 2;
    g_h[base + d] = p[0] * s[2 * i] + p[1] * s[2 * i + 1];
}

// ---------------- softmax over rows of g_scores (in place) ----------------
__global__ void softmax_rows() {
    size_t row = blockIdx.x;
    float* p = g_scores + row * LL;
    __shared__ float red[8];
    int lane = threadIdx.x & 31, wid = threadIdx.x >> 5;

    float mx = -1e30f;
    for (int i = threadIdx.x; i < LL; i += 256) mx = fmaxf(mx, p[i]);
    #pragma unroll
    for (int o = 16; o; o >>= 1) mx = fmaxf(mx, __shfl_down_sync(~0u, mx, o));
    if (lane == 0) red[wid] = mx;
    __syncthreads();
    if (threadIdx.x < 8) {
        float m = red[threadIdx.x];
        #pragma unroll
        for (int o = 4; o; o >>= 1) m = fmaxf(m, __shfl_down_sync(0xff, m, o));
        if (threadIdx.x == 0) red[0] = m;
    }
    __syncthreads();
    mx = red[0];
    __syncthreads();

    float sum = 0.f;
    for (int i = threadIdx.x; i < LL; i += 256) {
        float e = __expf(p[i] - mx);
        p[i] = e; sum += e;
    }
    #pragma unroll
    for (int o = 16; o; o >>= 1) sum += __shfl_down_sync(~0u, sum, o);
    if (lane == 0) red[wid] = sum;
    __syncthreads();
    if (threadIdx.x < 8) {
        float t = red[threadIdx.x];
        #pragma unroll
        for (int o = 4; o; o >>= 1) t += __shfl_down_sync(0xff, t, o);
        if (threadIdx.x == 0) red[0] = t;
    }
    __syncthreads();
    float inv = 1.f / red[0];
    for (int i = threadIdx.x; i < LL; i += 256) p[i] *= inv;
}

// ---------------- gelu(mlp) -> g_oc second half ----------------
__global__ void gelu_copy() {
    size_t idx = (size_t)blockIdx.x * 256 + threadIdx.x;   // L*MLP total
    size_t l = idx / MLPD;
    size_t m = idx % MLPD;
    float v = g_h[l * NN1 + 3 * HID + m];
    float c = 0.7978845608028654f * (v + 0.044715f * v * v * v);
    g_oc[l * NN2 + HID + m] = 0.5f * v * (1.f + tanhf(c));
}

// ---------------- launcher ----------------
extern "C" void kernel_launch(void* const* d_in, const int* in_sizes, int n_in,
                              void* d_out, int out_size) {
    const float* x       = (const float*)d_in[0];
    const float* vec     = (const float*)d_in[1];
    const float* pe      = (const float*)d_in[2];
    const float* mod_w   = (const float*)d_in[3];
    const float* mod_b   = (const float*)d_in[4];
    const float* gamma   = (const float*)d_in[5];
    const float* beta    = (const float*)d_in[6];
    const float* w1      = (const float*)d_in[7];
    const float* b1      = (const float*)d_in[8];
    const float* q_scale = (const float*)d_in[9];
    const float* k_scale = (const float*)d_in[10];
    const float* w2      = (const float*)d_in[11];
    const float* b2      = (const float*)d_in[12];
    float* out = (float*)d_out;

    float *p_xmod, *p_h, *p_scores, *p_oc, *p_mod;
    cudaGetSymbolAddress((void**)&p_xmod,   g_xmod);
    cudaGetSymbolAddress((void**)&p_h,      g_h);
    cudaGetSymbolAddress((void**)&p_scores, g_scores);
    cudaGetSymbolAddress((void**)&p_oc,     g_oc);
    cudaGetSymbolAddress((void**)&p_mod,    g_mod);

    // 1) modulation GEMV
    mod_gemv<<<(3 * HID) / 256, 256>>>(vec, mod_w, mod_b);
    // 2) layernorm + modulation
    ln_mod_kernel<<<LL, 256>>>(x, gamma, beta);
    // 3) h = x_mod @ w1 + b1     (M=2048, N=21504, K=3072)
    tgemm<false, 1><<<dim3(NN1 / 128, LL / 128, 1), 128>>>(
        p_xmod, HID, 0, w1, NN1, 0, p_h, NN1, 0, HID, b1, 1.f, nullptr, nullptr);
    // 4) rmsnorm + rope on q and k (in place)
    rmsnorm_rope<<<dim3(LL, HH, 2), 128>>>(pe, q_scale, k_scale);
    // 5) scores = q @ k^T * D^-0.5   (batched over heads, NT)
    tgemm<true, 2><<<dim3(LL / 128, LL / 128, HH), 128>>>(
        p_h, NN1, 128, p_h + HID, NN1, 128,
        p_scores, LL, (long)LL * LL, DD, nullptr, 0.08838834764831845f, nullptr, nullptr);
    // 6) softmax
    softmax_rows<<<HH * LL, 256>>>();
    // 7) attn = P @ v  -> first HID cols of g_oc   (batched, NN)
    tgemm<false, 0><<<dim3(1, LL / 128, HH), 128>>>(
        p_scores, LL, (long)LL * LL, p_h + 2 * HID, NN1, 128,
        p_oc, NN2, 128, LL, nullptr, 1.f, nullptr, nullptr);
    // 8) gelu(mlp) -> rest of g_oc
    gelu_copy<<<((size_t)LL * MLPD) / 256, 256>>>();
    // 9) out = x + gate * (g_oc @ w2 + b2)   (M=2048, N=3072, K=15360)
    tgemm<false, 3><<<dim3(HID / 128, LL / 128, 1), 128>>>(
        p_oc, NN2, 0, w2, HID, 0, out, HID, 0, NN2,
        b2, 1.f, x, p_mod + 2 * HID);
}

// round 4
// speedup vs baseline: 3.4308x; 3.4308x over previous
#include <cuda_runtime.h>
#include <cuda_bf16.h>
#include <math.h>
#include <stdint.h>

// Problem constants
#define LL   2048
#define HH   24
#define DD   128
#define HID  3072
#define MLPD 12288
#define NN1  21504   // 3*HID + MLP
#define NN2  15360   // HID + MLP
#define EPSF 1e-6f

// ---------------- scratch (static device arrays; no allocs) ----------------
__device__ float g_mod[3 * HID];
__device__ __nv_bfloat16 g_xh[(size_t)LL * HID];
__device__ __nv_bfloat16 g_xl[(size_t)LL * HID];
__device__ __nv_bfloat16 g_w1h[(size_t)NN1 * HID];      // w1 transposed [N][K]
__device__ __nv_bfloat16 g_w1l[(size_t)NN1 * HID];
__device__ float g_h[(size_t)LL * NN1];                  // gemm1 out fp32
__device__ __nv_bfloat16 g_qh[(size_t)HH * LL * DD];
__device__ __nv_bfloat16 g_ql[(size_t)HH * LL * DD];
__device__ __nv_bfloat16 g_kh[(size_t)HH * LL * DD];
__device__ __nv_bfloat16 g_kl[(size_t)HH * LL * DD];
__device__ __nv_bfloat16 g_vth[(size_t)HH * DD * LL];   // V transposed per head [D][L]
__device__ __nv_bfloat16 g_vtl[(size_t)HH * DD * LL];
__device__ float g_scores[(size_t)HH * LL * LL];
__device__ __nv_bfloat16 g_ph[(size_t)HH * LL * LL];
__device__ __nv_bfloat16 g_pl[(size_t)HH * LL * LL];
__device__ __nv_bfloat16 g_och[(size_t)LL * NN2];
__device__ __nv_bfloat16 g_ocl[(size_t)LL * NN2];
__device__ __nv_bfloat16 g_w2h[(size_t)HID * NN2];      // w2 transposed [N][K]
__device__ __nv_bfloat16 g_w2l[(size_t)HID * NN2];

// ---------------- helpers ----------------
__device__ __forceinline__ uint32_t smem_u32(const void* p) {
    uint32_t a;
    asm("{ .reg .u64 t; cvta.to.shared.u64 t, %1; cvt.u32.u64 %0, t; }" : "=r"(a) : "l"(p));
    return a;
}
__device__ __forceinline__ void bsplit(float v, __nv_bfloat16& h, __nv_bfloat16& l) {
    h = __float2bfloat16(v);
    l = __float2bfloat16(v - __bfloat162float(h));
}
__device__ __forceinline__ void cpasync16(uint32_t dst, const void* src) {
    asm volatile("cp.async.cg.shared.global [%0], [%1], 16;" :: "r"(dst), "l"(src));
}
__device__ __forceinline__ void cp_commit() { asm volatile("cp.async.commit_group;"); }
__device__ __forceinline__ void cp_wait1()  { asm volatile("cp.async.wait_group 1;" ::: "memory"); }
__device__ __forceinline__ void cp_wait0()  { asm volatile("cp.async.wait_group 0;" ::: "memory"); }

__device__ __forceinline__ void ldsm4(uint32_t& r0, uint32_t& r1, uint32_t& r2, uint32_t& r3, uint32_t a) {
    asm volatile("ldmatrix.sync.aligned.m8n8.x4.shared.b16 {%0,%1,%2,%3}, [%4];"
                 : "=r"(r0), "=r"(r1), "=r"(r2), "=r"(r3) : "r"(a));
}
__device__ __forceinline__ void mma16816(float* c, const uint32_t* a, uint32_t b0, uint32_t b1) {
    asm volatile(
        "mma.sync.aligned.m16n8k16.row.col.f32.bf16.bf16.f32 "
        "{%0,%1,%2,%3},{%4,%5,%6,%7},{%8,%9},{%0,%1,%2,%3};\n"
        : "+f"(c[0]), "+f"(c[1]), "+f"(c[2]), "+f"(c[3])
        : "r"(a[0]), "r"(a[1]), "r"(a[2]), "r"(a[3]), "r"(b0), "r"(b1));
}

// ---------------- HMMA split-3 GEMM ----------------
// D[m][n] = sum_k A[m][k]*B[n][k]; fp32 via bf16 hi/lo: Ah*Bh + Al*Bh + Ah*Bl.
// CTA tile 128x128, K-chunk 64 bf16, double-buffered cp.async, swizzled smem.
// 8 warps: warp tile 32(m) x 64(n).
// EPI: 1 +bias | 2 *alpha | 3 resid + gate*(acc+bias) | 4 bf16-split to C2h/C2l
template<int EPI>
__global__ void __launch_bounds__(256, 1) hmma_gemm(
    const __nv_bfloat16* __restrict__ Ah, const __nv_bfloat16* __restrict__ Al, size_t lda, long sA,
    const __nv_bfloat16* __restrict__ Bh, const __nv_bfloat16* __restrict__ Bl, size_t ldb, long sB,
    float* __restrict__ C, size_t ldc, long sC, int K,
    const float* __restrict__ bias, float alpha,
    const float* __restrict__ resid, const float* __restrict__ gate,
    __nv_bfloat16* __restrict__ C2h, __nv_bfloat16* __restrict__ C2l, long sC2)
{
    extern __shared__ char smem[];
    constexpr int TILE = 128 * 128;      // 16 KB: 128 rows x 64 bf16
    constexpr int STAGE = 4 * TILE;      // Ah | Al | Bh | Bl
    const uint32_t sb = smem_u32(smem);
    const int tid = threadIdx.x, wid = tid >> 5, lane = tid & 31;
    const int wm = wid & 3, wn = wid >> 2;

    Ah += (long)blockIdx.z * sA;  Al += (long)blockIdx.z * sA;
    Bh += (long)blockIdx.z * sB;  Bl += (long)blockIdx.z * sB;
    if (EPI == 4) { C2h += (long)blockIdx.z * sC2; C2l += (long)blockIdx.z * sC2; }
    else          { C   += (long)blockIdx.z * sC; }

    const size_t row0 = (size_t)blockIdx.y * 128;
    const size_t col0 = (size_t)blockIdx.x * 128;
    const __nv_bfloat16* base[4] = { Ah + row0 * lda, Al + row0 * lda,
                                     Bh + col0 * ldb, Bl + col0 * ldb };
    const size_t lds[4] = { lda, lda, ldb, ldb };

    // per-thread load geometry: chunk c = tid + j*256; row = c>>3, k8 = c&7
    const int lrow = tid >> 3, lk8 = tid & 7;

    auto load_stage = [&](int s) {
        const uint32_t st = sb + (uint32_t)(s & 1) * STAGE;
        const int ko = s * 64;
        #pragma unroll
        for (int t = 0; t < 4; t++) {
            const __nv_bfloat16* g = base[t] + ko;
            const size_t ld = lds[t];
            #pragma unroll
            for (int j = 0; j < 4; j++) {
                int row = lrow + j * 32;
                uint32_t dst = st + t * TILE + row * 128 + ((lk8 ^ (row & 7)) << 4);
                cpasync16(dst, (const char*)(g + (size_t)row * ld) + lk8 * 16);
            }
        }
    };

    float acc[2][8][4] = {};
    const int S = K >> 6;

    load_stage(0); cp_commit();
    for (int s = 0; s < S; s++) {
        if (s + 1 < S) { load_stage(s + 1); cp_commit(); cp_wait1(); }
        else           { cp_wait0(); }
        __syncthreads();

        const uint32_t st = sb + (uint32_t)(s & 1) * STAGE;
        const uint32_t tAh = st, tAl = st + TILE, tBh = st + 2 * TILE, tBl = st + 3 * TILE;

        #pragma unroll
        for (int kg = 0; kg < 4; kg++) {
            // A fragments (hi & lo) for 2 m16 tiles
            uint32_t ah[2][4], al[2][4];
            {
                int arow = wm * 32 + (lane & 15);
                int ak8 = kg * 2 + (lane >> 4);
                #pragma unroll
                for (int im = 0; im < 2; im++) {
                    int r = arow + im * 16;
                    uint32_t off = r * 128 + ((ak8 ^ (r & 7)) << 4);
                    ldsm4(ah[im][0], ah[im][1], ah[im][2], ah[im][3], tAh + off);
                    ldsm4(al[im][0], al[im][1], al[im][2], al[im][3], tAl + off);
                }
            }
            // B fragments per n16 group
            int brow_b = wn * 64 + (lane & 7) + ((lane >> 4) << 3);
            int bk8 = kg * 2 + ((lane >> 3) & 1);
            #pragma unroll
            for (int g = 0; g < 4; g++) {
                int r = brow_b + g * 16;
                uint32_t off = r * 128 + ((bk8 ^ (r & 7)) << 4);
                uint32_t h0, h1, h2, h3, l0, l1, l2, l3;
                ldsm4(h0, h1, h2, h3, tBh + off);
                ldsm4(l0, l1, l2, l3, tBl + off);
                #pragma unroll
                for (int im = 0; im < 2; im++) {
                    mma16816(acc[im][2 * g],     ah[im], h0, h1);
                    mma16816(acc[im][2 * g + 1], ah[im], h2, h3);
                    mma16816(acc[im][2 * g],     al[im], h0, h1);
                    mma16816(acc[im][2 * g + 1], al[im], h2, h3);
                    mma16816(acc[im][2 * g],     ah[im], l0, l1);
                    mma16816(acc[im][2 * g + 1], ah[im], l2, l3);
                }
            }
        }
        __syncthreads();
    }

    // epilogue
    #pragma unroll
    for (int im = 0; im < 2; im++) {
        #pragma unroll
        for (int in = 0; in < 8; in++) {
            size_t m0 = row0 + wm * 32 + im * 16 + (lane >> 2);
            size_t n  = col0 + wn * 64 + in * 8 + (lane & 3) * 2;
            #pragma unroll
            for (int half = 0; half < 2; half++) {
                size_t m = m0 + half * 8;
                float v0 = acc[im][in][half * 2 + 0];
                float v1 = acc[im][in][half * 2 + 1];
                if (EPI == 4) {
                    __nv_bfloat16 h0, l0, h1, l1;
                    bsplit(v0, h0, l0); bsplit(v1, h1, l1);
                    *(__nv_bfloat162*)&C2h[m * ldc + n] = __halves2bfloat162(h0, h1);
                    *(__nv_bfloat162*)&C2l[m * ldc + n] = __halves2bfloat162(l0, l1);
                } else {
                    if (EPI == 1)      { v0 += bias[n]; v1 += bias[n + 1]; }
                    else if (EPI == 2) { v0 *= alpha;   v1 *= alpha; }
                    else if (EPI == 3) {
                        v0 = resid[m * ldc + n]     + gate[n]     * (v0 + bias[n]);
                        v1 = resid[m * ldc + n + 1] + gate[n + 1] * (v1 + bias[n + 1]);
                    }
                    *(float2*)&C[m * ldc + n] = make_float2(v0, v1);
                }
            }
        }
    }
}

// ---------------- transpose + split: in [R][Cc] fp32 -> out [Cc][R] bf16 hi/lo ----------------
__global__ void transpose_split(const float* __restrict__ in, size_t ld_in, long in_z,
                                __nv_bfloat16* __restrict__ oh, __nv_bfloat16* __restrict__ ol,
                                size_t ld_out, long out_z) {
    __shared__ float t[32][33];
    in += (long)blockIdx.z * in_z;
    oh += (long)blockIdx.z * out_z;  ol += (long)blockIdx.z * out_z;
    int c0 = blockIdx.x * 32, r0 = blockIdx.y * 32;
    int tx = threadIdx.x, ty = threadIdx.y;
    #pragma unroll
    for (int j = 0; j < 4; j++)
        t[ty + 8 * j][tx] = in[(size_t)(r0 + ty + 8 * j) * ld_in + c0 + tx];
    __syncthreads();
    #pragma unroll
    for (int j = 0; j < 4; j++) {
        float v = t[tx][ty + 8 * j];
        __nv_bfloat16 h, l; bsplit(v, h, l);
        size_t idx = (size_t)(c0 + ty + 8 * j) * ld_out + r0 + tx;
        oh[idx] = h; ol[idx] = l;
    }
}

// ---------------- kernel: mod = silu(vec) @ mod_w + mod_b ----------------
__global__ void mod_gemv(const float* __restrict__ vec,
                         const float* __restrict__ mod_w,
                         const float* __restrict__ mod_b) {
    __shared__ float sv[HID];
    int tid = threadIdx.x;
    for (int i = tid; i < HID; i += blockDim.x) {
        float a = vec[i];
        sv[i] = a / (1.f + __expf(-a));
    }
    __syncthreads();
    int j = blockIdx.x * blockDim.x + tid;
    float acc = 0.f;
    #pragma unroll 4
    for (int k = 0; k < HID; k++)
        acc += sv[k] * mod_w[(size_t)k * (3 * HID) + j];
    g_mod[j] = acc + mod_b[j];
}

// ---------------- layernorm + modulation -> bf16 split ----------------
__global__ void ln_mod_kernel(const float* __restrict__ x,
                              const float* __restrict__ gamma,
                              const float* __restrict__ beta) {
    __shared__ float red[32];
    int l = blockIdx.x;
    const float* xr = x + (size_t)l * HID;
    float s = 0.f, s2 = 0.f;
    for (int i = threadIdx.x; i < HID; i += 256) {
        float v = xr[i];
        s += v; s2 += v * v;
    }
    int lane = threadIdx.x & 31, wid = threadIdx.x >> 5;
    #pragma unroll
    for (int o = 16; o; o >>= 1) { s += __shfl_down_sync(~0u, s, o); s2 += __shfl_down_sync(~0u, s2, o); }
    if (lane == 0) { red[wid] = s; red[wid + 8] = s2; }
    __syncthreads();
    float ts = 0.f, ts2 = 0.f;
    if (threadIdx.x < 8) { ts = red[threadIdx.x]; ts2 = red[threadIdx.x + 8]; }
    #pragma unroll
    for (int o = 4; o; o >>= 1) { ts += __shfl_down_sync(0xff, ts, o); ts2 += __shfl_down_sync(0xff, ts2, o); }
    if (threadIdx.x == 0) { red[0] = ts; red[1] = ts2; }
    __syncthreads();
    float mu = red[0] / HID;
    float var = red[1] / HID - mu * mu;
    float rsig = rsqrtf(var + EPSF);
    for (int i = threadIdx.x; i < HID; i += 256) {
        float lnv = (xr[i] - mu) * rsig * gamma[i] + beta[i];
        float v = (1.f + g_mod[HID + i]) * lnv + g_mod[i];
        __nv_bfloat16 h, lo; bsplit(v, h, lo);
        g_xh[(size_t)l * HID + i] = h;
        g_xl[(size_t)l * HID + i] = lo;
    }
}

// ---------------- rmsnorm + rope -> q/k bf16 split [h][l][d] ----------------
__global__ void rmsnorm_rope(const float* __restrict__ pe,
                             const float* __restrict__ q_scale,
                             const float* __restrict__ k_scale) {
    int l = blockIdx.x, hd = blockIdx.y, which = blockIdx.z;
    const float* sc = which ? k_scale : q_scale;
    size_t base = (size_t)l * NN1 + (size_t)which * HID + (size_t)hd * DD;
    int d = threadIdx.x;
    float t = g_h[base + d];
    __shared__ float red[4];
    float v = t * t;
    #pragma unroll
    for (int o = 16; o; o >>= 1) v += __shfl_down_sync(~0u, v, o);
    if ((d & 31) == 0) red[d >> 5] = v;
    __syncthreads();
    float ss = red[0] + red[1] + red[2] + red[3];
    float r = rsqrtf(ss / DD + EPSF);
    __shared__ float s[DD];
    s[d] = t * r * sc[d];
    __syncthreads();
    int i = d >> 1, j = d & 1;
    const float* p = pe + (((size_t)l * (DD / 2) + i) * 2 + j) * 2;
    float out = p[0] * s[2 * i] + p[1] * s[2 * i + 1];
    __nv_bfloat16 h, lo; bsplit(out, h, lo);
    size_t oi = ((size_t)hd * LL + l) * DD + d;
    if (which) { g_kh[oi] = h; g_kl[oi] = lo; }
    else       { g_qh[oi] = h; g_ql[oi] = lo; }
}

// ---------------- softmax rows of g_scores -> P bf16 split ----------------
__global__ void softmax_rows() {
    size_t row = blockIdx.x;
    float* p = g_scores + row * LL;
    __shared__ float red[8];
    int lane = threadIdx.x & 31, wid = threadIdx.x >> 5;

    float mx = -1e30f;
    for (int i = threadIdx.x; i < LL; i += 256) mx = fmaxf(mx, p[i]);
    #pragma unroll
    for (int o = 16; o; o >>= 1) mx = fmaxf(mx, __shfl_down_sync(~0u, mx, o));
    if (lane == 0) red[wid] = mx;
    __syncthreads();
    if (threadIdx.x < 8) {
        float m = red[threadIdx.x];
        #pragma unroll
        for (int o = 4; o; o >>= 1) m = fmaxf(m, __shfl_down_sync(0xff, m, o));
        if (threadIdx.x == 0) red[0] = m;
    }
    __syncthreads();
    mx = red[0];
    __syncthreads();

    float sum = 0.f;
    for (int i = threadIdx.x; i < LL; i += 256) {
        float e = __expf(p[i] - mx);
        p[i] = e; sum += e;
    }
    #pragma unroll
    for (int o = 16; o; o >>= 1) sum += __shfl_down_sync(~0u, sum, o);
    if (lane == 0) red[wid] = sum;
    __syncthreads();
    if (threadIdx.x < 8) {
        float t = red[threadIdx.x];
        #pragma unroll
        for (int o = 4; o; o >>= 1) t += __shfl_down_sync(0xff, t, o);
        if (threadIdx.x == 0) red[0] = t;
    }
    __syncthreads();
    float inv = 1.f / red[0];
    for (int i = threadIdx.x; i < LL; i += 256) {
        float v = p[i] * inv;
        __nv_bfloat16 h, lo; bsplit(v, h, lo);
        g_ph[row * LL + i] = h;
        g_pl[row * LL + i] = lo;
    }
}

// ---------------- gelu(mlp) -> oc bf16 split ----------------
__global__ void gelu_split() {
    size_t idx = (size_t)blockIdx.x * 256 + threadIdx.x;
    size_t l = idx / MLPD;
    size_t m = idx % MLPD;
    float v = g_h[l * NN1 + 3 * HID + m];
    float c = 0.7978845608028654f * (v + 0.044715f * v * v * v);
    float o = 0.5f * v * (1.f + tanhf(c));
    __nv_bfloat16 h, lo; bsplit(o, h, lo);
    g_och[l * NN2 + HID + m] = h;
    g_ocl[l * NN2 + HID + m] = lo;
}

// ---------------- launcher ----------------
extern "C" void kernel_launch(void* const* d_in, const int* in_sizes, int n_in,
                              void* d_out, int out_size) {
    const float* x       = (const float*)d_in[0];
    const float* vec     = (const float*)d_in[1];
    const float* pe      = (const float*)d_in[2];
    const float* mod_w   = (const float*)d_in[3];
    const float* mod_b   = (const float*)d_in[4];
    const float* gamma   = (const float*)d_in[5];
    const float* beta    = (const float*)d_in[6];
    const float* w1      = (const float*)d_in[7];
    const float* b1      = (const float*)d_in[8];
    const float* q_scale = (const float*)d_in[9];
    const float* k_scale = (const float*)d_in[10];
    const float* w2      = (const float*)d_in[11];
    const float* b2      = (const float*)d_in[12];
    float* out = (float*)d_out;

    float *p_mod, *p_h, *p_scores;
    __nv_bfloat16 *p_xh, *p_xl, *p_w1h, *p_w1l, *p_qh, *p_ql, *p_kh, *p_kl;
    __nv_bfloat16 *p_vth, *p_vtl, *p_ph, *p_pl, *p_och, *p_ocl, *p_w2h, *p_w2l;
    cudaGetSymbolAddress((void**)&p_mod, g_mod);
    cudaGetSymbolAddress((void**)&p_h, g_h);
    cudaGetSymbolAddress((void**)&p_scores, g_scores);
    cudaGetSymbolAddress((void**)&p_xh, g_xh);   cudaGetSymbolAddress((void**)&p_xl, g_xl);
    cudaGetSymbolAddress((void**)&p_w1h, g_w1h); cudaGetSymbolAddress((void**)&p_w1l, g_w1l);
    cudaGetSymbolAddress((void**)&p_qh, g_qh);   cudaGetSymbolAddress((void**)&p_ql, g_ql);
    cudaGetSymbolAddress((void**)&p_kh, g_kh);   cudaGetSymbolAddress((void**)&p_kl, g_kl);
    cudaGetSymbolAddress((void**)&p_vth, g_vth); cudaGetSymbolAddress((void**)&p_vtl, g_vtl);
    cudaGetSymbolAddress((void**)&p_ph, g_ph);   cudaGetSymbolAddress((void**)&p_pl, g_pl);
    cudaGetSymbolAddress((void**)&p_och, g_och); cudaGetSymbolAddress((void**)&p_ocl, g_ocl);
    cudaGetSymbolAddress((void**)&p_w2h, g_w2h); cudaGetSymbolAddress((void**)&p_w2l, g_w2l);

    const int SMEM = 2 * 4 * 128 * 128;   // 131072
    cudaFuncSetAttribute((const void*)hmma_gemm<1>, cudaFuncAttributeMaxDynamicSharedMemorySize, SMEM);
    cudaFuncSetAttribute((const void*)hmma_gemm<2>, cudaFuncAttributeMaxDynamicSharedMemorySize, SMEM);
    cudaFuncSetAttribute((const void*)hmma_gemm<3>, cudaFuncAttributeMaxDynamicSharedMemorySize, SMEM);
    cudaFuncSetAttribute((const void*)hmma_gemm<4>, cudaFuncAttributeMaxDynamicSharedMemorySize, SMEM);

    // 1) modulation GEMV
    mod_gemv<<<(3 * HID) / 256, 256>>>(vec, mod_w, mod_b);
    // 2) layernorm + modulation -> xh/xl
    ln_mod_kernel<<<LL, 256>>>(x, gamma, beta);
    // 3) split+transpose w1 [HID][NN1] -> [NN1][HID]
    transpose_split<<<dim3(NN1 / 32, HID / 32, 1), dim3(32, 8)>>>(w1, NN1, 0, p_w1h, p_w1l, HID, 0);
    // 4) gemm1: h = xmod @ w1 + b1   (M=2048, N=21504, K=3072)
    hmma_gemm<1><<<dim3(NN1 / 128, LL / 128, 1), 256, SMEM>>>(
        p_xh, p_xl, HID, 0, p_w1h, p_w1l, HID, 0,
        p_h, NN1, 0, HID, b1, 1.f, nullptr, nullptr, nullptr, nullptr, 0);
    // 5) rmsnorm + rope -> q/k split
    rmsnorm_rope<<<dim3(LL, HH, 2), 128>>>(pe, q_scale, k_scale);
    // 6) v transpose+split per head: [L][D] -> [D][L]
    transpose_split<<<dim3(DD / 32, LL / 32, HH), dim3(32, 8)>>>(
        p_h + 2 * HID, NN1, DD, p_vth, p_vtl, LL, (long)DD * LL);
    // 7) scores = q @ k^T * D^-0.5   (batched over heads)
    hmma_gemm<2><<<dim3(LL / 128, LL / 128, HH), 256, SMEM>>>(
        p_qh, p_ql, DD, (long)LL * DD, p_kh, p_kl, DD, (long)LL * DD,
        p_scores, LL, (long)LL * LL, DD, nullptr, 0.08838834764831845f, nullptr, nullptr, nullptr, nullptr, 0);
    // 8) softmax -> P split
    softmax_rows<<<HH * LL, 256>>>();
    // 9) attn = P @ V^T -> oc cols [head*128, +128) as bf16 split
    hmma_gemm<4><<<dim3(1, LL / 128, HH), 256, SMEM>>>(
        p_ph, p_pl, LL, (long)LL * LL, p_vth, p_vtl, LL, (long)DD * LL,
        nullptr, NN2, 0, LL, nullptr, 1.f, nullptr, nullptr, p_och, p_ocl, DD);
    // 10) gelu(mlp) -> oc split
    gelu_split<<<((size_t)LL * MLPD) / 256, 256>>>();
    // 11) split+transpose w2 [NN2][HID] -> [HID][NN2]
    transpose_split<<<dim3(HID / 32, NN2 / 32, 1), dim3(32, 8)>>>(w2, HID, 0, p_w2h, p_w2l, NN2, 0);
    // 12) out = x + gate * (oc @ w2 + b2)   (M=2048, N=3072, K=15360)
    hmma_gemm<3><<<dim3(HID / 128, LL / 128, 1), 256, SMEM>>>(
        p_och, p_ocl, NN2, 0, p_w2h, p_w2l, NN2, 0,
        out, HID, 0, NN2, b2, 1.f, x, p_mod + 2 * HID, nullptr, nullptr, 0);
}

// round 5
// speedup vs baseline: 6.1037x; 1.7791x over previous
#include <cuda_runtime.h>
#include <cuda_fp16.h>
#include <math.h>
#include <stdint.h>

// Problem constants
#define LL   2048
#define HH   24
#define DD   128
#define HID  3072
#define MLPD 12288
#define NN1  21504   // 3*HID + MLP
#define NN2  15360   // HID + MLP
#define EPSF 1e-6f

// ---------------- scratch (static device arrays; no allocs) ----------------
__device__ float g_mod[3 * HID];
__device__ __half g_xf[(size_t)LL * HID];              // x_mod fp16
__device__ __half g_w1f[(size_t)NN1 * HID];            // w1^T fp16 [N][K]
__device__ float  g_h[(size_t)LL * NN1];               // gemm1 out fp32
__device__ __half g_qf[(size_t)HH * LL * DD];
__device__ __half g_kf[(size_t)HH * LL * DD];
__device__ __half g_vtf[(size_t)HH * DD * LL];         // V^T per head [D][L]
__device__ float  g_scores[(size_t)HH * LL * LL];
__device__ __half g_pf[(size_t)HH * LL * LL];          // softmax probs fp16
__device__ __half g_ocf[(size_t)LL * NN2];             // attn | gelu(mlp) fp16
__device__ __half g_w2f[(size_t)HID * NN2];            // w2^T fp16 [N][K]

// ---------------- helpers ----------------
__device__ __forceinline__ uint32_t smem_u32(const void* p) {
    uint32_t a;
    asm("{ .reg .u64 t; cvta.to.shared.u64 t, %1; cvt.u32.u64 %0, t; }" : "=r"(a) : "l"(p));
    return a;
}
__device__ __forceinline__ void cpasync16(uint32_t dst, const void* src) {
    asm volatile("cp.async.cg.shared.global [%0], [%1], 16;" :: "r"(dst), "l"(src));
}
__device__ __forceinline__ void cp_commit() { asm volatile("cp.async.commit_group;"); }
__device__ __forceinline__ void cp_wait1()  { asm volatile("cp.async.wait_group 1;" ::: "memory"); }
__device__ __forceinline__ void cp_wait0()  { asm volatile("cp.async.wait_group 0;" ::: "memory"); }

__device__ __forceinline__ void ldsm4(uint32_t& r0, uint32_t& r1, uint32_t& r2, uint32_t& r3, uint32_t a) {
    asm volatile("ldmatrix.sync.aligned.m8n8.x4.shared.b16 {%0,%1,%2,%3}, [%4];"
                 : "=r"(r0), "=r"(r1), "=r"(r2), "=r"(r3) : "r"(a));
}
__device__ __forceinline__ void mma16816(float* c, const uint32_t* a, uint32_t b0, uint32_t b1) {
    asm volatile(
        "mma.sync.aligned.m16n8k16.row.col.f32.f16.f16.f32 "
        "{%0,%1,%2,%3},{%4,%5,%6,%7},{%8,%9},{%0,%1,%2,%3};\n"
        : "+f"(c[0]), "+f"(c[1]), "+f"(c[2]), "+f"(c[3])
        : "r"(a[0]), "r"(a[1]), "r"(a[2]), "r"(a[3]), "r"(b0), "r"(b1));
}

// ---------------- fp16 HMMA GEMM ----------------
// D[m][n] = sum_k A[m][k]*B[n][k]; single-pass fp16, fp32 accum.
// CTA tile 128x128, K-chunk 64, double-buffered cp.async, swizzled smem.
// 8 warps: warp tile 32(m) x 64(n).
// EPI: 1 +bias -> f32 | 2 *alpha -> f32 | 3 resid + gate*(acc+bias) -> f32 | 5 -> fp16 C2
template<int EPI>
__global__ void __launch_bounds__(256, 1) hgemm(
    const __half* __restrict__ A, size_t lda, long sA,
    const __half* __restrict__ B, size_t ldb, long sB,
    float* __restrict__ C, size_t ldc, long sC, int K,
    const float* __restrict__ bias, float alpha,
    const float* __restrict__ resid, const float* __restrict__ gate,
    __half* __restrict__ C2, long sC2)
{
    extern __shared__ char smem[];
    constexpr int TILE = 128 * 128;      // 16 KB: 128 rows x 64 halves
    constexpr int STAGE = 2 * TILE;      // A | B
    const uint32_t sb = smem_u32(smem);
    const int tid = threadIdx.x, wid = tid >> 5, lane = tid & 31;
    const int wm = wid & 3, wn = wid >> 2;

    A += (long)blockIdx.z * sA;
    B += (long)blockIdx.z * sB;
    if (EPI == 5) C2 += (long)blockIdx.z * sC2;
    else          C  += (long)blockIdx.z * sC;

    const size_t row0 = (size_t)blockIdx.y * 128;
    const size_t col0 = (size_t)blockIdx.x * 128;
    const __half* baseA = A + row0 * lda;
    const __half* baseB = B + col0 * ldb;

    const int lrow = tid >> 3, lk8 = tid & 7;

    auto load_stage = [&](int s) {
        const uint32_t st = sb + (uint32_t)(s & 1) * STAGE;
        const int ko = s * 64;
        #pragma unroll
        for (int j = 0; j < 4; j++) {
            int row = lrow + j * 32;
            uint32_t dst = st + row * 128 + ((lk8 ^ (row & 7)) << 4);
            cpasync16(dst, (const char*)(baseA + ko + (size_t)row * lda) + lk8 * 16);
        }
        #pragma unroll
        for (int j = 0; j < 4; j++) {
            int row = lrow + j * 32;
            uint32_t dst = st + TILE + row * 128 + ((lk8 ^ (row & 7)) << 4);
            cpasync16(dst, (const char*)(baseB + ko + (size_t)row * ldb) + lk8 * 16);
        }
    };

    float acc[2][8][4] = {};
    const int S = K >> 6;

    load_stage(0); cp_commit();
    for (int s = 0; s < S; s++) {
        if (s + 1 < S) { load_stage(s + 1); cp_commit(); cp_wait1(); }
        else           { cp_wait0(); }
        __syncthreads();

        const uint32_t st = sb + (uint32_t)(s & 1) * STAGE;
        const uint32_t tA = st, tB = st + TILE;

        #pragma unroll
        for (int kg = 0; kg < 4; kg++) {
            uint32_t af[2][4];
            {
                int arow = wm * 32 + (lane & 15);
                int ak8 = kg * 2 + (lane >> 4);
                #pragma unroll
                for (int im = 0; im < 2; im++) {
                    int r = arow + im * 16;
                    uint32_t off = r * 128 + ((ak8 ^ (r & 7)) << 4);
                    ldsm4(af[im][0], af[im][1], af[im][2], af[im][3], tA + off);
                }
            }
            int brow_b = wn * 64 + (lane & 7) + ((lane >> 4) << 3);
            int bk8 = kg * 2 + ((lane >> 3) & 1);
            #pragma unroll
            for (int g = 0; g < 4; g++) {
                int r = brow_b + g * 16;
                uint32_t off = r * 128 + ((bk8 ^ (r & 7)) << 4);
                uint32_t b0, b1, b2, b3;
                ldsm4(b0, b1, b2, b3, tB + off);
                #pragma unroll
                for (int im = 0; im < 2; im++) {
                    mma16816(acc[im][2 * g],     af[im], b0, b1);
                    mma16816(acc[im][2 * g + 1], af[im], b2, b3);
                }
            }
        }
        __syncthreads();
    }

    // epilogue
    #pragma unroll
    for (int im = 0; im < 2; im++) {
        #pragma unroll
        for (int in = 0; in < 8; in++) {
            size_t m0 = row0 + wm * 32 + im * 16 + (lane >> 2);
            size_t n  = col0 + wn * 64 + in * 8 + (lane & 3) * 2;
            #pragma unroll
            for (int half = 0; half < 2; half++) {
                size_t m = m0 + half * 8;
                float v0 = acc[im][in][half * 2 + 0];
                float v1 = acc[im][in][half * 2 + 1];
                if (EPI == 5) {
                    *(__half2*)&C2[m * ldc + n] = __floats2half2_rn(v0, v1);
                } else {
                    if (EPI == 1)      { v0 += bias[n]; v1 += bias[n + 1]; }
                    else if (EPI == 2) { v0 *= alpha;   v1 *= alpha; }
                    else if (EPI == 3) {
                        v0 = resid[m * ldc + n]     + gate[n]     * (v0 + bias[n]);
                        v1 = resid[m * ldc + n + 1] + gate[n + 1] * (v1 + bias[n + 1]);
                    }
                    *(float2*)&C[m * ldc + n] = make_float2(v0, v1);
                }
            }
        }
    }
}

// ---------------- transpose + cast: in [R][Cc] fp32 -> out [Cc][R] fp16 ----------------
__global__ void transpose_cast(const float* __restrict__ in, size_t ld_in, long in_z,
                               __half* __restrict__ o, size_t ld_out, long out_z) {
    __shared__ float t[32][33];
    in += (long)blockIdx.z * in_z;
    o  += (long)blockIdx.z * out_z;
    int c0 = blockIdx.x * 32, r0 = blockIdx.y * 32;
    int tx = threadIdx.x, ty = threadIdx.y;
    #pragma unroll
    for (int j = 0; j < 4; j++)
        t[ty + 8 * j][tx] = in[(size_t)(r0 + ty + 8 * j) * ld_in + c0 + tx];
    __syncthreads();
    #pragma unroll
    for (int j = 0; j < 4; j++) {
        o[(size_t)(c0 + ty + 8 * j) * ld_out + r0 + tx] = __float2half_rn(t[tx][ty + 8 * j]);
    }
}

// ---------------- kernel: mod = silu(vec) @ mod_w + mod_b ----------------
__global__ void mod_gemv(const float* __restrict__ vec,
                         const float* __restrict__ mod_w,
                         const float* __restrict__ mod_b) {
    __shared__ float sv[HID];
    int tid = threadIdx.x;
    for (int i = tid; i < HID; i += blockDim.x) {
        float a = vec[i];
        sv[i] = a / (1.f + __expf(-a));
    }
    __syncthreads();
    int j = blockIdx.x * blockDim.x + tid;
    float acc = 0.f;
    #pragma unroll 4
    for (int k = 0; k < HID; k++)
        acc += sv[k] * mod_w[(size_t)k * (3 * HID) + j];
    g_mod[j] = acc + mod_b[j];
}

// ---------------- layernorm + modulation -> fp16 ----------------
__global__ void ln_mod_kernel(const float* __restrict__ x,
                              const float* __restrict__ gamma,
                              const float* __restrict__ beta) {
    __shared__ float red[32];
    int l = blockIdx.x;
    const float* xr = x + (size_t)l * HID;
    float s = 0.f, s2 = 0.f;
    for (int i = threadIdx.x; i < HID; i += 256) {
        float v = xr[i];
        s += v; s2 += v * v;
    }
    int lane = threadIdx.x & 31, wid = threadIdx.x >> 5;
    #pragma unroll
    for (int o = 16; o; o >>= 1) { s += __shfl_down_sync(~0u, s, o); s2 += __shfl_down_sync(~0u, s2, o); }
    if (lane == 0) { red[wid] = s; red[wid + 8] = s2; }
    __syncthreads();
    float ts = 0.f, ts2 = 0.f;
    if (threadIdx.x < 8) { ts = red[threadIdx.x]; ts2 = red[threadIdx.x + 8]; }
    #pragma unroll
    for (int o = 4; o; o >>= 1) { ts += __shfl_down_sync(0xff, ts, o); ts2 += __shfl_down_sync(0xff, ts2, o); }
    if (threadIdx.x == 0) { red[0] = ts; red[1] = ts2; }
    __syncthreads();
    float mu = red[0] / HID;
    float var = red[1] / HID - mu * mu;
    float rsig = rsqrtf(var + EPSF);
    for (int i = threadIdx.x; i < HID; i += 256) {
        float lnv = (xr[i] - mu) * rsig * gamma[i] + beta[i];
        float v = (1.f + g_mod[HID + i]) * lnv + g_mod[i];
        g_xf[(size_t)l * HID + i] = __float2half_rn(v);
    }
}

// ---------------- rmsnorm + rope -> q/k fp16 [h][l][d] ----------------
__global__ void rmsnorm_rope(const float* __restrict__ pe,
                             const float* __restrict__ q_scale,
                             const float* __restrict__ k_scale) {
    int l = blockIdx.x, hd = blockIdx.y, which = blockIdx.z;
    const float* sc = which ? k_scale : q_scale;
    size_t base = (size_t)l * NN1 + (size_t)which * HID + (size_t)hd * DD;
    int d = threadIdx.x;
    float t = g_h[base + d];
    __shared__ float red[4];
    float v = t * t;
    #pragma unroll
    for (int o = 16; o; o >>= 1) v += __shfl_down_sync(~0u, v, o);
    if ((d & 31) == 0) red[d >> 5] = v;
    __syncthreads();
    float ss = red[0] + red[1] + red[2] + red[3];
    float r = rsqrtf(ss / DD + EPSF);
    __shared__ float s[DD];
    s[d] = t * r * sc[d];
    __syncthreads();
    int i = d >> 1, j = d & 1;
    const float* p = pe + (((size_t)l * (DD / 2) + i) * 2 + j) * 2;
    float out = p[0] * s[2 * i] + p[1] * s[2 * i + 1];
    size_t oi = ((size_t)hd * LL + l) * DD + d;
    if (which) g_kf[oi] = __float2half_rn(out);
    else       g_qf[oi] = __float2half_rn(out);
}

// ---------------- softmax rows of g_scores -> P fp16 ----------------
__global__ void softmax_rows() {
    size_t row = blockIdx.x;
    float* p = g_scores + row * LL;
    __shared__ float red[8];
    int lane = threadIdx.x & 31, wid = threadIdx.x >> 5;

    float mx = -1e30f;
    for (int i = threadIdx.x; i < LL; i += 256) mx = fmaxf(mx, p[i]);
    #pragma unroll
    for (int o = 16; o; o >>= 1) mx = fmaxf(mx, __shfl_down_sync(~0u, mx, o));
    if (lane == 0) red[wid] = mx;
    __syncthreads();
    if (threadIdx.x < 8) {
        float m = red[threadIdx.x];
        #pragma unroll
        for (int o = 4; o; o >>= 1) m = fmaxf(m, __shfl_down_sync(0xff, m, o));
        if (threadIdx.x == 0) red[0] = m;
    }
    __syncthreads();
    mx = red[0];
    __syncthreads();

    float sum = 0.f;
    for (int i = threadIdx.x; i < LL; i += 256) {
        float e = __expf(p[i] - mx);
        p[i] = e; sum += e;
    }
    #pragma unroll
    for (int o = 16; o; o >>= 1) sum += __shfl_down_sync(~0u, sum, o);
    if (lane == 0) red[wid] = sum;
    __syncthreads();
    if (threadIdx.x < 8) {
        float t = red[threadIdx.x];
        #pragma unroll
        for (int o = 4; o; o >>= 1) t += __shfl_down_sync(0xff, t, o);
        if (threadIdx.x == 0) red[0] = t;
    }
    __syncthreads();
    float inv = 1.f / red[0];
    for (int i = threadIdx.x; i < LL; i += 256)
        g_pf[row * LL + i] = __float2half_rn(p[i] * inv);
}

// ---------------- gelu(mlp) -> oc fp16 ----------------
__global__ void gelu_cast() {
    size_t idx = (size_t)blockIdx.x * 256 + threadIdx.x;
    size_t l = idx / MLPD;
    size_t m = idx % MLPD;
    float v = g_h[l * NN1 + 3 * HID + m];
    float c = 0.7978845608028654f * (v + 0.044715f * v * v * v);
    float o = 0.5f * v * (1.f + tanhf(c));
    g_ocf[l * NN2 + HID + m] = __float2half_rn(o);
}

// ---------------- launcher ----------------
extern "C" void kernel_launch(void* const* d_in, const int* in_sizes, int n_in,
                              void* d_out, int out_size) {
    const float* x       = (const float*)d_in[0];
    const float* vec     = (const float*)d_in[1];
    const float* pe      = (const float*)d_in[2];
    const float* mod_w   = (const float*)d_in[3];
    const float* mod_b   = (const float*)d_in[4];
    const float* gamma   = (const float*)d_in[5];
    const float* beta    = (const float*)d_in[6];
    const float* w1      = (const float*)d_in[7];
    const float* b1      = (const float*)d_in[8];
    const float* q_scale = (const float*)d_in[9];
    const float* k_scale = (const float*)d_in[10];
    const float* w2      = (const float*)d_in[11];
    const float* b2      = (const float*)d_in[12];
    float* out = (float*)d_out;

    float *p_mod, *p_h, *p_scores;
    __half *p_xf, *p_w1f, *p_qf, *p_kf, *p_vtf, *p_pf, *p_ocf, *p_w2f;
    cudaGetSymbolAddress((void**)&p_mod, g_mod);
    cudaGetSymbolAddress((void**)&p_h, g_h);
    cudaGetSymbolAddress((void**)&p_scores, g_scores);
    cudaGetSymbolAddress((void**)&p_xf, g_xf);
    cudaGetSymbolAddress((void**)&p_w1f, g_w1f);
    cudaGetSymbolAddress((void**)&p_qf, g_qf);
    cudaGetSymbolAddress((void**)&p_kf, g_kf);
    cudaGetSymbolAddress((void**)&p_vtf, g_vtf);
    cudaGetSymbolAddress((void**)&p_pf, g_pf);
    cudaGetSymbolAddress((void**)&p_ocf, g_ocf);
    cudaGetSymbolAddress((void**)&p_w2f, g_w2f);

    const int SMEM = 2 * 2 * 128 * 128;   // 65536
    cudaFuncSetAttribute((const void*)hgemm<1>, cudaFuncAttributeMaxDynamicSharedMemorySize, SMEM);
    cudaFuncSetAttribute((const void*)hgemm<2>, cudaFuncAttributeMaxDynamicSharedMemorySize, SMEM);
    cudaFuncSetAttribute((const void*)hgemm<3>, cudaFuncAttributeMaxDynamicSharedMemorySize, SMEM);
    cudaFuncSetAttribute((const void*)hgemm<5>, cudaFuncAttributeMaxDynamicSharedMemorySize, SMEM);

    // 1) modulation GEMV
    mod_gemv<<<(3 * HID) / 256, 256>>>(vec, mod_w, mod_b);
    // 2) layernorm + modulation -> xf
    ln_mod_kernel<<<LL, 256>>>(x, gamma, beta);
    // 3) transpose+cast w1 [HID][NN1] -> [NN1][HID]
    transpose_cast<<<dim3(NN1 / 32, HID / 32, 1), dim3(32, 8)>>>(w1, NN1, 0, p_w1f, HID, 0);
    // 4) gemm1: h = xmod @ w1 + b1   (M=2048, N=21504, K=3072)
    hgemm<1><<<dim3(NN1 / 128, LL / 128, 1), 256, SMEM>>>(
        p_xf, HID, 0, p_w1f, HID, 0,
        p_h, NN1, 0, HID, b1, 1.f, nullptr, nullptr, nullptr, 0);
    // 5) rmsnorm + rope -> q/k fp16
    rmsnorm_rope<<<dim3(LL, HH, 2), 128>>>(pe, q_scale, k_scale);
    // 6) v transpose+cast per head: [L][D] -> [D][L]
    transpose_cast<<<dim3(DD / 32, LL / 32, HH), dim3(32, 8)>>>(
        p_h + 2 * HID, NN1, DD, p_vtf, LL, (long)DD * LL);
    // 7) scores = q @ k^T * D^-0.5   (batched over heads)
    hgemm<2><<<dim3(LL / 128, LL / 128, HH), 256, SMEM>>>(
        p_qf, DD, (long)LL * DD, p_kf, DD, (long)LL * DD,
        p_scores, LL, (long)LL * LL, DD, nullptr, 0.08838834764831845f, nullptr, nullptr, nullptr, 0);
    // 8) softmax -> P fp16
    softmax_rows<<<HH * LL, 256>>>();
    // 9) attn = P @ V^T -> oc cols [head*128, +128) fp16
    hgemm<5><<<dim3(1, LL / 128, HH), 256, SMEM>>>(
        p_pf, LL, (long)LL * LL, p_vtf, LL, (long)DD * LL,
        nullptr, NN2, 0, LL, nullptr, 1.f, nullptr, nullptr, p_ocf, DD);
    // 10) gelu(mlp) -> oc fp16
    gelu_cast<<<((size_t)LL * MLPD) / 256, 256>>>();
    // 11) transpose+cast w2 [NN2][HID] -> [HID][NN2]
    transpose_cast<<<dim3(HID / 32, NN2 / 32, 1), dim3(32, 8)>>>(w2, HID, 0, p_w2f, NN2, 0);
    // 12) out = x + gate * (oc @ w2 + b2)   (M=2048, N=3072, K=15360)
    hgemm<3><<<dim3(HID / 128, LL / 128, 1), 256, SMEM>>>(
        p_ocf, NN2, 0, p_w2f, NN2, 0,
        out, HID, 0, NN2, b2, 1.f, x, p_mod + 2 * HID, nullptr, 0);
}

// round 6
// speedup vs baseline: 6.1595x; 1.0091x over previous
#include <cuda_runtime.h>
#include <cuda_fp16.h>
#include <math.h>
#include <stdint.h>

// Problem constants
#define LL   2048
#define HH   24
#define DD   128
#define HID  3072
#define MLPD 12288
#define NN1  21504   // 3*HID + MLP
#define NN2  15360   // HID + MLP
#define EPSF 1e-6f

// ---------------- scratch (static device arrays; no allocs) ----------------
__device__ float g_mod[3 * HID];
__device__ __half g_xf[(size_t)LL * HID];              // x_mod fp16
__device__ __half g_w1f[(size_t)NN1 * HID];            // w1^T fp16 [N][K]
__device__ float  g_h[(size_t)LL * NN1];               // gemm1 out fp32
__device__ __half g_qf[(size_t)HH * LL * DD];
__device__ __half g_kf[(size_t)HH * LL * DD];
__device__ __half g_vtf[(size_t)HH * DD * LL];         // V^T per head [D][L]
__device__ float  g_scores[(size_t)HH * LL * LL];
__device__ __half g_pf[(size_t)HH * LL * LL];          // softmax probs fp16
__device__ __half g_ocf[(size_t)LL * NN2];             // attn | gelu(mlp) fp16
__device__ __half g_w2f[(size_t)HID * NN2];            // w2^T fp16 [N][K]

// ---------------- helpers ----------------
__device__ __forceinline__ uint32_t smem_u32(const void* p) {
    uint32_t a;
    asm("{ .reg .u64 t; cvta.to.shared.u64 t, %1; cvt.u32.u64 %0, t; }" : "=r"(a) : "l"(p));
    return a;
}
__device__ __forceinline__ void cpasync16(uint32_t dst, const void* src) {
    asm volatile("cp.async.cg.shared.global [%0], [%1], 16;" :: "r"(dst), "l"(src));
}
__device__ __forceinline__ void cp_commit() { asm volatile("cp.async.commit_group;"); }
__device__ __forceinline__ void cp_wait1()  { asm volatile("cp.async.wait_group 1;" ::: "memory"); }
__device__ __forceinline__ void cp_wait0()  { asm volatile("cp.async.wait_group 0;" ::: "memory"); }

__device__ __forceinline__ void ldsm4(uint32_t& r0, uint32_t& r1, uint32_t& r2, uint32_t& r3, uint32_t a) {
    asm volatile("ldmatrix.sync.aligned.m8n8.x4.shared.b16 {%0,%1,%2,%3}, [%4];"
                 : "=r"(r0), "=r"(r1), "=r"(r2), "=r"(r3) : "r"(a));
}
__device__ __forceinline__ void mma16816(float* c, const uint32_t* a, uint32_t b0, uint32_t b1) {
    asm volatile(
        "mma.sync.aligned.m16n8k16.row.col.f32.f16.f16.f32 "
        "{%0,%1,%2,%3},{%4,%5,%6,%7},{%8,%9},{%0,%1,%2,%3};\n"
        : "+f"(c[0]), "+f"(c[1]), "+f"(c[2]), "+f"(c[3])
        : "r"(a[0]), "r"(a[1]), "r"(a[2]), "r"(a[3]), "r"(b0), "r"(b1));
}

// ---------------- fp16 HMMA GEMM ----------------
// D[m][n] = sum_k A[m][k]*B[n][k]; single-pass fp16, fp32 accum.
// CTA tile 256x128, K-chunk 64, double-buffered cp.async, swizzled smem.
// 8 warps laid out 4(m) x 2(n): warp tile 64 x 64.
// EPI: 1 +bias -> f32 | 2 *alpha -> f32 | 3 resid + gate*(acc+bias) -> f32 | 5 -> fp16 C2
template<int EPI>
__global__ void __launch_bounds__(256, 1) hgemm(
    const __half* __restrict__ A, size_t lda, long sA,
    const __half* __restrict__ B, size_t ldb, long sB,
    float* __restrict__ C, size_t ldc, long sC, int K,
    const float* __restrict__ bias, float alpha,
    const float* __restrict__ resid, const float* __restrict__ gate,
    __half* __restrict__ C2, long sC2)
{
    extern __shared__ char smem[];
    constexpr int TILEA = 256 * 128;     // 32 KB: 256 rows x 64 halves
    constexpr int TILEB = 128 * 128;     // 16 KB
    constexpr int STAGE = TILEA + TILEB;
    const uint32_t sb = smem_u32(smem);
    const int tid = threadIdx.x, wid = tid >> 5, lane = tid & 31;
    const int wm = wid & 3, wn = wid >> 2;

    A += (long)blockIdx.z * sA;
    B += (long)blockIdx.z * sB;
    if (EPI == 5) C2 += (long)blockIdx.z * sC2;
    else          C  += (long)blockIdx.z * sC;

    const size_t row0 = (size_t)blockIdx.y * 256;
    const size_t col0 = (size_t)blockIdx.x * 128;
    const __half* baseA = A + row0 * lda;
    const __half* baseB = B + col0 * ldb;

    const int lrow = tid >> 3, lk8 = tid & 7;

    auto load_stage = [&](int s) {
        const uint32_t st = sb + (uint32_t)(s & 1) * STAGE;
        const int ko = s * 64;
        #pragma unroll
        for (int j = 0; j < 8; j++) {
            int row = lrow + j * 32;
            uint32_t dst = st + row * 128 + ((lk8 ^ (row & 7)) << 4);
            cpasync16(dst, (const char*)(baseA + ko + (size_t)row * lda) + lk8 * 16);
        }
        #pragma unroll
        for (int j = 0; j < 4; j++) {
            int row = lrow + j * 32;
            uint32_t dst = st + TILEA + row * 128 + ((lk8 ^ (row & 7)) << 4);
            cpasync16(dst, (const char*)(baseB + ko + (size_t)row * ldb) + lk8 * 16);
        }
    };

    float acc[4][8][4] = {};
    const int S = K >> 6;

    load_stage(0); cp_commit();
    for (int s = 0; s < S; s++) {
        if (s + 1 < S) { load_stage(s + 1); cp_commit(); cp_wait1(); }
        else           { cp_wait0(); }
        __syncthreads();

        const uint32_t st = sb + (uint32_t)(s & 1) * STAGE;
        const uint32_t tA = st, tB = st + TILEA;

        #pragma unroll
        for (int kg = 0; kg < 4; kg++) {
            uint32_t af[4][4];
            {
                int arow = wm * 64 + (lane & 15);
                int ak8 = kg * 2 + (lane >> 4);
                #pragma unroll
                for (int im = 0; im < 4; im++) {
                    int r = arow + im * 16;
                    uint32_t off = r * 128 + ((ak8 ^ (r & 7)) << 4);
                    ldsm4(af[im][0], af[im][1], af[im][2], af[im][3], tA + off);
                }
            }
            int brow_b = wn * 64 + (lane & 7) + ((lane >> 4) << 3);
            int bk8 = kg * 2 + ((lane >> 3) & 1);
            #pragma unroll
            for (int g = 0; g < 4; g++) {
                int r = brow_b + g * 16;
                uint32_t off = r * 128 + ((bk8 ^ (r & 7)) << 4);
                uint32_t b0, b1, b2, b3;
                ldsm4(b0, b1, b2, b3, tB + off);
                #pragma unroll
                for (int im = 0; im < 4; im++) {
                    mma16816(acc[im][2 * g],     af[im], b0, b1);
                    mma16816(acc[im][2 * g + 1], af[im], b2, b3);
                }
            }
        }
        __syncthreads();
    }

    // epilogue
    #pragma unroll
    for (int im = 0; im < 4; im++) {
        #pragma unroll
        for (int in = 0; in < 8; in++) {
            size_t m0 = row0 + wm * 64 + im * 16 + (lane >> 2);
            size_t n  = col0 + wn * 64 + in * 8 + (lane & 3) * 2;
            #pragma unroll
            for (int half = 0; half < 2; half++) {
                size_t m = m0 + half * 8;
                float v0 = acc[im][in][half * 2 + 0];
                float v1 = acc[im][in][half * 2 + 1];
                if (EPI == 5) {
                    *(__half2*)&C2[m * ldc + n] = __floats2half2_rn(v0, v1);
                } else {
                    if (EPI == 1)      { v0 += bias[n]; v1 += bias[n + 1]; }
                    else if (EPI == 2) { v0 *= alpha;   v1 *= alpha; }
                    else if (EPI == 3) {
                        v0 = resid[m * ldc + n]     + gate[n]     * (v0 + bias[n]);
                        v1 = resid[m * ldc + n + 1] + gate[n + 1] * (v1 + bias[n + 1]);
                    }
                    *(float2*)&C[m * ldc + n] = make_float2(v0, v1);
                }
            }
        }
    }
}

// ---------------- transpose + cast: in [R][Cc] fp32 -> out [Cc][R] fp16 ----------------
__global__ void transpose_cast(const float* __restrict__ in, size_t ld_in, long in_z,
                               __half* __restrict__ o, size_t ld_out, long out_z) {
    __shared__ float t[32][33];
    in += (long)blockIdx.z * in_z;
    o  += (long)blockIdx.z * out_z;
    int c0 = blockIdx.x * 32, r0 = blockIdx.y * 32;
    int tx = threadIdx.x, ty = threadIdx.y;
    #pragma unroll
    for (int j = 0; j < 4; j++)
        t[ty + 8 * j][tx] = in[(size_t)(r0 + ty + 8 * j) * ld_in + c0 + tx];
    __syncthreads();
    #pragma unroll
    for (int j = 0; j < 4; j++) {
        o[(size_t)(c0 + ty + 8 * j) * ld_out + r0 + tx] = __float2half_rn(t[tx][ty + 8 * j]);
    }
}

// ---------------- kernel: mod = silu(vec) @ mod_w + mod_b ----------------
__global__ void mod_gemv(const float* __restrict__ vec,
                         const float* __restrict__ mod_w,
                         const float* __restrict__ mod_b) {
    __shared__ float sv[HID];
    int tid = threadIdx.x;
    for (int i = tid; i < HID; i += blockDim.x) {
        float a = vec[i];
        sv[i] = a / (1.f + __expf(-a));
    }
    __syncthreads();
    int j = blockIdx.x * blockDim.x + tid;
    float acc = 0.f;
    #pragma unroll 4
    for (int k = 0; k < HID; k++)
        acc += sv[k] * mod_w[(size_t)k * (3 * HID) + j];
    g_mod[j] = acc + mod_b[j];
}

// ---------------- layernorm + modulation -> fp16 ----------------
__global__ void ln_mod_kernel(const float* __restrict__ x,
                              const float* __restrict__ gamma,
                              const float* __restrict__ beta) {
    __shared__ float red[32];
    int l = blockIdx.x;
    const float* xr = x + (size_t)l * HID;
    float s = 0.f, s2 = 0.f;
    for (int i = threadIdx.x; i < HID; i += 256) {
        float v = xr[i];
        s += v; s2 += v * v;
    }
    int lane = threadIdx.x & 31, wid = threadIdx.x >> 5;
    #pragma unroll
    for (int o = 16; o; o >>= 1) { s += __shfl_down_sync(~0u, s, o); s2 += __shfl_down_sync(~0u, s2, o); }
    if (lane == 0) { red[wid] = s; red[wid + 8] = s2; }
    __syncthreads();
    float ts = 0.f, ts2 = 0.f;
    if (threadIdx.x < 8) { ts = red[threadIdx.x]; ts2 = red[threadIdx.x + 8]; }
    #pragma unroll
    for (int o = 4; o; o >>= 1) { ts += __shfl_down_sync(0xff, ts, o); ts2 += __shfl_down_sync(0xff, ts2, o); }
    if (threadIdx.x == 0) { red[0] = ts; red[1] = ts2; }
    __syncthreads();
    float mu = red[0] / HID;
    float var = red[1] / HID - mu * mu;
    float rsig = rsqrtf(var + EPSF);
    for (int i = threadIdx.x; i < HID; i += 256) {
        float lnv = (xr[i] - mu) * rsig * gamma[i] + beta[i];
        float v = (1.f + g_mod[HID + i]) * lnv + g_mod[i];
        g_xf[(size_t)l * HID + i] = __float2half_rn(v);
    }
}

// ---------------- rmsnorm + rope -> q/k fp16 [h][l][d] ----------------
__global__ void rmsnorm_rope(const float* __restrict__ pe,
                             const float* __restrict__ q_scale,
                             const float* __restrict__ k_scale) {
    int l = blockIdx.x, hd = blockIdx.y, which = blockIdx.z;
    const float* sc = which ? k_scale : q_scale;
    size_t base = (size_t)l * NN1 + (size_t)which * HID + (size_t)hd * DD;
    int d = threadIdx.x;
    float t = g_h[base + d];
    __shared__ float red[4];
    float v = t * t;
    #pragma unroll
    for (int o = 16; o; o >>= 1) v += __shfl_down_sync(~0u, v, o);
    if ((d & 31) == 0) red[d >> 5] = v;
    __syncthreads();
    float ss = red[0] + red[1] + red[2] + red[3];
    float r = rsqrtf(ss / DD + EPSF);
    __shared__ float s[DD];
    s[d] = t * r * sc[d];
    __syncthreads();
    int i = d >> 1, j = d & 1;
    const float* p = pe + (((size_t)l * (DD / 2) + i) * 2 + j) * 2;
    float out = p[0] * s[2 * i] + p[1] * s[2 * i + 1];
    size_t oi = ((size_t)hd * LL + l) * DD + d;
    if (which) g_kf[oi] = __float2half_rn(out);
    else       g_qf[oi] = __float2half_rn(out);
}

// ---------------- softmax rows of g_scores -> P fp16 ----------------
__global__ void softmax_rows() {
    size_t row = blockIdx.x;
    float* p = g_scores + row * LL;
    __shared__ float red[8];
    int lane = threadIdx.x & 31, wid = threadIdx.x >> 5;

    float mx = -1e30f;
    for (int i = threadIdx.x; i < LL; i += 256) mx = fmaxf(mx, p[i]);
    #pragma unroll
    for (int o = 16; o; o >>= 1) mx = fmaxf(mx, __shfl_down_sync(~0u, mx, o));
    if (lane == 0) red[wid] = mx;
    __syncthreads();
    if (threadIdx.x < 8) {
        float m = red[threadIdx.x];
        #pragma unroll
        for (int o = 4; o; o >>= 1) m = fmaxf(m, __shfl_down_sync(0xff, m, o));
        if (threadIdx.x == 0) red[0] = m;
    }
    __syncthreads();
    mx = red[0];
    __syncthreads();

    float sum = 0.f;
    for (int i = threadIdx.x; i < LL; i += 256) {
        float e = __expf(p[i] - mx);
        p[i] = e; sum += e;
    }
    #pragma unroll
    for (int o = 16; o; o >>= 1) sum += __shfl_down_sync(~0u, sum, o);
    if (lane == 0) red[wid] = sum;
    __syncthreads();
    if (threadIdx.x < 8) {
        float t = red[threadIdx.x];
        #pragma unroll
        for (int o = 4; o; o >>= 1) t += __shfl_down_sync(0xff, t, o);
        if (threadIdx.x == 0) red[0] = t;
    }
    __syncthreads();
    float inv = 1.f / red[0];
    for (int i = threadIdx.x; i < LL; i += 256)
        g_pf[row * LL + i] = __float2half_rn(p[i] * inv);
}

// ---------------- gelu(mlp) -> oc fp16 ----------------
__global__ void gelu_cast() {
    size_t idx = (size_t)blockIdx.x * 256 + threadIdx.x;
    size_t l = idx / MLPD;
    size_t m = idx % MLPD;
    float v = g_h[l * NN1 + 3 * HID + m];
    float c = 0.7978845608028654f * (v + 0.044715f * v * v * v);
    float o = 0.5f * v * (1.f + tanhf(c));
    g_ocf[l * NN2 + HID + m] = __float2half_rn(o);
}

// ---------------- launcher ----------------
extern "C" void kernel_launch(void* const* d_in, const int* in_sizes, int n_in,
                              void* d_out, int out_size) {
    const float* x       = (const float*)d_in[0];
    const float* vec     = (const float*)d_in[1];
    const float* pe      = (const float*)d_in[2];
    const float* mod_w   = (const float*)d_in[3];
    const float* mod_b   = (const float*)d_in[4];
    const float* gamma   = (const float*)d_in[5];
    const float* beta    = (const float*)d_in[6];
    const float* w1      = (const float*)d_in[7];
    const float* b1      = (const float*)d_in[8];
    const float* q_scale = (const float*)d_in[9];
    const float* k_scale = (const float*)d_in[10];
    const float* w2      = (const float*)d_in[11];
    const float* b2      = (const float*)d_in[12];
    float* out = (float*)d_out;

    float *p_mod, *p_h, *p_scores;
    __half *p_xf, *p_w1f, *p_qf, *p_kf, *p_vtf, *p_pf, *p_ocf, *p_w2f;
    cudaGetSymbolAddress((void**)&p_mod, g_mod);
    cudaGetSymbolAddress((void**)&p_h, g_h);
    cudaGetSymbolAddress((void**)&p_scores, g_scores);
    cudaGetSymbolAddress((void**)&p_xf, g_xf);
    cudaGetSymbolAddress((void**)&p_w1f, g_w1f);
    cudaGetSymbolAddress((void**)&p_qf, g_qf);
    cudaGetSymbolAddress((void**)&p_kf, g_kf);
    cudaGetSymbolAddress((void**)&p_vtf, g_vtf);
    cudaGetSymbolAddress((void**)&p_pf, g_pf);
    cudaGetSymbolAddress((void**)&p_ocf, g_ocf);
    cudaGetSymbolAddress((void**)&p_w2f, g_w2f);

    const int SMEM = 2 * (256 + 128) * 128;   // 98304
    cudaFuncSetAttribute((const void*)hgemm<1>, cudaFuncAttributeMaxDynamicSharedMemorySize, SMEM);
    cudaFuncSetAttribute((const void*)hgemm<2>, cudaFuncAttributeMaxDynamicSharedMemorySize, SMEM);
    cudaFuncSetAttribute((const void*)hgemm<3>, cudaFuncAttributeMaxDynamicSharedMemorySize, SMEM);
    cudaFuncSetAttribute((const void*)hgemm<5>, cudaFuncAttributeMaxDynamicSharedMemorySize, SMEM);

    // 1) modulation GEMV
    mod_gemv<<<(3 * HID) / 256, 256>>>(vec, mod_w, mod_b);
    // 2) layernorm + modulation -> xf
    ln_mod_kernel<<<LL, 256>>>(x, gamma, beta);
    // 3) transpose+cast w1 [HID][NN1] -> [NN1][HID]
    transpose_cast<<<dim3(NN1 / 32, HID / 32, 1), dim3(32, 8)>>>(w1, NN1, 0, p_w1f, HID, 0);
    // 4) gemm1: h = xmod @ w1 + b1   (M=2048, N=21504, K=3072)
    hgemm<1><<<dim3(NN1 / 128, LL / 256, 1), 256, SMEM>>>(
        p_xf, HID, 0, p_w1f, HID, 0,
        p_h, NN1, 0, HID, b1, 1.f, nullptr, nullptr, nullptr, 0);
    // 5) rmsnorm + rope -> q/k fp16
    rmsnorm_rope<<<dim3(LL, HH, 2), 128>>>(pe, q_scale, k_scale);
    // 6) v transpose+cast per head: [L][D] -> [D][L]
    transpose_cast<<<dim3(DD / 32, LL / 32, HH), dim3(32, 8)>>>(
        p_h + 2 * HID, NN1, DD, p_vtf, LL, (long)DD * LL);
    // 7) scores = q @ k^T * D^-0.5   (batched over heads)
    hgemm<2><<<dim3(LL / 128, LL / 256, HH), 256, SMEM>>>(
        p_qf, DD, (long)LL * DD, p_kf, DD, (long)LL * DD,
        p_scores, LL, (long)LL * LL, DD, nullptr, 0.08838834764831845f, nullptr, nullptr, nullptr, 0);
    // 8) softmax -> P fp16
    softmax_rows<<<HH * LL, 256>>>();
    // 9) attn = P @ V^T -> oc cols [head*128, +128) fp16
    hgemm<5><<<dim3(1, LL / 256, HH), 256, SMEM>>>(
        p_pf, LL, (long)LL * LL, p_vtf, LL, (long)DD * LL,
        nullptr, NN2, 0, LL, nullptr, 1.f, nullptr, nullptr, p_ocf, DD);
    // 10) gelu(mlp) -> oc fp16
    gelu_cast<<<((size_t)LL * MLPD) / 256, 256>>>();
    // 11) transpose+cast w2 [NN2][HID] -> [HID][NN2]
    transpose_cast<<<dim3(HID / 32, NN2 / 32, 1), dim3(32, 8)>>>(w2, HID, 0, p_w2f, NN2, 0);
    // 12) out = x + gate * (oc @ w2 + b2)   (M=2048, N=3072, K=15360)
    hgemm<3><<<dim3(HID / 128, LL / 256, 1), 256, SMEM>>>(
        p_ocf, NN2, 0, p_w2f, NN2, 0,
        out, HID, 0, NN2, b2, 1.f, x, p_mod + 2 * HID, nullptr, 0);
}

// round 7
// speedup vs baseline: 7.0747x; 1.1486x over previous
#include <cuda_runtime.h>
#include <cuda_fp16.h>
#include <math.h>
#include <stdint.h>

// Problem constants
#define LL   2048
#define HH   24
#define DD   128
#define HID  3072
#define MLPD 12288
#define NN1  21504   // 3*HID + MLP
#define NN2  15360   // HID + MLP
#define EPSF 1e-6f
#define LOG2E 1.4426950408889634f

// ---------------- scratch (static device arrays; no allocs) ----------------
__device__ float g_mod[3 * HID];
__device__ __half g_xf[(size_t)LL * HID];              // x_mod fp16
__device__ __half g_w1f[(size_t)NN1 * HID];            // w1^T fp16 [N][K]
__device__ float  g_h[(size_t)LL * NN1];               // gemm1 out fp32
__device__ __half g_qf[(size_t)HH * LL * DD];          // q (pre-scaled by D^-0.5)
__device__ __half g_kf[(size_t)HH * LL * DD];
__device__ __half g_vf[(size_t)HH * LL * DD];          // v fp16 [h][l][d]
__device__ __half g_ocf[(size_t)LL * NN2];             // attn | gelu(mlp) fp16
__device__ __half g_w2f[(size_t)HID * NN2];            // w2^T fp16 [N][K]

// ---------------- helpers ----------------
__device__ __forceinline__ uint32_t smem_u32(const void* p) {
    uint32_t a;
    asm("{ .reg .u64 t; cvta.to.shared.u64 t, %1; cvt.u32.u64 %0, t; }" : "=r"(a) : "l"(p));
    return a;
}
__device__ __forceinline__ void cpasync16(uint32_t dst, const void* src) {
    asm volatile("cp.async.cg.shared.global [%0], [%1], 16;" :: "r"(dst), "l"(src));
}
__device__ __forceinline__ void cp_commit() { asm volatile("cp.async.commit_group;"); }
__device__ __forceinline__ void cp_wait1()  { asm volatile("cp.async.wait_group 1;" ::: "memory"); }
__device__ __forceinline__ void cp_wait0()  { asm volatile("cp.async.wait_group 0;" ::: "memory"); }

__device__ __forceinline__ void ldsm4(uint32_t& r0, uint32_t& r1, uint32_t& r2, uint32_t& r3, uint32_t a) {
    asm volatile("ldmatrix.sync.aligned.m8n8.x4.shared.b16 {%0,%1,%2,%3}, [%4];"
                 : "=r"(r0), "=r"(r1), "=r"(r2), "=r"(r3) : "r"(a));
}
__device__ __forceinline__ void ldsm4t(uint32_t& r0, uint32_t& r1, uint32_t& r2, uint32_t& r3, uint32_t a) {
    asm volatile("ldmatrix.sync.aligned.m8n8.x4.trans.shared.b16 {%0,%1,%2,%3}, [%4];"
                 : "=r"(r0), "=r"(r1), "=r"(r2), "=r"(r3) : "r"(a));
}
__device__ __forceinline__ void mma16816(float* c, const uint32_t* a, uint32_t b0, uint32_t b1) {
    asm volatile(
        "mma.sync.aligned.m16n8k16.row.col.f32.f16.f16.f32 "
        "{%0,%1,%2,%3},{%4,%5,%6,%7},{%8,%9},{%0,%1,%2,%3};\n"
        : "+f"(c[0]), "+f"(c[1]), "+f"(c[2]), "+f"(c[3])
        : "r"(a[0]), "r"(a[1]), "r"(a[2]), "r"(a[3]), "r"(b0), "r"(b1));
}

// ---------------- fp16 HMMA GEMM (256x128 CTA tile) ----------------
// EPI: 1 +bias -> f32 | 3 resid + gate*(acc+bias) -> f32
template<int EPI>
__global__ void __launch_bounds__(256, 1) hgemm(
    const __half* __restrict__ A, size_t lda, long sA,
    const __half* __restrict__ B, size_t ldb, long sB,
    float* __restrict__ C, size_t ldc, long sC, int K,
    const float* __restrict__ bias, float alpha,
    const float* __restrict__ resid, const float* __restrict__ gate,
    __half* __restrict__ C2, long sC2)
{
    extern __shared__ char smem[];
    constexpr int TILEA = 256 * 128;     // 32 KB
    constexpr int TILEB = 128 * 128;     // 16 KB
    constexpr int STAGE = TILEA + TILEB;
    const uint32_t sb = smem_u32(smem);
    const int tid = threadIdx.x, wid = tid >> 5, lane = tid & 31;
    const int wm = wid & 3, wn = wid >> 2;

    A += (long)blockIdx.z * sA;
    B += (long)blockIdx.z * sB;
    C += (long)blockIdx.z * sC;

    const size_t row0 = (size_t)blockIdx.y * 256;
    const size_t col0 = (size_t)blockIdx.x * 128;
    const __half* baseA = A + row0 * lda;
    const __half* baseB = B + col0 * ldb;

    const int lrow = tid >> 3, lk8 = tid & 7;

    auto load_stage = [&](int s) {
        const uint32_t st = sb + (uint32_t)(s & 1) * STAGE;
        const int ko = s * 64;
        #pragma unroll
        for (int j = 0; j < 8; j++) {
            int row = lrow + j * 32;
            uint32_t dst = st + row * 128 + ((lk8 ^ (row & 7)) << 4);
            cpasync16(dst, (const char*)(baseA + ko + (size_t)row * lda) + lk8 * 16);
        }
        #pragma unroll
        for (int j = 0; j < 4; j++) {
            int row = lrow + j * 32;
            uint32_t dst = st + TILEA + row * 128 + ((lk8 ^ (row & 7)) << 4);
            cpasync16(dst, (const char*)(baseB + ko + (size_t)row * ldb) + lk8 * 16);
        }
    };

    float acc[4][8][4] = {};
    const int S = K >> 6;

    load_stage(0); cp_commit();
    for (int s = 0; s < S; s++) {
        if (s + 1 < S) { load_stage(s + 1); cp_commit(); cp_wait1(); }
        else           { cp_wait0(); }
        __syncthreads();

        const uint32_t st = sb + (uint32_t)(s & 1) * STAGE;
        const uint32_t tA = st, tB = st + TILEA;

        #pragma unroll
        for (int kg = 0; kg < 4; kg++) {
            uint32_t af[4][4];
            {
                int arow = wm * 64 + (lane & 15);
                int ak8 = kg * 2 + (lane >> 4);
                #pragma unroll
                for (int im = 0; im < 4; im++) {
                    int r = arow + im * 16;
                    uint32_t off = r * 128 + ((ak8 ^ (r & 7)) << 4);
                    ldsm4(af[im][0], af[im][1], af[im][2], af[im][3], tA + off);
                }
            }
            int brow_b = wn * 64 + (lane & 7) + ((lane >> 4) << 3);
            int bk8 = kg * 2 + ((lane >> 3) & 1);
            #pragma unroll
            for (int g = 0; g < 4; g++) {
                int r = brow_b + g * 16;
                uint32_t off = r * 128 + ((bk8 ^ (r & 7)) << 4);
                uint32_t b0, b1, b2, b3;
                ldsm4(b0, b1, b2, b3, tB + off);
                #pragma unroll
                for (int im = 0; im < 4; im++) {
                    mma16816(acc[im][2 * g],     af[im], b0, b1);
                    mma16816(acc[im][2 * g + 1], af[im], b2, b3);
                }
            }
        }
        __syncthreads();
    }

    #pragma unroll
    for (int im = 0; im < 4; im++) {
        #pragma unroll
        for (int in = 0; in < 8; in++) {
            size_t m0 = row0 + wm * 64 + im * 16 + (lane >> 2);
            size_t n  = col0 + wn * 64 + in * 8 + (lane & 3) * 2;
            #pragma unroll
            for (int half = 0; half < 2; half++) {
                size_t m = m0 + half * 8;
                float v0 = acc[im][in][half * 2 + 0];
                float v1 = acc[im][in][half * 2 + 1];
                if (EPI == 1)      { v0 += bias[n]; v1 += bias[n + 1]; }
                else if (EPI == 3) {
                    v0 = resid[m * ldc + n]     + gate[n]     * (v0 + bias[n]);
                    v1 = resid[m * ldc + n + 1] + gate[n + 1] * (v1 + bias[n + 1]);
                }
                *(float2*)&C[m * ldc + n] = make_float2(v0, v1);
            }
        }
    }
}

// ---------------- fused flash attention ----------------
// One CTA = (head, 128 q rows). 8 warps, 16 q rows each. Online softmax.
// Q pre-scaled by D^-0.5. Writes O (fp16) into g_ocf cols [head*128, +128).
__global__ void __launch_bounds__(256, 1) flash_attn(
    const __half* __restrict__ Qg, const __half* __restrict__ Kg,
    const __half* __restrict__ Vg, __half* __restrict__ O)
{
    extern __shared__ char smem[];
    const uint32_t sb = smem_u32(smem);
    const int tid = threadIdx.x, wid = tid >> 5, lane = tid & 31;
    const int qb = blockIdx.x, head = blockIdx.y;
    constexpr uint32_t KOFF = 32768, VOFF = 98304;

    const __half* Qh = Qg + ((size_t)head * LL + (size_t)qb * 128) * DD;
    const __half* Kh = Kg + (size_t)head * LL * DD;
    const __half* Vh = Vg + (size_t)head * LL * DD;

    // load a 128x128-half tile as 2 swizzled [128][64] subtiles
    auto load_tile = [&](uint32_t dst, const __half* g) {
        #pragma unroll
        for (int i = 0; i < 8; i++) {
            int c = tid + i * 256;
            int row = c >> 4, ds = c & 15;
            uint32_t off = (uint32_t)(ds >> 3) * 16384 + row * 128 + (((ds & 7) ^ (row & 7)) << 4);
            cpasync16(dst + off, (const char*)g + (size_t)row * 256 + ds * 16);
        }
    };

    load_tile(sb, Qh); cp_commit();
    load_tile(sb + KOFF, Kh); load_tile(sb + VOFF, Vh); cp_commit();
    cp_wait1();
    __syncthreads();

    // persistent Q fragments (warp m16 tile)
    uint32_t qfr[8][4];
    {
        int r = wid * 16 + (lane & 15);
        #pragma unroll
        for (int ks = 0; ks < 8; ks++) {
            int seg = (ks & 3) * 2 + (lane >> 4);
            uint32_t addr = sb + (uint32_t)(ks >> 2) * 16384 + r * 128 + ((seg ^ (r & 7)) << 4);
            ldsm4(qfr[ks][0], qfr[ks][1], qfr[ks][2], qfr[ks][3], addr);
        }
    }

    float oacc[16][4] = {};
    float m0 = -1e30f, m1 = -1e30f, l0 = 0.f, l1 = 0.f;

    for (int j = 0; j < 16; j++) {
        const int buf = j & 1;
        if (j + 1 < 16) {
            load_tile(sb + KOFF + (buf ^ 1) * 32768, Kh + (size_t)(j + 1) * 128 * DD);
            load_tile(sb + VOFF + (buf ^ 1) * 32768, Vh + (size_t)(j + 1) * 128 * DD);
            cp_commit(); cp_wait1();
        } else cp_wait0();
        __syncthreads();

        // S = Q @ K^T (k-dim = d = 128)
        float sacc[16][4] = {};
        const uint32_t tK = sb + KOFF + buf * 32768;
        #pragma unroll
        for (int ks = 0; ks < 8; ks++) {
            #pragma unroll
            for (int g = 0; g < 8; g++) {
                int r = g * 16 + (lane & 7) + ((lane >> 4) << 3);
                int seg = (ks & 3) * 2 + ((lane >> 3) & 1);
                uint32_t addr = tK + (uint32_t)(ks >> 2) * 16384 + r * 128 + ((seg ^ (r & 7)) << 4);
                uint32_t b0, b1, b2, b3;
                ldsm4(b0, b1, b2, b3, addr);
                mma16816(sacc[2 * g],     qfr[ks], b0, b1);
                mma16816(sacc[2 * g + 1], qfr[ks], b2, b3);
            }
        }

        // online softmax (rows r=lane>>2 and r+8; quad butterfly over lane&3)
        float tm0 = -1e30f, tm1 = -1e30f;
        #pragma unroll
        for (int t = 0; t < 16; t++) {
            tm0 = fmaxf(tm0, fmaxf(sacc[t][0], sacc[t][1]));
            tm1 = fmaxf(tm1, fmaxf(sacc[t][2], sacc[t][3]));
        }
        tm0 = fmaxf(tm0, __shfl_xor_sync(~0u, tm0, 1));
        tm0 = fmaxf(tm0, __shfl_xor_sync(~0u, tm0, 2));
        tm1 = fmaxf(tm1, __shfl_xor_sync(~0u, tm1, 1));
        tm1 = fmaxf(tm1, __shfl_xor_sync(~0u, tm1, 2));
        float nm0 = fmaxf(m0, tm0), nm1 = fmaxf(m1, tm1);
        float f0 = exp2f((m0 - nm0) * LOG2E), f1 = exp2f((m1 - nm1) * LOG2E);
        m0 = nm0; m1 = nm1;

        // P = exp(S - m); pack C-frag pairs directly as A-frags for P@V
        uint32_t pP[8][4];
        float rs0 = 0.f, rs1 = 0.f;
        #pragma unroll
        for (int t = 0; t < 8; t++) {
            float p00 = exp2f((sacc[2*t][0]   - nm0) * LOG2E);
            float p01 = exp2f((sacc[2*t][1]   - nm0) * LOG2E);
            float p02 = exp2f((sacc[2*t][2]   - nm1) * LOG2E);
            float p03 = exp2f((sacc[2*t][3]   - nm1) * LOG2E);
            float p10 = exp2f((sacc[2*t+1][0] - nm0) * LOG2E);
            float p11 = exp2f((sacc[2*t+1][1] - nm0) * LOG2E);
            float p12 = exp2f((sacc[2*t+1][2] - nm1) * LOG2E);
            float p13 = exp2f((sacc[2*t+1][3] - nm1) * LOG2E);
            rs0 += p00 + p01 + p10 + p11;
            rs1 += p02 + p03 + p12 + p13;
            __half2 h;
            h = __floats2half2_rn(p00, p01); pP[t][0] = *(uint32_t*)&h;
            h = __floats2half2_rn(p02, p03); pP[t][1] = *(uint32_t*)&h;
            h = __floats2half2_rn(p10, p11); pP[t][2] = *(uint32_t*)&h;
            h = __floats2half2_rn(p12, p13); pP[t][3] = *(uint32_t*)&h;
        }
        rs0 += __shfl_xor_sync(~0u, rs0, 1); rs0 += __shfl_xor_sync(~0u, rs0, 2);
        rs1 += __shfl_xor_sync(~0u, rs1, 1); rs1 += __shfl_xor_sync(~0u, rs1, 2);
        l0 = l0 * f0 + rs0; l1 = l1 * f1 + rs1;
        #pragma unroll
        for (int t = 0; t < 16; t++) {
            oacc[t][0] *= f0; oacc[t][1] *= f0;
            oacc[t][2] *= f1; oacc[t][3] *= f1;
        }

        // O += P @ V  (ldsm.trans on [l][d] gives B (k=l, n=d) fragments)
        const uint32_t tV = sb + VOFF + buf * 32768;
        #pragma unroll
        for (int t = 0; t < 8; t++) {
            #pragma unroll
            for (int g = 0; g < 8; g++) {
                int r = t * 16 + (lane & 7) + (lane & 8);
                int seg = (g & 3) * 2 + (lane >> 4);
                uint32_t addr = tV + (uint32_t)(g >> 2) * 16384 + r * 128 + ((seg ^ (r & 7)) << 4);
                uint32_t b0, b1, b2, b3;
                ldsm4t(b0, b1, b2, b3, addr);
                mma16816(oacc[2 * g],     pP[t], b0, b1);
                mma16816(oacc[2 * g + 1], pP[t], b2, b3);
            }
        }
        __syncthreads();
    }

    // finalize: O /= l, write fp16
    float inv0 = 1.f / l0, inv1 = 1.f / l1;
    size_t m = (size_t)qb * 128 + wid * 16 + (lane >> 2);
    size_t col0 = (size_t)head * 128 + (lane & 3) * 2;
    #pragma unroll
    for (int t = 0; t < 16; t++) {
        __half2 h0 = __floats2half2_rn(oacc[t][0] * inv0, oacc[t][1] * inv0);
        __half2 h1 = __floats2half2_rn(oacc[t][2] * inv1, oacc[t][3] * inv1);
        *(__half2*)&O[m * NN2 + col0 + t * 8]       = h0;
        *(__half2*)&O[(m + 8) * NN2 + col0 + t * 8] = h1;
    }
}

// ---------------- transpose + cast: in [R][Cc] fp32 -> out [Cc][R] fp16 ----------------
__global__ void transpose_cast(const float* __restrict__ in, size_t ld_in, long in_z,
                               __half* __restrict__ o, size_t ld_out, long out_z) {
    __shared__ float t[32][33];
    in += (long)blockIdx.z * in_z;
    o  += (long)blockIdx.z * out_z;
    int c0 = blockIdx.x * 32, r0 = blockIdx.y * 32;
    int tx = threadIdx.x, ty = threadIdx.y;
    #pragma unroll
    for (int j = 0; j < 4; j++)
        t[ty + 8 * j][tx] = in[(size_t)(r0 + ty + 8 * j) * ld_in + c0 + tx];
    __syncthreads();
    #pragma unroll
    for (int j = 0; j < 4; j++) {
        o[(size_t)(c0 + ty + 8 * j) * ld_out + r0 + tx] = __float2half_rn(t[tx][ty + 8 * j]);
    }
}

// ---------------- kernel: mod = silu(vec) @ mod_w + mod_b ----------------
__global__ void mod_gemv(const float* __restrict__ vec,
                         const float* __restrict__ mod_w,
                         const float* __restrict__ mod_b) {
    __shared__ float sv[HID];
    int tid = threadIdx.x;
    for (int i = tid; i < HID; i += blockDim.x) {
        float a = vec[i];
        sv[i] = a / (1.f + __expf(-a));
    }
    __syncthreads();
    int j = blockIdx.x * blockDim.x + tid;
    float acc = 0.f;
    #pragma unroll 4
    for (int k = 0; k < HID; k++)
        acc += sv[k] * mod_w[(size_t)k * (3 * HID) + j];
    g_mod[j] = acc + mod_b[j];
}

// ---------------- layernorm + modulation -> fp16 ----------------
__global__ void ln_mod_kernel(const float* __restrict__ x,
                              const float* __restrict__ gamma,
                              const float* __restrict__ beta) {
    __shared__ float red[32];
    int l = blockIdx.x;
    const float* xr = x + (size_t)l * HID;
    float s = 0.f, s2 = 0.f;
    for (int i = threadIdx.x; i < HID; i += 256) {
        float v = xr[i];
        s += v; s2 += v * v;
    }
    int lane = threadIdx.x & 31, wid = threadIdx.x >> 5;
    #pragma unroll
    for (int o = 16; o; o >>= 1) { s += __shfl_down_sync(~0u, s, o); s2 += __shfl_down_sync(~0u, s2, o); }
    if (lane == 0) { red[wid] = s; red[wid + 8] = s2; }
    __syncthreads();
    float ts = 0.f, ts2 = 0.f;
    if (threadIdx.x < 8) { ts = red[threadIdx.x]; ts2 = red[threadIdx.x + 8]; }
    #pragma unroll
    for (int o = 4; o; o >>= 1) { ts += __shfl_down_sync(0xff, ts, o); ts2 += __shfl_down_sync(0xff, ts2, o); }
    if (threadIdx.x == 0) { red[0] = ts; red[1] = ts2; }
    __syncthreads();
    float mu = red[0] / HID;
    float var = red[1] / HID - mu * mu;
    float rsig = rsqrtf(var + EPSF);
    for (int i = threadIdx.x; i < HID; i += 256) {
        float lnv = (xr[i] - mu) * rsig * gamma[i] + beta[i];
        float v = (1.f + g_mod[HID + i]) * lnv + g_mod[i];
        g_xf[(size_t)l * HID + i] = __float2half_rn(v);
    }
}

// ---------------- rmsnorm + rope (q,k) / cast (v) -> fp16 [h][l][d] ----------------
__global__ void qkv_prep(const float* __restrict__ pe,
                         const float* __restrict__ q_scale,
                         const float* __restrict__ k_scale) {
    int l = blockIdx.x, hd = blockIdx.y, which = blockIdx.z;
    size_t base = (size_t)l * NN1 + (size_t)which * HID + (size_t)hd * DD;
    int d = threadIdx.x;
    float t = g_h[base + d];
    float out;
    size_t oi = ((size_t)hd * LL + l) * DD + d;
    if (which == 2) {
        g_vf[oi] = __float2half_rn(t);
        return;
    }
    const float* sc = which ? k_scale : q_scale;
    __shared__ float red[4];
    float v = t * t;
    #pragma unroll
    for (int o = 16; o; o >>= 1) v += __shfl_down_sync(~0u, v, o);
    if ((d & 31) == 0) red[d >> 5] = v;
    __syncthreads();
    float ss = red[0] + red[1] + red[2] + red[3];
    float r = rsqrtf(ss / DD + EPSF);
    __shared__ float s[DD];
    s[d] = t * r * sc[d];
    __syncthreads();
    int i = d >> 1, j = d & 1;
    const float* p = pe + (((size_t)l * (DD / 2) + i) * 2 + j) * 2;
    out = p[0] * s[2 * i] + p[1] * s[2 * i + 1];
    if (which == 0) out *= 0.08838834764831845f;   // fold D^-0.5 into q
    if (which) g_kf[oi] = __float2half_rn(out);
    else       g_qf[oi] = __float2half_rn(out);
}

// ---------------- gelu(mlp) -> oc fp16 ----------------
__global__ void gelu_cast() {
    size_t idx = (size_t)blockIdx.x * 256 + threadIdx.x;
    size_t l = idx / MLPD;
    size_t m = idx % MLPD;
    float v = g_h[l * NN1 + 3 * HID + m];
    float c = 0.7978845608028654f * (v + 0.044715f * v * v * v);
    float o = 0.5f * v * (1.f + tanhf(c));
    g_ocf[l * NN2 + HID + m] = __float2half_rn(o);
}

// ---------------- launcher ----------------
extern "C" void kernel_launch(void* const* d_in, const int* in_sizes, int n_in,
                              void* d_out, int out_size) {
    const float* x       = (const float*)d_in[0];
    const float* vec     = (const float*)d_in[1];
    const float* pe      = (const float*)d_in[2];
    const float* mod_w   = (const float*)d_in[3];
    const float* mod_b   = (const float*)d_in[4];
    const float* gamma   = (const float*)d_in[5];
    const float* beta    = (const float*)d_in[6];
    const float* w1      = (const float*)d_in[7];
    const float* b1      = (const float*)d_in[8];
    const float* q_scale = (const float*)d_in[9];
    const float* k_scale = (const float*)d_in[10];
    const float* w2      = (const float*)d_in[11];
    const float* b2      = (const float*)d_in[12];
    float* out = (float*)d_out;

    float *p_mod, *p_h;
    __half *p_xf, *p_w1f, *p_qf, *p_kf, *p_vf, *p_ocf, *p_w2f;
    cudaGetSymbolAddress((void**)&p_mod, g_mod);
    cudaGetSymbolAddress((void**)&p_h, g_h);
    cudaGetSymbolAddress((void**)&p_xf, g_xf);
    cudaGetSymbolAddress((void**)&p_w1f, g_w1f);
    cudaGetSymbolAddress((void**)&p_qf, g_qf);
    cudaGetSymbolAddress((void**)&p_kf, g_kf);
    cudaGetSymbolAddress((void**)&p_vf, g_vf);
    cudaGetSymbolAddress((void**)&p_ocf, g_ocf);
    cudaGetSymbolAddress((void**)&p_w2f, g_w2f);

    const int SMEM = 2 * (256 + 128) * 128;   // 98304
    const int FSMEM = 163840;                  // Q 32K + 2x32K K + 2x32K V
    cudaFuncSetAttribute((const void*)hgemm<1>, cudaFuncAttributeMaxDynamicSharedMemorySize, SMEM);
    cudaFuncSetAttribute((const void*)hgemm<3>, cudaFuncAttributeMaxDynamicSharedMemorySize, SMEM);
    cudaFuncSetAttribute((const void*)flash_attn, cudaFuncAttributeMaxDynamicSharedMemorySize, FSMEM);

    // 1) modulation GEMV
    mod_gemv<<<(3 * HID) / 256, 256>>>(vec, mod_w, mod_b);
    // 2) layernorm + modulation -> xf
    ln_mod_kernel<<<LL, 256>>>(x, gamma, beta);
    // 3) transpose+cast w1 [HID][NN1] -> [NN1][HID]
    transpose_cast<<<dim3(NN1 / 32, HID / 32, 1), dim3(32, 8)>>>(w1, NN1, 0, p_w1f, HID, 0);
    // 4) gemm1: h = xmod @ w1 + b1   (M=2048, N=21504, K=3072)
    hgemm<1><<<dim3(NN1 / 128, LL / 256, 1), 256, SMEM>>>(
        p_xf, HID, 0, p_w1f, HID, 0,
        p_h, NN1, 0, HID, b1, 1.f, nullptr, nullptr, nullptr, 0);
    // 5) q/k rmsnorm+rope (+scale on q), v cast -> fp16 [h][l][d]
    qkv_prep<<<dim3(LL, HH, 3), 128>>>(pe, q_scale, k_scale);
    // 6) fused attention -> oc cols [head*128, +128)
    flash_attn<<<dim3(LL / 128, HH), 256, FSMEM>>>(p_qf, p_kf, p_vf, p_ocf);
    // 7) gelu(mlp) -> oc fp16
    gelu_cast<<<((size_t)LL * MLPD) / 256, 256>>>();
    // 8) transpose+cast w2 [NN2][HID] -> [HID][NN2]
    transpose_cast<<<dim3(HID / 32, NN2 / 32, 1), dim3(32, 8)>>>(w2, HID, 0, p_w2f, NN2, 0);
    // 9) out = x + gate * (oc @ w2 + b2)   (M=2048, N=3072, K=15360)
    hgemm<3><<<dim3(HID / 128, LL / 256, 1), 256, SMEM>>>(
        p_ocf, NN2, 0, p_w2f, NN2, 0,
        out, HID, 0, NN2, b2, 1.f, x, p_mod + 2 * HID, nullptr, 0);
}

// round 8
// speedup vs baseline: 8.1353x; 1.1499x over previous
#include <cuda_runtime.h>
#include <cuda_fp16.h>
#include <math.h>
#include <stdint.h>

// Problem constants
#define LL   2048
#define HH   24
#define DD   128
#define HID  3072
#define MLPD 12288
#define NN1  21504   // 3*HID + MLP
#define NN2  15360   // HID + MLP
#define QKV  9216    // 3*HID
#define EPSF 1e-6f
#define LOG2E 1.4426950408889634f
#define KSPLIT 3
#define KCHUNK (NN2 / KSPLIT)   // 5120

// ---------------- scratch (static device arrays; no allocs) ----------------
__device__ float g_mod[3 * HID];
__device__ __half g_xf[(size_t)LL * HID];              // x_mod fp16
__device__ __half g_w1f[(size_t)NN1 * HID];            // w1^T fp16 [N][K]
__device__ float  g_h[(size_t)LL * NN1];               // gemm1 qkv out fp32 (mlp part unused)
__device__ __half g_qf[(size_t)HH * LL * DD];          // q (pre-scaled by D^-0.5)
__device__ __half g_kf[(size_t)HH * LL * DD];
__device__ __half g_vf[(size_t)HH * LL * DD];          // v fp16 [h][l][d]
__device__ __half g_ocf[(size_t)LL * NN2];             // attn | gelu(mlp) fp16
__device__ __half g_w2f[(size_t)HID * NN2];            // w2^T fp16 [N][K]
__device__ float  g_part[(size_t)KSPLIT * LL * HID];   // split-K partials

// ---------------- helpers ----------------
__device__ __forceinline__ uint32_t smem_u32(const void* p) {
    uint32_t a;
    asm("{ .reg .u64 t; cvta.to.shared.u64 t, %1; cvt.u32.u64 %0, t; }" : "=r"(a) : "l"(p));
    return a;
}
__device__ __forceinline__ void cpasync16(uint32_t dst, const void* src) {
    asm volatile("cp.async.cg.shared.global [%0], [%1], 16;" :: "r"(dst), "l"(src));
}
__device__ __forceinline__ void cp_commit() { asm volatile("cp.async.commit_group;"); }
__device__ __forceinline__ void cp_wait1()  { asm volatile("cp.async.wait_group 1;" ::: "memory"); }
__device__ __forceinline__ void cp_wait0()  { asm volatile("cp.async.wait_group 0;" ::: "memory"); }

__device__ __forceinline__ void ldsm4(uint32_t& r0, uint32_t& r1, uint32_t& r2, uint32_t& r3, uint32_t a) {
    asm volatile("ldmatrix.sync.aligned.m8n8.x4.shared.b16 {%0,%1,%2,%3}, [%4];"
                 : "=r"(r0), "=r"(r1), "=r"(r2), "=r"(r3) : "r"(a));
}
__device__ __forceinline__ void ldsm4t(uint32_t& r0, uint32_t& r1, uint32_t& r2, uint32_t& r3, uint32_t a) {
    asm volatile("ldmatrix.sync.aligned.m8n8.x4.trans.shared.b16 {%0,%1,%2,%3}, [%4];"
                 : "=r"(r0), "=r"(r1), "=r"(r2), "=r"(r3) : "r"(a));
}
__device__ __forceinline__ void mma16816(float* c, const uint32_t* a, uint32_t b0, uint32_t b1) {
    asm volatile(
        "mma.sync.aligned.m16n8k16.row.col.f32.f16.f16.f32 "
        "{%0,%1,%2,%3},{%4,%5,%6,%7},{%8,%9},{%0,%1,%2,%3};\n"
        : "+f"(c[0]), "+f"(c[1]), "+f"(c[2]), "+f"(c[3])
        : "r"(a[0]), "r"(a[1]), "r"(a[2]), "r"(a[3]), "r"(b0), "r"(b1));
}
__device__ __forceinline__ float gelu_f(float v) {
    float c = 0.7978845608028654f * (v + 0.044715f * v * v * v);
    return 0.5f * v * (1.f + tanhf(c));
}

// ---------------- fp16 HMMA GEMM (256x128 CTA tile) ----------------
// EPI: 0 plain fp32 | 1 +bias fp32 | 6 mixed: col<QKV -> +bias fp32 C; col>=QKV -> gelu(+bias) fp16 C2
template<int EPI>
__global__ void __launch_bounds__(256, 1) hgemm(
    const __half* __restrict__ A, size_t lda, long sA,
    const __half* __restrict__ B, size_t ldb, long sB,
    float* __restrict__ C, size_t ldc, long sC, int K,
    const float* __restrict__ bias,
    __half* __restrict__ C2, size_t ldc2)
{
    extern __shared__ char smem[];
    constexpr int TILEA = 256 * 128;     // 32 KB
    constexpr int TILEB = 128 * 128;     // 16 KB
    constexpr int STAGE = TILEA + TILEB;
    const uint32_t sb = smem_u32(smem);
    const int tid = threadIdx.x, wid = tid >> 5, lane = tid & 31;
    const int wm = wid & 3, wn = wid >> 2;

    A += (long)blockIdx.z * sA;
    B += (long)blockIdx.z * sB;
    C += (long)blockIdx.z * sC;

    const size_t row0 = (size_t)blockIdx.y * 256;
    const size_t col0 = (size_t)blockIdx.x * 128;
    const __half* baseA = A + row0 * lda;
    const __half* baseB = B + col0 * ldb;

    const int lrow = tid >> 3, lk8 = tid & 7;

    auto load_stage = [&](int s) {
        const uint32_t st = sb + (uint32_t)(s & 1) * STAGE;
        const int ko = s * 64;
        #pragma unroll
        for (int j = 0; j < 8; j++) {
            int row = lrow + j * 32;
            uint32_t dst = st + row * 128 + ((lk8 ^ (row & 7)) << 4);
            cpasync16(dst, (const char*)(baseA + ko + (size_t)row * lda) + lk8 * 16);
        }
        #pragma unroll
        for (int j = 0; j < 4; j++) {
            int row = lrow + j * 32;
            uint32_t dst = st + TILEA + row * 128 + ((lk8 ^ (row & 7)) << 4);
            cpasync16(dst, (const char*)(baseB + ko + (size_t)row * ldb) + lk8 * 16);
        }
    };

    float acc[4][8][4] = {};
    const int S = K >> 6;

    load_stage(0); cp_commit();
    for (int s = 0; s < S; s++) {
        cp_wait0();
        __syncthreads();
        if (s + 1 < S) { load_stage(s + 1); cp_commit(); }

        const uint32_t st = sb + (uint32_t)(s & 1) * STAGE;
        const uint32_t tA = st, tB = st + TILEA;

        #pragma unroll
        for (int kg = 0; kg < 4; kg++) {
            uint32_t af[4][4];
            {
                int arow = wm * 64 + (lane & 15);
                int ak8 = kg * 2 + (lane >> 4);
                #pragma unroll
                for (int im = 0; im < 4; im++) {
                    int r = arow + im * 16;
                    uint32_t off = r * 128 + ((ak8 ^ (r & 7)) << 4);
                    ldsm4(af[im][0], af[im][1], af[im][2], af[im][3], tA + off);
                }
            }
            int brow_b = wn * 64 + (lane & 7) + ((lane >> 4) << 3);
            int bk8 = kg * 2 + ((lane >> 3) & 1);
            #pragma unroll
            for (int g = 0; g < 4; g++) {
                int r = brow_b + g * 16;
                uint32_t off = r * 128 + ((bk8 ^ (r & 7)) << 4);
                uint32_t b0, b1, b2, b3;
                ldsm4(b0, b1, b2, b3, tB + off);
                #pragma unroll
                for (int im = 0; im < 4; im++) {
                    mma16816(acc[im][2 * g],     af[im], b0, b1);
                    mma16816(acc[im][2 * g + 1], af[im], b2, b3);
                }
            }
        }
    }

    const bool do_gelu = (EPI == 6) && (col0 >= QKV);
    #pragma unroll
    for (int im = 0; im < 4; im++) {
        #pragma unroll
        for (int in = 0; in < 8; in++) {
            size_t m0 = row0 + wm * 64 + im * 16 + (lane >> 2);
            size_t n  = col0 + wn * 64 + in * 8 + (lane & 3) * 2;
            #pragma unroll
            for (int half = 0; half < 2; half++) {
                size_t m = m0 + half * 8;
                float v0 = acc[im][in][half * 2 + 0];
                float v1 = acc[im][in][half * 2 + 1];
                if (EPI == 0) {
                    *(float2*)&C[m * ldc + n] = make_float2(v0, v1);
                } else if (EPI == 6) {
                    v0 += bias[n]; v1 += bias[n + 1];
                    if (do_gelu) {
                        __half2 h = __floats2half2_rn(gelu_f(v0), gelu_f(v1));
                        *(__half2*)&C2[m * ldc2 + (n - 6144)] = h;   // QKV - HID = 6144
                    } else {
                        *(float2*)&C[m * ldc + n] = make_float2(v0, v1);
                    }
                } else {   // EPI == 1
                    v0 += bias[n]; v1 += bias[n + 1];
                    *(float2*)&C[m * ldc + n] = make_float2(v0, v1);
                }
            }
        }
    }
}

// ---------------- split-K reduce: out = x + gate*(p0+p1+p2+b2) ----------------
__global__ void reduce_out(const float* __restrict__ x, const float* __restrict__ b2,
                           float* __restrict__ out) {
    size_t i = ((size_t)blockIdx.x * 256 + threadIdx.x) * 4;
    int n = (int)(i % HID);
    float4 p0 = *(const float4*)&g_part[i];
    float4 p1 = *(const float4*)&g_part[(size_t)LL * HID + i];
    float4 p2 = *(const float4*)&g_part[(size_t)2 * LL * HID + i];
    float4 xb = *(const float4*)&x[i];
    float4 bb = *(const float4*)&b2[n];
    float4 gg = *(const float4*)&g_mod[2 * HID + n];
    float4 o;
    o.x = xb.x + gg.x * (p0.x + p1.x + p2.x + bb.x);
    o.y = xb.y + gg.y * (p0.y + p1.y + p2.y + bb.y);
    o.z = xb.z + gg.z * (p0.z + p1.z + p2.z + bb.z);
    o.w = xb.w + gg.w * (p0.w + p1.w + p2.w + bb.w);
    *(float4*)&out[i] = o;
}

// ---------------- fused flash attention ----------------
__global__ void __launch_bounds__(256, 1) flash_attn(
    const __half* __restrict__ Qg, const __half* __restrict__ Kg,
    const __half* __restrict__ Vg, __half* __restrict__ O)
{
    extern __shared__ char smem[];
    const uint32_t sb = smem_u32(smem);
    const int tid = threadIdx.x, wid = tid >> 5, lane = tid & 31;
    const int qb = blockIdx.x, head = blockIdx.y;
    constexpr uint32_t KOFF = 32768, VOFF = 98304;

    const __half* Qh = Qg + ((size_t)head * LL + (size_t)qb * 128) * DD;
    const __half* Kh = Kg + (size_t)head * LL * DD;
    const __half* Vh = Vg + (size_t)head * LL * DD;

    auto load_tile = [&](uint32_t dst, const __half* g) {
        #pragma unroll
        for (int i = 0; i < 8; i++) {
            int c = tid + i * 256;
            int row = c >> 4, ds = c & 15;
            uint32_t off = (uint32_t)(ds >> 3) * 16384 + row * 128 + (((ds & 7) ^ (row & 7)) << 4);
            cpasync16(dst + off, (const char*)g + (size_t)row * 256 + ds * 16);
        }
    };

    load_tile(sb, Qh); cp_commit();
    load_tile(sb + KOFF, Kh); load_tile(sb + VOFF, Vh); cp_commit();
    cp_wait1();
    __syncthreads();

    uint32_t qfr[8][4];
    {
        int r = wid * 16 + (lane & 15);
        #pragma unroll
        for (int ks = 0; ks < 8; ks++) {
            int seg = (ks & 3) * 2 + (lane >> 4);
            uint32_t addr = sb + (uint32_t)(ks >> 2) * 16384 + r * 128 + ((seg ^ (r & 7)) << 4);
            ldsm4(qfr[ks][0], qfr[ks][1], qfr[ks][2], qfr[ks][3], addr);
        }
    }

    float oacc[16][4] = {};
    float m0 = -1e30f, m1 = -1e30f, l0 = 0.f, l1 = 0.f;

    for (int j = 0; j < 16; j++) {
        const int buf = j & 1;
        if (j + 1 < 16) {
            load_tile(sb + KOFF + (buf ^ 1) * 32768, Kh + (size_t)(j + 1) * 128 * DD);
            load_tile(sb + VOFF + (buf ^ 1) * 32768, Vh + (size_t)(j + 1) * 128 * DD);
            cp_commit(); cp_wait1();
        } else cp_wait0();
        __syncthreads();

        float sacc[16][4] = {};
        const uint32_t tK = sb + KOFF + buf * 32768;
        #pragma unroll
        for (int ks = 0; ks < 8; ks++) {
            #pragma unroll
            for (int g = 0; g < 8; g++) {
                int r = g * 16 + (lane & 7) + ((lane >> 4) << 3);
                int seg = (ks & 3) * 2 + ((lane >> 3) & 1);
                uint32_t addr = tK + (uint32_t)(ks >> 2) * 16384 + r * 128 + ((seg ^ (r & 7)) << 4);
                uint32_t b0, b1, b2, b3;
                ldsm4(b0, b1, b2, b3, addr);
                mma16816(sacc[2 * g],     qfr[ks], b0, b1);
                mma16816(sacc[2 * g + 1], qfr[ks], b2, b3);
            }
        }

        float tm0 = -1e30f, tm1 = -1e30f;
        #pragma unroll
        for (int t = 0; t < 16; t++) {
            tm0 = fmaxf(tm0, fmaxf(sacc[t][0], sacc[t][1]));
            tm1 = fmaxf(tm1, fmaxf(sacc[t][2], sacc[t][3]));
        }
        tm0 = fmaxf(tm0, __shfl_xor_sync(~0u, tm0, 1));
        tm0 = fmaxf(tm0, __shfl_xor_sync(~0u, tm0, 2));
        tm1 = fmaxf(tm1, __shfl_xor_sync(~0u, tm1, 1));
        tm1 = fmaxf(tm1, __shfl_xor_sync(~0u, tm1, 2));
        float nm0 = fmaxf(m0, tm0), nm1 = fmaxf(m1, tm1);
        float f0 = exp2f((m0 - nm0) * LOG2E), f1 = exp2f((m1 - nm1) * LOG2E);
        m0 = nm0; m1 = nm1;

        uint32_t pP[8][4];
        float rs0 = 0.f, rs1 = 0.f;
        #pragma unroll
        for (int t = 0; t < 8; t++) {
            float p00 = exp2f((sacc[2*t][0]   - nm0) * LOG2E);
            float p01 = exp2f((sacc[2*t][1]   - nm0) * LOG2E);
            float p02 = exp2f((sacc[2*t][2]   - nm1) * LOG2E);
            float p03 = exp2f((sacc[2*t][3]   - nm1) * LOG2E);
            float p10 = exp2f((sacc[2*t+1][0] - nm0) * LOG2E);
            float p11 = exp2f((sacc[2*t+1][1] - nm0) * LOG2E);
            float p12 = exp2f((sacc[2*t+1][2] - nm1) * LOG2E);
            float p13 = exp2f((sacc[2*t+1][3] - nm1) * LOG2E);
            rs0 += p00 + p01 + p10 + p11;
            rs1 += p02 + p03 + p12 + p13;
            __half2 h;
            h = __floats2half2_rn(p00, p01); pP[t][0] = *(uint32_t*)&h;
            h = __floats2half2_rn(p02, p03); pP[t][1] = *(uint32_t*)&h;
            h = __floats2half2_rn(p10, p11); pP[t][2] = *(uint32_t*)&h;
            h = __floats2half2_rn(p12, p13); pP[t][3] = *(uint32_t*)&h;
        }
        rs0 += __shfl_xor_sync(~0u, rs0, 1); rs0 += __shfl_xor_sync(~0u, rs0, 2);
        rs1 += __shfl_xor_sync(~0u, rs1, 1); rs1 += __shfl_xor_sync(~0u, rs1, 2);
        l0 = l0 * f0 + rs0; l1 = l1 * f1 + rs1;
        #pragma unroll
        for (int t = 0; t < 16; t++) {
            oacc[t][0] *= f0; oacc[t][1] *= f0;
            oacc[t][2] *= f1; oacc[t][3] *= f1;
        }

        const uint32_t tV = sb + VOFF + buf * 32768;
        #pragma unroll
        for (int t = 0; t < 8; t++) {
            #pragma unroll
            for (int g = 0; g < 8; g++) {
                int r = t * 16 + (lane & 7) + (lane & 8);
                int seg = (g & 3) * 2 + (lane >> 4);
                uint32_t addr = tV + (uint32_t)(g >> 2) * 16384 + r * 128 + ((seg ^ (r & 7)) << 4);
                uint32_t b0, b1, b2, b3;
                ldsm4t(b0, b1, b2, b3, addr);
                mma16816(oacc[2 * g],     pP[t], b0, b1);
                mma16816(oacc[2 * g + 1], pP[t], b2, b3);
            }
        }
        __syncthreads();
    }

    float inv0 = 1.f / l0, inv1 = 1.f / l1;
    size_t m = (size_t)qb * 128 + wid * 16 + (lane >> 2);
    size_t col0 = (size_t)head * 128 + (lane & 3) * 2;
    #pragma unroll
    for (int t = 0; t < 16; t++) {
        __half2 h0 = __floats2half2_rn(oacc[t][0] * inv0, oacc[t][1] * inv0);
        __half2 h1 = __floats2half2_rn(oacc[t][2] * inv1, oacc[t][3] * inv1);
        *(__half2*)&O[m * NN2 + col0 + t * 8]       = h0;
        *(__half2*)&O[(m + 8) * NN2 + col0 + t * 8] = h1;
    }
}

// ---------------- transpose + cast: in [R][Cc] fp32 -> out [Cc][R] fp16 ----------------
__global__ void transpose_cast(const float* __restrict__ in, size_t ld_in, long in_z,
                               __half* __restrict__ o, size_t ld_out, long out_z) {
    __shared__ float t[32][33];
    in += (long)blockIdx.z * in_z;
    o  += (long)blockIdx.z * out_z;
    int c0 = blockIdx.x * 32, r0 = blockIdx.y * 32;
    int tx = threadIdx.x, ty = threadIdx.y;
    #pragma unroll
    for (int j = 0; j < 4; j++)
        t[ty + 8 * j][tx] = in[(size_t)(r0 + ty + 8 * j) * ld_in + c0 + tx];
    __syncthreads();
    #pragma unroll
    for (int j = 0; j < 4; j++) {
        o[(size_t)(c0 + ty + 8 * j) * ld_out + r0 + tx] = __float2half_rn(t[tx][ty + 8 * j]);
    }
}

// ---------------- kernel: mod = silu(vec) @ mod_w + mod_b ----------------
__global__ void mod_gemv(const float* __restrict__ vec,
                         const float* __restrict__ mod_w,
                         const float* __restrict__ mod_b) {
    __shared__ float sv[HID];
    int tid = threadIdx.x;
    for (int i = tid; i < HID; i += blockDim.x) {
        float a = vec[i];
        sv[i] = a / (1.f + __expf(-a));
    }
    __syncthreads();
    int j = blockIdx.x * blockDim.x + tid;
    float acc = 0.f;
    #pragma unroll 4
    for (int k = 0; k < HID; k++)
        acc += sv[k] * mod_w[(size_t)k * (3 * HID) + j];
    g_mod[j] = acc + mod_b[j];
}

// ---------------- layernorm + modulation -> fp16 ----------------
__global__ void ln_mod_kernel(const float* __restrict__ x,
                              const float* __restrict__ gamma,
                              const float* __restrict__ beta) {
    __shared__ float red[32];
    int l = blockIdx.x;
    const float* xr = x + (size_t)l * HID;
    float s = 0.f, s2 = 0.f;
    for (int i = threadIdx.x; i < HID; i += 256) {
        float v = xr[i];
        s += v; s2 += v * v;
    }
    int lane = threadIdx.x & 31, wid = threadIdx.x >> 5;
    #pragma unroll
    for (int o = 16; o; o >>= 1) { s += __shfl_down_sync(~0u, s, o); s2 += __shfl_down_sync(~0u, s2, o); }
    if (lane == 0) { red[wid] = s; red[wid + 8] = s2; }
    __syncthreads();
    float ts = 0.f, ts2 = 0.f;
    if (threadIdx.x < 8) { ts = red[threadIdx.x]; ts2 = red[threadIdx.x + 8]; }
    #pragma unroll
    for (int o = 4; o; o >>= 1) { ts += __shfl_down_sync(0xff, ts, o); ts2 += __shfl_down_sync(0xff, ts2, o); }
    if (threadIdx.x == 0) { red[0] = ts; red[1] = ts2; }
    __syncthreads();
    float mu = red[0] / HID;
    float var = red[1] / HID - mu * mu;
    float rsig = rsqrtf(var + EPSF);
    for (int i = threadIdx.x; i < HID; i += 256) {
        float lnv = (xr[i] - mu) * rsig * gamma[i] + beta[i];
        float v = (1.f + g_mod[HID + i]) * lnv + g_mod[i];
        g_xf[(size_t)l * HID + i] = __float2half_rn(v);
    }
}

// ---------------- rmsnorm + rope (q,k) / cast (v) -> fp16 [h][l][d] ----------------
__global__ void qkv_prep(const float* __restrict__ pe,
                         const float* __restrict__ q_scale,
                         const float* __restrict__ k_scale) {
    int l = blockIdx.x, hd = blockIdx.y, which = blockIdx.z;
    size_t base = (size_t)l * NN1 + (size_t)which * HID + (size_t)hd * DD;
    int d = threadIdx.x;
    float t = g_h[base + d];
    size_t oi = ((size_t)hd * LL + l) * DD + d;
    if (which == 2) {
        g_vf[oi] = __float2half_rn(t);
        return;
    }
    const float* sc = which ? k_scale : q_scale;
    __shared__ float red[4];
    float v = t * t;
    #pragma unroll
    for (int o = 16; o; o >>= 1) v += __shfl_down_sync(~0u, v, o);
    if ((d & 31) == 0) red[d >> 5] = v;
    __syncthreads();
    float ss = red[0] + red[1] + red[2] + red[3];
    float r = rsqrtf(ss / DD + EPSF);
    __shared__ float s[DD];
    s[d] = t * r * sc[d];
    __syncthreads();
    int i = d >> 1, j = d & 1;
    const float* p = pe + (((size_t)l * (DD / 2) + i) * 2 + j) * 2;
    float out = p[0] * s[2 * i] + p[1] * s[2 * i + 1];
    if (which == 0) out *= 0.08838834764831845f;   // fold D^-0.5 into q
    if (which) g_kf[oi] = __float2half_rn(out);
    else       g_qf[oi] = __float2half_rn(out);
}

// ---------------- launcher ----------------
extern "C" void kernel_launch(void* const* d_in, const int* in_sizes, int n_in,
                              void* d_out, int out_size) {
    const float* x       = (const float*)d_in[0];
    const float* vec     = (const float*)d_in[1];
    const float* pe      = (const float*)d_in[2];
    const float* mod_w   = (const float*)d_in[3];
    const float* mod_b   = (const float*)d_in[4];
    const float* gamma   = (const float*)d_in[5];
    const float* beta    = (const float*)d_in[6];
    const float* w1      = (const float*)d_in[7];
    const float* b1      = (const float*)d_in[8];
    const float* q_scale = (const float*)d_in[9];
    const float* k_scale = (const float*)d_in[10];
    const float* w2      = (const float*)d_in[11];
    const float* b2      = (const float*)d_in[12];
    float* out = (float*)d_out;

    float *p_h, *p_part;
    __half *p_xf, *p_w1f, *p_qf, *p_kf, *p_vf, *p_ocf, *p_w2f;
    cudaGetSymbolAddress((void**)&p_h, g_h);
    cudaGetSymbolAddress((void**)&p_part, g_part);
    cudaGetSymbolAddress((void**)&p_xf, g_xf);
    cudaGetSymbolAddress((void**)&p_w1f, g_w1f);
    cudaGetSymbolAddress((void**)&p_qf, g_qf);
    cudaGetSymbolAddress((void**)&p_kf, g_kf);
    cudaGetSymbolAddress((void**)&p_vf, g_vf);
    cudaGetSymbolAddress((void**)&p_ocf, g_ocf);
    cudaGetSymbolAddress((void**)&p_w2f, g_w2f);

    const int SMEM = 2 * (256 + 128) * 128;   // 98304
    const int FSMEM = 163840;
    cudaFuncSetAttribute((const void*)hgemm<0>, cudaFuncAttributeMaxDynamicSharedMemorySize, SMEM);
    cudaFuncSetAttribute((const void*)hgemm<6>, cudaFuncAttributeMaxDynamicSharedMemorySize, SMEM);
    cudaFuncSetAttribute((const void*)flash_attn, cudaFuncAttributeMaxDynamicSharedMemorySize, FSMEM);

    // 1) modulation GEMV
    mod_gemv<<<(3 * HID) / 256, 256>>>(vec, mod_w, mod_b);
    // 2) layernorm + modulation -> xf
    ln_mod_kernel<<<LL, 256>>>(x, gamma, beta);
    // 3) transpose+cast w1 [HID][NN1] -> [NN1][HID]
    transpose_cast<<<dim3(NN1 / 32, HID / 32, 1), dim3(32, 8)>>>(w1, NN1, 0, p_w1f, HID, 0);
    // 4) gemm1: qkv -> g_h fp32; mlp -> gelu -> g_ocf fp16 (fused)
    hgemm<6><<<dim3(NN1 / 128, LL / 256, 1), 256, SMEM>>>(
        p_xf, HID, 0, p_w1f, HID, 0,
        p_h, NN1, 0, HID, b1, p_ocf, NN2);
    // 5) q/k rmsnorm+rope (+scale on q), v cast -> fp16 [h][l][d]
    qkv_prep<<<dim3(LL, HH, 3), 128>>>(pe, q_scale, k_scale);
    // 6) fused attention -> oc cols [head*128, +128)
    flash_attn<<<dim3(LL / 128, HH), 256, FSMEM>>>(p_qf, p_kf, p_vf, p_ocf);
    // 7) transpose+cast w2 [NN2][HID] -> [HID][NN2]
    transpose_cast<<<dim3(HID / 32, NN2 / 32, 1), dim3(32, 8)>>>(w2, HID, 0, p_w2f, NN2, 0);
    // 8) gemm2 split-K=3: partials = oc @ w2 (per K slice)
    hgemm<0><<<dim3(HID / 128, LL / 256, KSPLIT), 256, SMEM>>>(
        p_ocf, NN2, KCHUNK, p_w2f, NN2, KCHUNK,
        p_part, HID, (long)LL * HID, KCHUNK, nullptr, nullptr, 0);
    // 9) out = x + gate * (sum partials + b2)
    reduce_out<<<((size_t)LL * HID / 4) / 256, 256>>>(x, b2, out);
}

// round 9
// speedup vs baseline: 8.4026x; 1.0328x over previous
#include <cuda_runtime.h>
#include <cuda_fp16.h>
#include <math.h>
#include <stdint.h>

// Problem constants
#define LL   2048
#define HH   24
#define DD   128
#define HID  3072
#define MLPD 12288
#define NN1  21504   // 3*HID + MLP
#define NN2  15360   // HID + MLP
#define QKV  9216    // 3*HID
#define EPSF 1e-6f
#define LOG2E 1.4426950408889634f
#define KSPLIT 3
#define KCHUNK (NN2 / KSPLIT)   // 5120

// ---------------- scratch (static device arrays; no allocs) ----------------
__device__ float g_mod[3 * HID];
__device__ __half g_xf[(size_t)LL * HID];              // x_mod fp16
__device__ __half g_w1f[(size_t)NN1 * HID];            // w1^T fp16 [N][K]
__device__ float  g_h[(size_t)LL * NN1];               // gemm1 qkv out fp32 (mlp part unused)
__device__ __half g_qf[(size_t)HH * LL * DD];          // q (pre-scaled by D^-0.5)
__device__ __half g_kf[(size_t)HH * LL * DD];
__device__ __half g_vf[(size_t)HH * LL * DD];          // v fp16 [h][l][d]
__device__ __half g_ocf[(size_t)LL * NN2];             // attn | gelu(mlp) fp16
__device__ __half g_w2f[(size_t)HID * NN2];            // w2^T fp16 [N][K]
__device__ float  g_part[(size_t)KSPLIT * LL * HID];   // split-K partials

// ---------------- helpers ----------------
__device__ __forceinline__ uint32_t smem_u32(const void* p) {
    uint32_t a;
    asm("{ .reg .u64 t; cvta.to.shared.u64 t, %1; cvt.u32.u64 %0, t; }" : "=r"(a) : "l"(p));
    return a;
}
__device__ __forceinline__ void cpasync16(uint32_t dst, const void* src) {
    asm volatile("cp.async.cg.shared.global [%0], [%1], 16;" :: "r"(dst), "l"(src));
}
__device__ __forceinline__ void cp_commit() { asm volatile("cp.async.commit_group;"); }
__device__ __forceinline__ void cp_wait1()  { asm volatile("cp.async.wait_group 1;" ::: "memory"); }
__device__ __forceinline__ void cp_wait0()  { asm volatile("cp.async.wait_group 0;" ::: "memory"); }

__device__ __forceinline__ void ldsm4(uint32_t& r0, uint32_t& r1, uint32_t& r2, uint32_t& r3, uint32_t a) {
    asm volatile("ldmatrix.sync.aligned.m8n8.x4.shared.b16 {%0,%1,%2,%3}, [%4];"
                 : "=r"(r0), "=r"(r1), "=r"(r2), "=r"(r3) : "r"(a));
}
__device__ __forceinline__ void ldsm4t(uint32_t& r0, uint32_t& r1, uint32_t& r2, uint32_t& r3, uint32_t a) {
    asm volatile("ldmatrix.sync.aligned.m8n8.x4.trans.shared.b16 {%0,%1,%2,%3}, [%4];"
                 : "=r"(r0), "=r"(r1), "=r"(r2), "=r"(r3) : "r"(a));
}
__device__ __forceinline__ void mma16816(float* c, const uint32_t* a, uint32_t b0, uint32_t b1) {
    asm volatile(
        "mma.sync.aligned.m16n8k16.row.col.f32.f16.f16.f32 "
        "{%0,%1,%2,%3},{%4,%5,%6,%7},{%8,%9},{%0,%1,%2,%3};\n"
        : "+f"(c[0]), "+f"(c[1]), "+f"(c[2]), "+f"(c[3])
        : "r"(a[0]), "r"(a[1]), "r"(a[2]), "r"(a[3]), "r"(b0), "r"(b1));
}
__device__ __forceinline__ float gelu_f(float v) {
    float c = 0.7978845608028654f * (v + 0.044715f * v * v * v);
    return 0.5f * v * (1.f + tanhf(c));
}

// ---------------- fp16 HMMA GEMM (256x128 CTA tile, K-chunk 128) ----------------
// EPI: 0 plain fp32 | 6 mixed: col<QKV -> +bias fp32 C; col>=QKV -> gelu(+bias) fp16 C2
template<int EPI>
__global__ void __launch_bounds__(256, 1) hgemm(
    const __half* __restrict__ A, size_t lda, long sA,
    const __half* __restrict__ B, size_t ldb, long sB,
    float* __restrict__ C, size_t ldc, long sC, int K,
    const float* __restrict__ bias,
    __half* __restrict__ C2, size_t ldc2)
{
    extern __shared__ char smem[];
    constexpr int TILEA = 256 * 256;     // 64 KB: 256 rows x 128 halves
    constexpr int TILEB = 128 * 256;     // 32 KB
    constexpr int STAGE = TILEA + TILEB; // 96 KB
    const uint32_t sb = smem_u32(smem);
    const int tid = threadIdx.x, wid = tid >> 5, lane = tid & 31;
    const int wm = wid & 3, wn = wid >> 2;

    A += (long)blockIdx.z * sA;
    B += (long)blockIdx.z * sB;
    C += (long)blockIdx.z * sC;

    const size_t row0 = (size_t)blockIdx.y * 256;
    const size_t col0 = (size_t)blockIdx.x * 128;
    const __half* baseA = A + row0 * lda;
    const __half* baseB = B + col0 * ldb;

    auto load_stage = [&](int s) {
        const uint32_t st = sb + (uint32_t)(s & 1) * STAGE;
        const int ko = s * 128;
        #pragma unroll
        for (int j = 0; j < 16; j++) {
            int c = tid + j * 256;
            int row = c >> 4, seg = c & 15;
            uint32_t dst = st + row * 256 + ((seg ^ (row & 7)) << 4);
            cpasync16(dst, (const char*)(baseA + ko + (size_t)row * lda) + seg * 16);
        }
        #pragma unroll
        for (int j = 0; j < 8; j++) {
            int c = tid + j * 256;
            int row = c >> 4, seg = c & 15;
            uint32_t dst = st + TILEA + row * 256 + ((seg ^ (row & 7)) << 4);
            cpasync16(dst, (const char*)(baseB + ko + (size_t)row * ldb) + seg * 16);
        }
    };

    float acc[4][8][4] = {};
    const int S = K >> 7;

    load_stage(0); cp_commit();
    for (int s = 0; s < S; s++) {
        cp_wait0();
        __syncthreads();
        if (s + 1 < S) { load_stage(s + 1); cp_commit(); }

        const uint32_t st = sb + (uint32_t)(s & 1) * STAGE;
        const uint32_t tA = st, tB = st + TILEA;

        #pragma unroll
        for (int kg = 0; kg < 8; kg++) {
            uint32_t af[4][4];
            {
                int arow = wm * 64 + (lane & 15);
                int ak8 = kg * 2 + (lane >> 4);
                #pragma unroll
                for (int im = 0; im < 4; im++) {
                    int r = arow + im * 16;
                    uint32_t off = r * 256 + ((ak8 ^ (r & 7)) << 4);
                    ldsm4(af[im][0], af[im][1], af[im][2], af[im][3], tA + off);
                }
            }
            int brow_b = wn * 64 + (lane & 7) + ((lane >> 4) << 3);
            int bk8 = kg * 2 + ((lane >> 3) & 1);
            #pragma unroll
            for (int g = 0; g < 4; g++) {
                int r = brow_b + g * 16;
                uint32_t off = r * 256 + ((bk8 ^ (r & 7)) << 4);
                uint32_t b0, b1, b2, b3;
                ldsm4(b0, b1, b2, b3, tB + off);
                #pragma unroll
                for (int im = 0; im < 4; im++) {
                    mma16816(acc[im][2 * g],     af[im], b0, b1);
                    mma16816(acc[im][2 * g + 1], af[im], b2, b3);
                }
            }
        }
    }

    const bool do_gelu = (EPI == 6) && (col0 >= QKV);
    #pragma unroll
    for (int im = 0; im < 4; im++) {
        #pragma unroll
        for (int in = 0; in < 8; in++) {
            size_t m0 = row0 + wm * 64 + im * 16 + (lane >> 2);
            size_t n  = col0 + wn * 64 + in * 8 + (lane & 3) * 2;
            #pragma unroll
            for (int half = 0; half < 2; half++) {
                size_t m = m0 + half * 8;
                float v0 = acc[im][in][half * 2 + 0];
                float v1 = acc[im][in][half * 2 + 1];
                if (EPI == 0) {
                    *(float2*)&C[m * ldc + n] = make_float2(v0, v1);
                } else {   // EPI == 6
                    v0 += bias[n]; v1 += bias[n + 1];
                    if (do_gelu) {
                        __half2 h = __floats2half2_rn(gelu_f(v0), gelu_f(v1));
                        *(__half2*)&C2[m * ldc2 + (n - 6144)] = h;   // QKV - HID = 6144
                    } else {
                        *(float2*)&C[m * ldc + n] = make_float2(v0, v1);
                    }
                }
            }
        }
    }
}

// ---------------- split-K reduce: out = x + gate*(p0+p1+p2+b2) ----------------
__global__ void reduce_out(const float* __restrict__ x, const float* __restrict__ b2,
                           float* __restrict__ out) {
    size_t i = ((size_t)blockIdx.x * 256 + threadIdx.x) * 4;
    int n = (int)(i % HID);
    float4 p0 = *(const float4*)&g_part[i];
    float4 p1 = *(const float4*)&g_part[(size_t)LL * HID + i];
    float4 p2 = *(const float4*)&g_part[(size_t)2 * LL * HID + i];
    float4 xb = *(const float4*)&x[i];
    float4 bb = *(const float4*)&b2[n];
    float4 gg = *(const float4*)&g_mod[2 * HID + n];
    float4 o;
    o.x = xb.x + gg.x * (p0.x + p1.x + p2.x + bb.x);
    o.y = xb.y + gg.y * (p0.y + p1.y + p2.y + bb.y);
    o.z = xb.z + gg.z * (p0.z + p1.z + p2.z + bb.z);
    o.w = xb.w + gg.w * (p0.w + p1.w + p2.w + bb.w);
    *(float4*)&out[i] = o;
}

// ---------------- fused flash attention ----------------
__global__ void __launch_bounds__(256, 1) flash_attn(
    const __half* __restrict__ Qg, const __half* __restrict__ Kg,
    const __half* __restrict__ Vg, __half* __restrict__ O)
{
    extern __shared__ char smem[];
    const uint32_t sb = smem_u32(smem);
    const int tid = threadIdx.x, wid = tid >> 5, lane = tid & 31;
    const int qb = blockIdx.x, head = blockIdx.y;
    constexpr uint32_t KOFF = 32768, VOFF = 98304;

    const __half* Qh = Qg + ((size_t)head * LL + (size_t)qb * 128) * DD;
    const __half* Kh = Kg + (size_t)head * LL * DD;
    const __half* Vh = Vg + (size_t)head * LL * DD;

    auto load_tile = [&](uint32_t dst, const __half* g) {
        #pragma unroll
        for (int i = 0; i < 8; i++) {
            int c = tid + i * 256;
            int row = c >> 4, ds = c & 15;
            uint32_t off = (uint32_t)(ds >> 3) * 16384 + row * 128 + (((ds & 7) ^ (row & 7)) << 4);
            cpasync16(dst + off, (const char*)g + (size_t)row * 256 + ds * 16);
        }
    };

    load_tile(sb, Qh); cp_commit();
    load_tile(sb + KOFF, Kh); load_tile(sb + VOFF, Vh); cp_commit();
    cp_wait1();
    __syncthreads();

    uint32_t qfr[8][4];
    {
        int r = wid * 16 + (lane & 15);
        #pragma unroll
        for (int ks = 0; ks < 8; ks++) {
            int seg = (ks & 3) * 2 + (lane >> 4);
            uint32_t addr = sb + (uint32_t)(ks >> 2) * 16384 + r * 128 + ((seg ^ (r & 7)) << 4);
            ldsm4(qfr[ks][0], qfr[ks][1], qfr[ks][2], qfr[ks][3], addr);
        }
    }

    float oacc[16][4] = {};
    float m0 = -1e30f, m1 = -1e30f, l0 = 0.f, l1 = 0.f;

    for (int j = 0; j < 16; j++) {
        const int buf = j & 1;
        if (j + 1 < 16) {
            load_tile(sb + KOFF + (buf ^ 1) * 32768, Kh + (size_t)(j + 1) * 128 * DD);
            load_tile(sb + VOFF + (buf ^ 1) * 32768, Vh + (size_t)(j + 1) * 128 * DD);
            cp_commit(); cp_wait1();
        } else cp_wait0();
        __syncthreads();

        float sacc[16][4] = {};
        const uint32_t tK = sb + KOFF + buf * 32768;
        #pragma unroll
        for (int ks = 0; ks < 8; ks++) {
            #pragma unroll
            for (int g = 0; g < 8; g++) {
                int r = g * 16 + (lane & 7) + ((lane >> 4) << 3);
                int seg = (ks & 3) * 2 + ((lane >> 3) & 1);
                uint32_t addr = tK + (uint32_t)(ks >> 2) * 16384 + r * 128 + ((seg ^ (r & 7)) << 4);
                uint32_t b0, b1, b2, b3;
                ldsm4(b0, b1, b2, b3, addr);
                mma16816(sacc[2 * g],     qfr[ks], b0, b1);
                mma16816(sacc[2 * g + 1], qfr[ks], b2, b3);
            }
        }

        float tm0 = -1e30f, tm1 = -1e30f;
        #pragma unroll
        for (int t = 0; t < 16; t++) {
            tm0 = fmaxf(tm0, fmaxf(sacc[t][0], sacc[t][1]));
            tm1 = fmaxf(tm1, fmaxf(sacc[t][2], sacc[t][3]));
        }
        tm0 = fmaxf(tm0, __shfl_xor_sync(~0u, tm0, 1));
        tm0 = fmaxf(tm0, __shfl_xor_sync(~0u, tm0, 2));
        tm1 = fmaxf(tm1, __shfl_xor_sync(~0u, tm1, 1));
        tm1 = fmaxf(tm1, __shfl_xor_sync(~0u, tm1, 2));
        float nm0 = fmaxf(m0, tm0), nm1 = fmaxf(m1, tm1);
        float f0 = exp2f((m0 - nm0) * LOG2E), f1 = exp2f((m1 - nm1) * LOG2E);
        m0 = nm0; m1 = nm1;

        uint32_t pP[8][4];
        float rs0 = 0.f, rs1 = 0.f;
        #pragma unroll
        for (int t = 0; t < 8; t++) {
            float p00 = exp2f((sacc[2*t][0]   - nm0) * LOG2E);
            float p01 = exp2f((sacc[2*t][1]   - nm0) * LOG2E);
            float p02 = exp2f((sacc[2*t][2]   - nm1) * LOG2E);
            float p03 = exp2f((sacc[2*t][3]   - nm1) * LOG2E);
            float p10 = exp2f((sacc[2*t+1][0] - nm0) * LOG2E);
            float p11 = exp2f((sacc[2*t+1][1] - nm0) * LOG2E);
            float p12 = exp2f((sacc[2*t+1][2] - nm1) * LOG2E);
            float p13 = exp2f((sacc[2*t+1][3] - nm1) * LOG2E);
            rs0 += p00 + p01 + p10 + p11;
            rs1 += p02 + p03 + p12 + p13;
            __half2 h;
            h = __floats2half2_rn(p00, p01); pP[t][0] = *(uint32_t*)&h;
            h = __floats2half2_rn(p02, p03); pP[t][1] = *(uint32_t*)&h;
            h = __floats2half2_rn(p10, p11); pP[t][2] = *(uint32_t*)&h;
            h = __floats2half2_rn(p12, p13); pP[t][3] = *(uint32_t*)&h;
        }
        rs0 += __shfl_xor_sync(~0u, rs0, 1); rs0 += __shfl_xor_sync(~0u, rs0, 2);
        rs1 += __shfl_xor_sync(~0u, rs1, 1); rs1 += __shfl_xor_sync(~0u, rs1, 2);
        l0 = l0 * f0 + rs0; l1 = l1 * f1 + rs1;
        #pragma unroll
        for (int t = 0; t < 16; t++) {
            oacc[t][0] *= f0; oacc[t][1] *= f0;
            oacc[t][2] *= f1; oacc[t][3] *= f1;
        }

        const uint32_t tV = sb + VOFF + buf * 32768;
        #pragma unroll
        for (int t = 0; t < 8; t++) {
            #pragma unroll
            for (int g = 0; g < 8; g++) {
                int r = t * 16 + (lane & 7) + (lane & 8);
                int seg = (g & 3) * 2 + (lane >> 4);
                uint32_t addr = tV + (uint32_t)(g >> 2) * 16384 + r * 128 + ((seg ^ (r & 7)) << 4);
                uint32_t b0, b1, b2, b3;
                ldsm4t(b0, b1, b2, b3, addr);
                mma16816(oacc[2 * g],     pP[t], b0, b1);
                mma16816(oacc[2 * g + 1], pP[t], b2, b3);
            }
        }
        __syncthreads();
    }

    float inv0 = 1.f / l0, inv1 = 1.f / l1;
    size_t m = (size_t)qb * 128 + wid * 16 + (lane >> 2);
    size_t col0 = (size_t)head * 128 + (lane & 3) * 2;
    #pragma unroll
    for (int t = 0; t < 16; t++) {
        __half2 h0 = __floats2half2_rn(oacc[t][0] * inv0, oacc[t][1] * inv0);
        __half2 h1 = __floats2half2_rn(oacc[t][2] * inv1, oacc[t][3] * inv1);
        *(__half2*)&O[m * NN2 + col0 + t * 8]       = h0;
        *(__half2*)&O[(m + 8) * NN2 + col0 + t * 8] = h1;
    }
}

// ---------------- transpose + cast: in [R][Cc] fp32 -> out [Cc][R] fp16 ----------------
__global__ void transpose_cast(const float* __restrict__ in, size_t ld_in, long in_z,
                               __half* __restrict__ o, size_t ld_out, long out_z) {
    __shared__ float t[32][33];
    in += (long)blockIdx.z * in_z;
    o  += (long)blockIdx.z * out_z;
    int c0 = blockIdx.x * 32, r0 = blockIdx.y * 32;
    int tx = threadIdx.x, ty = threadIdx.y;
    #pragma unroll
    for (int j = 0; j < 4; j++)
        t[ty + 8 * j][tx] = in[(size_t)(r0 + ty + 8 * j) * ld_in + c0 + tx];
    __syncthreads();
    #pragma unroll
    for (int j = 0; j < 4; j++) {
        o[(size_t)(c0 + ty + 8 * j) * ld_out + r0 + tx] = __float2half_rn(t[tx][ty + 8 * j]);
    }
}

// ---------------- kernel: mod = silu(vec) @ mod_w + mod_b ----------------
__global__ void mod_gemv(const float* __restrict__ vec,
                         const float* __restrict__ mod_w,
                         const float* __restrict__ mod_b) {
    __shared__ float sv[HID];
    int tid = threadIdx.x;
    for (int i = tid; i < HID; i += blockDim.x) {
        float a = vec[i];
        sv[i] = a / (1.f + __expf(-a));
    }
    __syncthreads();
    int j = blockIdx.x * blockDim.x + tid;
    float acc = 0.f;
    #pragma unroll 4
    for (int k = 0; k < HID; k++)
        acc += sv[k] * mod_w[(size_t)k * (3 * HID) + j];
    g_mod[j] = acc + mod_b[j];
}

// ---------------- layernorm + modulation -> fp16 ----------------
__global__ void ln_mod_kernel(const float* __restrict__ x,
                              const float* __restrict__ gamma,
                              const float* __restrict__ beta) {
    __shared__ float red[32];
    int l = blockIdx.x;
    const float* xr = x + (size_t)l * HID;
    float s = 0.f, s2 = 0.f;
    for (int i = threadIdx.x; i < HID; i += 256) {
        float v = xr[i];
        s += v; s2 += v * v;
    }
    int lane = threadIdx.x & 31, wid = threadIdx.x >> 5;
    #pragma unroll
    for (int o = 16; o; o >>= 1) { s += __shfl_down_sync(~0u, s, o); s2 += __shfl_down_sync(~0u, s2, o); }
    if (lane == 0) { red[wid] = s; red[wid + 8] = s2; }
    __syncthreads();
    float ts = 0.f, ts2 = 0.f;
    if (threadIdx.x < 8) { ts = red[threadIdx.x]; ts2 = red[threadIdx.x + 8]; }
    #pragma unroll
    for (int o = 4; o; o >>= 1) { ts += __shfl_down_sync(0xff, ts, o); ts2 += __shfl_down_sync(0xff, ts2, o); }
    if (threadIdx.x == 0) { red[0] = ts; red[1] = ts2; }
    __syncthreads();
    float mu = red[0] / HID;
    float var = red[1] / HID - mu * mu;
    float rsig = rsqrtf(var + EPSF);
    for (int i = threadIdx.x; i < HID; i += 256) {
        float lnv = (xr[i] - mu) * rsig * gamma[i] + beta[i];
        float v = (1.f + g_mod[HID + i]) * lnv + g_mod[i];
        g_xf[(size_t)l * HID + i] = __float2half_rn(v);
    }
}

// ---------------- rmsnorm + rope (q,k) / cast (v) -> fp16 [h][l][d] ----------------
__global__ void qkv_prep(const float* __restrict__ pe,
                         const float* __restrict__ q_scale,
                         const float* __restrict__ k_scale) {
    int l = blockIdx.x, hd = blockIdx.y, which = blockIdx.z;
    size_t base = (size_t)l * NN1 + (size_t)which * HID + (size_t)hd * DD;
    int d = threadIdx.x;
    float t = g_h[base + d];
    size_t oi = ((size_t)hd * LL + l) * DD + d;
    if (which == 2) {
        g_vf[oi] = __float2half_rn(t);
        return;
    }
    const float* sc = which ? k_scale : q_scale;
    __shared__ float red[4];
    float v = t * t;
    #pragma unroll
    for (int o = 16; o; o >>= 1) v += __shfl_down_sync(~0u, v, o);
    if ((d & 31) == 0) red[d >> 5] = v;
    __syncthreads();
    float ss = red[0] + red[1] + red[2] + red[3];
    float r = rsqrtf(ss / DD + EPSF);
    __shared__ float s[DD];
    s[d] = t * r * sc[d];
    __syncthreads();
    int i = d >> 1, j = d & 1;
    const float* p = pe + (((size_t)l * (DD / 2) + i) * 2 + j) * 2;
    float out = p[0] * s[2 * i] + p[1] * s[2 * i + 1];
    if (which == 0) out *= 0.08838834764831845f;   // fold D^-0.5 into q
    if (which) g_kf[oi] = __float2half_rn(out);
    else       g_qf[oi] = __float2half_rn(out);
}

// ---------------- launcher ----------------
extern "C" void kernel_launch(void* const* d_in, const int* in_sizes, int n_in,
                              void* d_out, int out_size) {
    const float* x       = (const float*)d_in[0];
    const float* vec     = (const float*)d_in[1];
    const float* pe      = (const float*)d_in[2];
    const float* mod_w   = (const float*)d_in[3];
    const float* mod_b   = (const float*)d_in[4];
    const float* gamma   = (const float*)d_in[5];
    const float* beta    = (const float*)d_in[6];
    const float* w1      = (const float*)d_in[7];
    const float* b1      = (const float*)d_in[8];
    const float* q_scale = (const float*)d_in[9];
    const float* k_scale = (const float*)d_in[10];
    const float* w2      = (const float*)d_in[11];
    const float* b2      = (const float*)d_in[12];
    float* out = (float*)d_out;

    float *p_h, *p_part;
    __half *p_xf, *p_w1f, *p_qf, *p_kf, *p_vf, *p_ocf, *p_w2f;
    cudaGetSymbolAddress((void**)&p_h, g_h);
    cudaGetSymbolAddress((void**)&p_part, g_part);
    cudaGetSymbolAddress((void**)&p_xf, g_xf);
    cudaGetSymbolAddress((void**)&p_w1f, g_w1f);
    cudaGetSymbolAddress((void**)&p_qf, g_qf);
    cudaGetSymbolAddress((void**)&p_kf, g_kf);
    cudaGetSymbolAddress((void**)&p_vf, g_vf);
    cudaGetSymbolAddress((void**)&p_ocf, g_ocf);
    cudaGetSymbolAddress((void**)&p_w2f, g_w2f);

    const int SMEM = 2 * (256 + 128) * 256;   // 196608
    const int FSMEM = 163840;
    cudaFuncSetAttribute((const void*)hgemm<0>, cudaFuncAttributeMaxDynamicSharedMemorySize, SMEM);
    cudaFuncSetAttribute((const void*)hgemm<6>, cudaFuncAttributeMaxDynamicSharedMemorySize, SMEM);
    cudaFuncSetAttribute((const void*)flash_attn, cudaFuncAttributeMaxDynamicSharedMemorySize, FSMEM);

    // 1) modulation GEMV
    mod_gemv<<<(3 * HID) / 256, 256>>>(vec, mod_w, mod_b);
    // 2) layernorm + modulation -> xf
    ln_mod_kernel<<<LL, 256>>>(x, gamma, beta);
    // 3) transpose+cast w1 [HID][NN1] -> [NN1][HID]
    transpose_cast<<<dim3(NN1 / 32, HID / 32, 1), dim3(32, 8)>>>(w1, NN1, 0, p_w1f, HID, 0);
    // 4) gemm1: qkv -> g_h fp32; mlp -> gelu -> g_ocf fp16 (fused)
    hgemm<6><<<dim3(NN1 / 128, LL / 256, 1), 256, SMEM>>>(
        p_xf, HID, 0, p_w1f, HID, 0,
        p_h, NN1, 0, HID, b1, p_ocf, NN2);
    // 5) q/k rmsnorm+rope (+scale on q), v cast -> fp16 [h][l][d]
    qkv_prep<<<dim3(LL, HH, 3), 128>>>(pe, q_scale, k_scale);
    // 6) fused attention -> oc cols [head*128, +128)
    flash_attn<<<dim3(LL / 128, HH), 256, FSMEM>>>(p_qf, p_kf, p_vf, p_ocf);
    // 7) transpose+cast w2 [NN2][HID] -> [HID][NN2]
    transpose_cast<<<dim3(HID / 32, NN2 / 32, 1), dim3(32, 8)>>>(w2, HID, 0, p_w2f, NN2, 0);
    // 8) gemm2 split-K=3: partials = oc @ w2 (per K slice)
    hgemm<0><<<dim3(HID / 128, LL / 256, KSPLIT), 256, SMEM>>>(
        p_ocf, NN2, KCHUNK, p_w2f, NN2, KCHUNK,
        p_part, HID, (long)LL * HID, KCHUNK, nullptr, nullptr, 0);
    // 9) out = x + gate * (sum partials + b2)
    reduce_out<<<((size_t)LL * HID / 4) / 256, 256>>>(x, b2, out);
}

// round 10
// speedup vs baseline: 10.4360x; 1.2420x over previous
#include <cuda_runtime.h>
#include <cuda_fp16.h>
#include <math.h>
#include <stdint.h>

// Problem constants
#define LL   2048
#define HH   24
#define DD   128
#define HID  3072
#define MLPD 12288
#define NN1  21504   // 3*HID + MLP
#define NN2  15360   // HID + MLP
#define QKV  9216    // 3*HID
#define QK2  6144    // 2*HID
#define EPSF 1e-6f
#define LOG2E 1.4426950408889634f
#define KSPLIT 3
#define KCHUNK (NN2 / KSPLIT)   // 5120
#define MSPLIT 4                // mod_gemv k-split

// ---------------- scratch (static device arrays; no allocs) ----------------
__device__ float g_mod[3 * HID];
__device__ float g_modp[MSPLIT][3 * HID];
__device__ __half g_xf[(size_t)LL * HID];              // x_mod fp16
__device__ __half g_w1f[(size_t)HID * NN1];            // w1 fp16 [K][N]
__device__ float  g_h[(size_t)LL * QK2];               // gemm1 q|k out fp32
__device__ __half g_qf[(size_t)HH * LL * DD];          // q (pre-scaled by D^-0.5)
__device__ __half g_kf[(size_t)HH * LL * DD];
__device__ __half g_vf[(size_t)HH * LL * DD];          // v fp16 [h][l][d]
__device__ __half g_ocf[(size_t)LL * NN2];             // attn | gelu(mlp) fp16
__device__ __half g_w2f[(size_t)NN2 * HID];            // w2 fp16 [K][N]
__device__ float  g_part[(size_t)KSPLIT * LL * HID];   // split-K partials

// ---------------- helpers ----------------
__device__ __forceinline__ uint32_t smem_u32(const void* p) {
    uint32_t a;
    asm("{ .reg .u64 t; cvta.to.shared.u64 t, %1; cvt.u32.u64 %0, t; }" : "=r"(a) : "l"(p));
    return a;
}
__device__ __forceinline__ void cpasync16(uint32_t dst, const void* src) {
    asm volatile("cp.async.cg.shared.global [%0], [%1], 16;" :: "r"(dst), "l"(src));
}
__device__ __forceinline__ void cp_commit() { asm volatile("cp.async.commit_group;"); }
__device__ __forceinline__ void cp_wait1()  { asm volatile("cp.async.wait_group 1;" ::: "memory"); }
__device__ __forceinline__ void cp_wait0()  { asm volatile("cp.async.wait_group 0;" ::: "memory"); }

__device__ __forceinline__ void ldsm4(uint32_t& r0, uint32_t& r1, uint32_t& r2, uint32_t& r3, uint32_t a) {
    asm volatile("ldmatrix.sync.aligned.m8n8.x4.shared.b16 {%0,%1,%2,%3}, [%4];"
                 : "=r"(r0), "=r"(r1), "=r"(r2), "=r"(r3) : "r"(a));
}
__device__ __forceinline__ void ldsm4t(uint32_t& r0, uint32_t& r1, uint32_t& r2, uint32_t& r3, uint32_t a) {
    asm volatile("ldmatrix.sync.aligned.m8n8.x4.trans.shared.b16 {%0,%1,%2,%3}, [%4];"
                 : "=r"(r0), "=r"(r1), "=r"(r2), "=r"(r3) : "r"(a));
}
__device__ __forceinline__ void mma16816(float* c, const uint32_t* a, uint32_t b0, uint32_t b1) {
    asm volatile(
        "mma.sync.aligned.m16n8k16.row.col.f32.f16.f16.f32 "
        "{%0,%1,%2,%3},{%4,%5,%6,%7},{%8,%9},{%0,%1,%2,%3};\n"
        : "+f"(c[0]), "+f"(c[1]), "+f"(c[2]), "+f"(c[3])
        : "r"(a[0]), "r"(a[1]), "r"(a[2]), "r"(a[3]), "r"(b0), "r"(b1));
}
__device__ __forceinline__ float gelu_f(float v) {
    float c = 0.7978845608028654f * (v + 0.044715f * v * v * v);
    return 0.5f * v * (1.f + tanhf(c));
}

// ---------------- fp16 HMMA GEMM ----------------
// A [M][K] row-major fp16; B [K][N] (k-major) fp16 via ldmatrix.trans.
// CTA tile 256x128, K-chunk 128, double-buffered cp.async, swizzled smem.
// EPI: 0 plain fp32 | 6 gemm1 mixed: n<QK2 -> +bias fp32 g_h; [QK2,QKV) -> +bias fp16 V; >=QKV -> gelu(+bias) fp16 C2
template<int EPI>
__global__ void __launch_bounds__(256, 1) hgemm(
    const __half* __restrict__ A, size_t lda, long sA,
    const __half* __restrict__ B, size_t ldb, long sB,
    float* __restrict__ C, size_t ldc, long sC, int K,
    const float* __restrict__ bias,
    __half* __restrict__ C2, size_t ldc2,
    __half* __restrict__ V)
{
    extern __shared__ char smem[];
    constexpr int TILEA = 256 * 256;     // 64 KB: 256 m-rows x 128 k halves
    constexpr int TILEB = 128 * 256;     // 32 KB: 128 k-rows x 128 n halves
    constexpr int STAGE = TILEA + TILEB; // 96 KB
    const uint32_t sb = smem_u32(smem);
    const int tid = threadIdx.x, wid = tid >> 5, lane = tid & 31;
    const int wm = wid & 3, wn = wid >> 2;

    A += (long)blockIdx.z * sA;
    B += (long)blockIdx.z * sB;
    C += (long)blockIdx.z * sC;

    const size_t row0 = (size_t)blockIdx.y * 256;
    const size_t col0 = (size_t)blockIdx.x * 128;
    const __half* baseA = A + row0 * lda;
    const __half* baseB = B + col0;          // [K][N]: advance rows by k

    auto load_stage = [&](int s) {
        const uint32_t st = sb + (uint32_t)(s & 1) * STAGE;
        const int ko = s * 128;
        #pragma unroll
        for (int j = 0; j < 16; j++) {
            int c = tid + j * 256;
            int row = c >> 4, seg = c & 15;
            uint32_t dst = st + row * 256 + ((seg ^ (row & 7)) << 4);
            cpasync16(dst, (const char*)(baseA + ko + (size_t)row * lda) + seg * 16);
        }
        // B: 128 k-rows x 128 n (256B per row within tile)
        #pragma unroll
        for (int j = 0; j < 8; j++) {
            int c = tid + j * 256;
            int row = c >> 4, seg = c & 15;
            uint32_t dst = st + TILEA + row * 256 + ((seg ^ (row & 7)) << 4);
            cpasync16(dst, (const char*)(baseB + (size_t)(ko + row) * ldb) + seg * 16);
        }
    };

    float acc[4][8][4] = {};
    const int S = K >> 7;

    load_stage(0); cp_commit();
    for (int s = 0; s < S; s++) {
        cp_wait0();
        __syncthreads();
        if (s + 1 < S) { load_stage(s + 1); cp_commit(); }

        const uint32_t st = sb + (uint32_t)(s & 1) * STAGE;
        const uint32_t tA = st, tB = st + TILEA;

        #pragma unroll
        for (int kg = 0; kg < 8; kg++) {
            uint32_t af[4][4];
            {
                int arow = wm * 64 + (lane & 15);
                int ak8 = kg * 2 + (lane >> 4);
                #pragma unroll
                for (int im = 0; im < 4; im++) {
                    int r = arow + im * 16;
                    uint32_t off = r * 256 + ((ak8 ^ (r & 7)) << 4);
                    ldsm4(af[im][0], af[im][1], af[im][2], af[im][3], tA + off);
                }
            }
            // B fragments via ldsm.trans on [k][n] tile (mirrors flash V path)
            int brow = kg * 16 + (lane & 7) + (lane & 8);
            #pragma unroll
            for (int g = 0; g < 4; g++) {
                int seg = wn * 8 + g * 2 + (lane >> 4);
                uint32_t off = brow * 256 + ((seg ^ (brow & 7)) << 4);
                uint32_t b0, b1, b2, b3;
                ldsm4t(b0, b1, b2, b3, tB + off);
                #pragma unroll
                for (int im = 0; im < 4; im++) {
                    mma16816(acc[im][2 * g],     af[im], b0, b1);
                    mma16816(acc[im][2 * g + 1], af[im], b2, b3);
                }
            }
        }
    }

    const int mode = (EPI == 6) ? ((col0 >= QKV) ? 2 : (col0 >= QK2 ? 1 : 0)) : 3;
    #pragma unroll
    for (int im = 0; im < 4; im++) {
        #pragma unroll
        for (int in = 0; in < 8; in++) {
            size_t m0 = row0 + wm * 64 + im * 16 + (lane >> 2);
            size_t n  = col0 + wn * 64 + in * 8 + (lane & 3) * 2;
            #pragma unroll
            for (int half = 0; half < 2; half++) {
                size_t m = m0 + half * 8;
                float v0 = acc[im][in][half * 2 + 0];
                float v1 = acc[im][in][half * 2 + 1];
                if (mode == 3) {
                    *(float2*)&C[m * ldc + n] = make_float2(v0, v1);
                } else if (mode == 0) {
                    v0 += bias[n]; v1 += bias[n + 1];
                    *(float2*)&C[m * ldc + n] = make_float2(v0, v1);
                } else if (mode == 1) {
                    v0 += bias[n]; v1 += bias[n + 1];
                    size_t head = (n - QK2) >> 7, d = (n - QK2) & 127;
                    *(__half2*)&V[(head * LL + m) * DD + d] = __floats2half2_rn(v0, v1);
                } else {
                    v0 += bias[n]; v1 += bias[n + 1];
                    __half2 h = __floats2half2_rn(gelu_f(v0), gelu_f(v1));
                    *(__half2*)&C2[m * ldc2 + (n - QK2)] = h;   // QKV - HID = 6144 = QK2
                }
            }
        }
    }
}

// ---------------- split-K reduce: out = x + gate*(p0+p1+p2+b2) ----------------
__global__ void reduce_out(const float* __restrict__ x, const float* __restrict__ b2,
                           float* __restrict__ out) {
    size_t i = ((size_t)blockIdx.x * 256 + threadIdx.x) * 4;
    int n = (int)(i % HID);
    float4 p0 = *(const float4*)&g_part[i];
    float4 p1 = *(const float4*)&g_part[(size_t)LL * HID + i];
    float4 p2 = *(const float4*)&g_part[(size_t)2 * LL * HID + i];
    float4 xb = *(const float4*)&x[i];
    float4 bb = *(const float4*)&b2[n];
    float4 gg = *(const float4*)&g_mod[2 * HID + n];
    float4 o;
    o.x = xb.x + gg.x * (p0.x + p1.x + p2.x + bb.x);
    o.y = xb.y + gg.y * (p0.y + p1.y + p2.y + bb.y);
    o.z = xb.z + gg.z * (p0.z + p1.z + p2.z + bb.z);
    o.w = xb.w + gg.w * (p0.w + p1.w + p2.w + bb.w);
    *(float4*)&out[i] = o;
}

// ---------------- fused flash attention ----------------
__global__ void __launch_bounds__(256, 1) flash_attn(
    const __half* __restrict__ Qg, const __half* __restrict__ Kg,
    const __half* __restrict__ Vg, __half* __restrict__ O)
{
    extern __shared__ char smem[];
    const uint32_t sb = smem_u32(smem);
    const int tid = threadIdx.x, wid = tid >> 5, lane = tid & 31;
    const int qb = blockIdx.x, head = blockIdx.y;
    constexpr uint32_t KOFF = 32768, VOFF = 98304;

    const __half* Qh = Qg + ((size_t)head * LL + (size_t)qb * 128) * DD;
    const __half* Kh = Kg + (size_t)head * LL * DD;
    const __half* Vh = Vg + (size_t)head * LL * DD;

    auto load_tile = [&](uint32_t dst, const __half* g) {
        #pragma unroll
        for (int i = 0; i < 8; i++) {
            int c = tid + i * 256;
            int row = c >> 4, ds = c & 15;
            uint32_t off = (uint32_t)(ds >> 3) * 16384 + row * 128 + (((ds & 7) ^ (row & 7)) << 4);
            cpasync16(dst + off, (const char*)g + (size_t)row * 256 + ds * 16);
        }
    };

    load_tile(sb, Qh); cp_commit();
    load_tile(sb + KOFF, Kh); load_tile(sb + VOFF, Vh); cp_commit();
    cp_wait1();
    __syncthreads();

    uint32_t qfr[8][4];
    {
        int r = wid * 16 + (lane & 15);
        #pragma unroll
        for (int ks = 0; ks < 8; ks++) {
            int seg = (ks & 3) * 2 + (lane >> 4);
            uint32_t addr = sb + (uint32_t)(ks >> 2) * 16384 + r * 128 + ((seg ^ (r & 7)) << 4);
            ldsm4(qfr[ks][0], qfr[ks][1], qfr[ks][2], qfr[ks][3], addr);
        }
    }

    float oacc[16][4] = {};
    float m0 = -1e30f, m1 = -1e30f, l0 = 0.f, l1 = 0.f;

    for (int j = 0; j < 16; j++) {
        const int buf = j & 1;
        if (j + 1 < 16) {
            load_tile(sb + KOFF + (buf ^ 1) * 32768, Kh + (size_t)(j + 1) * 128 * DD);
            load_tile(sb + VOFF + (buf ^ 1) * 32768, Vh + (size_t)(j + 1) * 128 * DD);
            cp_commit(); cp_wait1();
        } else cp_wait0();
        __syncthreads();

        float sacc[16][4] = {};
        const uint32_t tK = sb + KOFF + buf * 32768;
        #pragma unroll
        for (int ks = 0; ks < 8; ks++) {
            #pragma unroll
            for (int g = 0; g < 8; g++) {
                int r = g * 16 + (lane & 7) + ((lane >> 4) << 3);
                int seg = (ks & 3) * 2 + ((lane >> 3) & 1);
                uint32_t addr = tK + (uint32_t)(ks >> 2) * 16384 + r * 128 + ((seg ^ (r & 7)) << 4);
                uint32_t b0, b1, b2, b3;
                ldsm4(b0, b1, b2, b3, addr);
                mma16816(sacc[2 * g],     qfr[ks], b0, b1);
                mma16816(sacc[2 * g + 1], qfr[ks], b2, b3);
            }
        }

        float tm0 = -1e30f, tm1 = -1e30f;
        #pragma unroll
        for (int t = 0; t < 16; t++) {
            tm0 = fmaxf(tm0, fmaxf(sacc[t][0], sacc[t][1]));
            tm1 = fmaxf(tm1, fmaxf(sacc[t][2], sacc[t][3]));
        }
        tm0 = fmaxf(tm0, __shfl_xor_sync(~0u, tm0, 1));
        tm0 = fmaxf(tm0, __shfl_xor_sync(~0u, tm0, 2));
        tm1 = fmaxf(tm1, __shfl_xor_sync(~0u, tm1, 1));
        tm1 = fmaxf(tm1, __shfl_xor_sync(~0u, tm1, 2));
        float nm0 = fmaxf(m0, tm0), nm1 = fmaxf(m1, tm1);
        float f0 = exp2f((m0 - nm0) * LOG2E), f1 = exp2f((m1 - nm1) * LOG2E);
        m0 = nm0; m1 = nm1;

        uint32_t pP[8][4];
        float rs0 = 0.f, rs1 = 0.f;
        #pragma unroll
        for (int t = 0; t < 8; t++) {
            float p00 = exp2f((sacc[2*t][0]   - nm0) * LOG2E);
            float p01 = exp2f((sacc[2*t][1]   - nm0) * LOG2E);
            float p02 = exp2f((sacc[2*t][2]   - nm1) * LOG2E);
            float p03 = exp2f((sacc[2*t][3]   - nm1) * LOG2E);
            float p10 = exp2f((sacc[2*t+1][0] - nm0) * LOG2E);
            float p11 = exp2f((sacc[2*t+1][1] - nm0) * LOG2E);
            float p12 = exp2f((sacc[2*t+1][2] - nm1) * LOG2E);
            float p13 = exp2f((sacc[2*t+1][3] - nm1) * LOG2E);
            rs0 += p00 + p01 + p10 + p11;
            rs1 += p02 + p03 + p12 + p13;
            __half2 h;
            h = __floats2half2_rn(p00, p01); pP[t][0] = *(uint32_t*)&h;
            h = __floats2half2_rn(p02, p03); pP[t][1] = *(uint32_t*)&h;
            h = __floats2half2_rn(p10, p11); pP[t][2] = *(uint32_t*)&h;
            h = __floats2half2_rn(p12, p13); pP[t][3] = *(uint32_t*)&h;
        }
        rs0 += __shfl_xor_sync(~0u, rs0, 1); rs0 += __shfl_xor_sync(~0u, rs0, 2);
        rs1 += __shfl_xor_sync(~0u, rs1, 1); rs1 += __shfl_xor_sync(~0u, rs1, 2);
        l0 = l0 * f0 + rs0; l1 = l1 * f1 + rs1;
        #pragma unroll
        for (int t = 0; t < 16; t++) {
            oacc[t][0] *= f0; oacc[t][1] *= f0;
            oacc[t][2] *= f1; oacc[t][3] *= f1;
        }

        const uint32_t tV = sb + VOFF + buf * 32768;
        #pragma unroll
        for (int t = 0; t < 8; t++) {
            #pragma unroll
            for (int g = 0; g < 8; g++) {
                int r = t * 16 + (lane & 7) + (lane & 8);
                int seg = (g & 3) * 2 + (lane >> 4);
                uint32_t addr = tV + (uint32_t)(g >> 2) * 16384 + r * 128 + ((seg ^ (r & 7)) << 4);
                uint32_t b0, b1, b2, b3;
                ldsm4t(b0, b1, b2, b3, addr);
                mma16816(oacc[2 * g],     pP[t], b0, b1);
                mma16816(oacc[2 * g + 1], pP[t], b2, b3);
            }
        }
        __syncthreads();
    }

    float inv0 = 1.f / l0, inv1 = 1.f / l1;
    size_t m = (size_t)qb * 128 + wid * 16 + (lane >> 2);
    size_t col0 = (size_t)head * 128 + (lane & 3) * 2;
    #pragma unroll
    for (int t = 0; t < 16; t++) {
        __half2 h0 = __floats2half2_rn(oacc[t][0] * inv0, oacc[t][1] * inv0);
        __half2 h1 = __floats2half2_rn(oacc[t][2] * inv1, oacc[t][3] * inv1);
        *(__half2*)&O[m * NN2 + col0 + t * 8]       = h0;
        *(__half2*)&O[(m + 8) * NN2 + col0 + t * 8] = h1;
    }
}

// ---------------- vectorized fp32 -> fp16 cast (same layout) ----------------
__global__ void cast_half(const float* __restrict__ in, __half* __restrict__ o, size_t n8) {
    size_t i = (size_t)blockIdx.x * 256 + threadIdx.x;
    if (i >= n8) return;
    float4 a = *(const float4*)&in[i * 8];
    float4 b = *(const float4*)&in[i * 8 + 4];
    __half2 h[4] = { __floats2half2_rn(a.x, a.y), __floats2half2_rn(a.z, a.w),
                     __floats2half2_rn(b.x, b.y), __floats2half2_rn(b.z, b.w) };
    *(uint2*)&o[i * 8]     = make_uint2(*(uint32_t*)&h[0], *(uint32_t*)&h[1]);
    *(uint2*)&o[i * 8 + 4] = make_uint2(*(uint32_t*)&h[2], *(uint32_t*)&h[3]);
}

// ---------------- mod = silu(vec) @ mod_w + mod_b  (k-split partials) ----------------
__global__ void mod_gemv(const float* __restrict__ vec,
                         const float* __restrict__ mod_w) {
    __shared__ float sv[HID / MSPLIT];
    int tid = threadIdx.x;
    int ks = blockIdx.y;
    int k0 = ks * (HID / MSPLIT);
    for (int i = tid; i < HID / MSPLIT; i += blockDim.x) {
        float a = vec[k0 + i];
        sv[i] = a / (1.f + __expf(-a));
    }
    __syncthreads();
    int j = blockIdx.x * blockDim.x + tid;
    float acc = 0.f;
    #pragma unroll 4
    for (int k = 0; k < HID / MSPLIT; k++)
        acc += sv[k] * mod_w[(size_t)(k0 + k) * (3 * HID) + j];
    g_modp[ks][j] = acc;
}
__global__ void mod_reduce(const float* __restrict__ mod_b) {
    int j = blockIdx.x * 256 + threadIdx.x;
    float s = mod_b[j];
    #pragma unroll
    for (int k = 0; k < MSPLIT; k++) s += g_modp[k][j];
    g_mod[j] = s;
}

// ---------------- layernorm + modulation -> fp16 ----------------
__global__ void ln_mod_kernel(const float* __restrict__ x,
                              const float* __restrict__ gamma,
                              const float* __restrict__ beta) {
    __shared__ float red[32];
    int l = blockIdx.x;
    const float* xr = x + (size_t)l * HID;
    float s = 0.f, s2 = 0.f;
    for (int i = threadIdx.x; i < HID; i += 256) {
        float v = xr[i];
        s += v; s2 += v * v;
    }
    int lane = threadIdx.x & 31, wid = threadIdx.x >> 5;
    #pragma unroll
    for (int o = 16; o; o >>= 1) { s += __shfl_down_sync(~0u, s, o); s2 += __shfl_down_sync(~0u, s2, o); }
    if (lane == 0) { red[wid] = s; red[wid + 8] = s2; }
    __syncthreads();
    float ts = 0.f, ts2 = 0.f;
    if (threadIdx.x < 8) { ts = red[threadIdx.x]; ts2 = red[threadIdx.x + 8]; }
    #pragma unroll
    for (int o = 4; o; o >>= 1) { ts += __shfl_down_sync(0xff, ts, o); ts2 += __shfl_down_sync(0xff, ts2, o); }
    if (threadIdx.x == 0) { red[0] = ts; red[1] = ts2; }
    __syncthreads();
    float mu = red[0] / HID;
    float var = red[1] / HID - mu * mu;
    float rsig = rsqrtf(var + EPSF);
    for (int i = threadIdx.x; i < HID; i += 256) {
        float lnv = (xr[i] - mu) * rsig * gamma[i] + beta[i];
        float v = (1.f + g_mod[HID + i]) * lnv + g_mod[i];
        g_xf[(size_t)l * HID + i] = __float2half_rn(v);
    }
}

// ---------------- rmsnorm + rope (q,k) -> fp16 [h][l][d] ----------------
__global__ void qkv_prep(const float* __restrict__ pe,
                         const float* __restrict__ q_scale,
                         const float* __restrict__ k_scale) {
    int l = blockIdx.x, hd = blockIdx.y, which = blockIdx.z;
    size_t base = (size_t)l * QK2 + (size_t)which * HID + (size_t)hd * DD;
    int d = threadIdx.x;
    float t = g_h[base + d];
    size_t oi = ((size_t)hd * LL + l) * DD + d;
    const float* sc = which ? k_scale : q_scale;
    __shared__ float red[4];
    float v = t * t;
    #pragma unroll
    for (int o = 16; o; o >>= 1) v += __shfl_down_sync(~0u, v, o);
    if ((d & 31) == 0) red[d >> 5] = v;
    __syncthreads();
    float ss = red[0] + red[1] + red[2] + red[3];
    float r = rsqrtf(ss / DD + EPSF);
    __shared__ float s[DD];
    s[d] = t * r * sc[d];
    __syncthreads();
    int i = d >> 1, j = d & 1;
    const float* p = pe + (((size_t)l * (DD / 2) + i) * 2 + j) * 2;
    float out = p[0] * s[2 * i] + p[1] * s[2 * i + 1];
    if (which == 0) out *= 0.08838834764831845f;   // fold D^-0.5 into q
    if (which) g_kf[oi] = __float2half_rn(out);
    else       g_qf[oi] = __float2half_rn(out);
}

// ---------------- launcher ----------------
extern "C" void kernel_launch(void* const* d_in, const int* in_sizes, int n_in,
                              void* d_out, int out_size) {
    const float* x       = (const float*)d_in[0];
    const float* vec     = (const float*)d_in[1];
    const float* pe      = (const float*)d_in[2];
    const float* mod_w   = (const float*)d_in[3];
    const float* mod_b   = (const float*)d_in[4];
    const float* gamma   = (const float*)d_in[5];
    const float* beta    = (const float*)d_in[6];
    const float* w1      = (const float*)d_in[7];
    const float* b1      = (const float*)d_in[8];
    const float* q_scale = (const float*)d_in[9];
    const float* k_scale = (const float*)d_in[10];
    const float* w2      = (const float*)d_in[11];
    const float* b2      = (const float*)d_in[12];
    float* out = (float*)d_out;

    float *p_h, *p_part;
    __half *p_xf, *p_w1f, *p_qf, *p_kf, *p_vf, *p_ocf, *p_w2f;
    cudaGetSymbolAddress((void**)&p_h, g_h);
    cudaGetSymbolAddress((void**)&p_part, g_part);
    cudaGetSymbolAddress((void**)&p_xf, g_xf);
    cudaGetSymbolAddress((void**)&p_w1f, g_w1f);
    cudaGetSymbolAddress((void**)&p_qf, g_qf);
    cudaGetSymbolAddress((void**)&p_kf, g_kf);
    cudaGetSymbolAddress((void**)&p_vf, g_vf);
    cudaGetSymbolAddress((void**)&p_ocf, g_ocf);
    cudaGetSymbolAddress((void**)&p_w2f, g_w2f);

    const int SMEM = 2 * (256 + 128) * 256;   // 196608
    const int FSMEM = 163840;
    cudaFuncSetAttribute((const void*)hgemm<0>, cudaFuncAttributeMaxDynamicSharedMemorySize, SMEM);
    cudaFuncSetAttribute((const void*)hgemm<6>, cudaFuncAttributeMaxDynamicSharedMemorySize, SMEM);
    cudaFuncSetAttribute((const void*)flash_attn, cudaFuncAttributeMaxDynamicSharedMemorySize, FSMEM);

    // 1) modulation GEMV (k-split) + reduce
    mod_gemv<<<dim3((3 * HID) / 256, MSPLIT), 256>>>(vec, mod_w);
    mod_reduce<<<(3 * HID) / 256, 256>>>(mod_b);
    // 2) layernorm + modulation -> xf
    ln_mod_kernel<<<LL, 256>>>(x, gamma, beta);
    // 3) cast w1 [HID][NN1] fp32 -> fp16 (same layout)
    cast_half<<<(unsigned)(((size_t)HID * NN1 / 8 + 255) / 256), 256>>>(w1, p_w1f, (size_t)HID * NN1 / 8);
    // 4) gemm1: q,k -> g_h fp32; v -> g_vf fp16; mlp -> gelu -> g_ocf fp16 (all fused)
    hgemm<6><<<dim3(NN1 / 128, LL / 256, 1), 256, SMEM>>>(
        p_xf, HID, 0, p_w1f, NN1, 0,
        p_h, QK2, 0, HID, b1, p_ocf, NN2, p_vf);
    // 5) q/k rmsnorm+rope (+scale on q) -> fp16 [h][l][d]
    qkv_prep<<<dim3(LL, HH, 2), 128>>>(pe, q_scale, k_scale);
    // 6) fused attention -> oc cols [head*128, +128)
    flash_attn<<<dim3(LL / 128, HH), 256, FSMEM>>>(p_qf, p_kf, p_vf, p_ocf);
    // 7) cast w2 [NN2][HID] fp32 -> fp16 (same layout)
    cast_half<<<(unsigned)(((size_t)NN2 * HID / 8 + 255) / 256), 256>>>(w2, p_w2f, (size_t)NN2 * HID / 8);
    // 8) gemm2 split-K=3: partials = oc @ w2 (per K slice)
    hgemm<0><<<dim3(HID / 128, LL / 256, KSPLIT), 256, SMEM>>>(
        p_ocf, NN2, KCHUNK, p_w2f, HID, (long)KCHUNK * HID,
        p_part, HID, (long)LL * HID, KCHUNK, nullptr, nullptr, 0, nullptr);
    // 9) out = x + gate * (sum partials + b2)
    reduce_out<<<((size_t)LL * HID / 4) / 256, 256>>>(x, b2, out);
}

// round 11
// speedup vs baseline: 10.4441x; 1.0008x over previous
#include <cuda_runtime.h>
#include <cuda_fp16.h>
#include <math.h>
#include <stdint.h>

// Problem constants
#define LL   2048
#define HH   24
#define DD   128
#define HID  3072
#define MLPD 12288
#define NN1  21504   // 3*HID + MLP
#define NN2  15360   // HID + MLP
#define QKV  9216    // 3*HID
#define QK2  6144    // 2*HID
#define EPSF 1e-6f
#define LOG2E 1.4426950408889634f
#define KSPLIT 3
#define KCHUNK (NN2 / KSPLIT)   // 5120
#define MSPLIT 4                // mod_gemv k-split

// ---------------- scratch (static device arrays; no allocs) ----------------
__device__ float g_mod[3 * HID];
__device__ float g_modp[MSPLIT][3 * HID];
__device__ __half g_xf[(size_t)LL * HID];              // x_mod fp16
__device__ __half g_w1f[(size_t)HID * NN1];            // w1 fp16 [K][N]
__device__ __half g_hqk[(size_t)LL * QK2];             // gemm1 q|k out fp16
__device__ __half g_qf[(size_t)HH * LL * DD];          // q (pre-scaled by D^-0.5)
__device__ __half g_kf[(size_t)HH * LL * DD];
__device__ __half g_vf[(size_t)HH * LL * DD];          // v fp16 [h][l][d]
__device__ __half g_ocf[(size_t)LL * NN2];             // attn | gelu(mlp) fp16
__device__ __half g_w2f[(size_t)NN2 * HID];            // w2 fp16 [K][N]
__device__ float  g_part[(size_t)KSPLIT * LL * HID];   // split-K partials

// ---------------- helpers ----------------
__device__ __forceinline__ uint32_t smem_u32(const void* p) {
    uint32_t a;
    asm("{ .reg .u64 t; cvta.to.shared.u64 t, %1; cvt.u32.u64 %0, t; }" : "=r"(a) : "l"(p));
    return a;
}
__device__ __forceinline__ void cpasync16(uint32_t dst, const void* src) {
    asm volatile("cp.async.cg.shared.global [%0], [%1], 16;" :: "r"(dst), "l"(src));
}
__device__ __forceinline__ void cp_commit() { asm volatile("cp.async.commit_group;"); }
__device__ __forceinline__ void cp_wait1()  { asm volatile("cp.async.wait_group 1;" ::: "memory"); }
__device__ __forceinline__ void cp_wait0()  { asm volatile("cp.async.wait_group 0;" ::: "memory"); }

__device__ __forceinline__ void ldsm4(uint32_t& r0, uint32_t& r1, uint32_t& r2, uint32_t& r3, uint32_t a) {
    asm volatile("ldmatrix.sync.aligned.m8n8.x4.shared.b16 {%0,%1,%2,%3}, [%4];"
                 : "=r"(r0), "=r"(r1), "=r"(r2), "=r"(r3) : "r"(a));
}
__device__ __forceinline__ void ldsm4t(uint32_t& r0, uint32_t& r1, uint32_t& r2, uint32_t& r3, uint32_t a) {
    asm volatile("ldmatrix.sync.aligned.m8n8.x4.trans.shared.b16 {%0,%1,%2,%3}, [%4];"
                 : "=r"(r0), "=r"(r1), "=r"(r2), "=r"(r3) : "r"(a));
}
__device__ __forceinline__ void mma16816(float* c, const uint32_t* a, uint32_t b0, uint32_t b1) {
    asm volatile(
        "mma.sync.aligned.m16n8k16.row.col.f32.f16.f16.f32 "
        "{%0,%1,%2,%3},{%4,%5,%6,%7},{%8,%9},{%0,%1,%2,%3};\n"
        : "+f"(c[0]), "+f"(c[1]), "+f"(c[2]), "+f"(c[3])
        : "r"(a[0]), "r"(a[1]), "r"(a[2]), "r"(a[3]), "r"(b0), "r"(b1));
}
__device__ __forceinline__ float gelu_f(float v) {
    float c = 0.7978845608028654f * (v + 0.044715f * v * v * v);
    return 0.5f * v * (1.f + tanhf(c));
}

// ---------------- fp16 HMMA GEMM ----------------
// A [M][K] row-major fp16; B [K][N] (k-major) fp16 via ldmatrix.trans.
// CTA tile 256x128, K-chunk 128, double-buffered cp.async, swizzled smem.
// EPI: 0 plain fp32 | 6 gemm1 mixed: n<QK2 -> +bias fp16 Hqk; [QK2,QKV) -> +bias fp16 V; >=QKV -> gelu(+bias) fp16 C2
template<int EPI>
__global__ void __launch_bounds__(256, 1) hgemm(
    const __half* __restrict__ A, size_t lda, long sA,
    const __half* __restrict__ B, size_t ldb, long sB,
    float* __restrict__ C, size_t ldc, long sC, int K,
    const float* __restrict__ bias,
    __half* __restrict__ C2, size_t ldc2,
    __half* __restrict__ V, __half* __restrict__ Hqk)
{
    extern __shared__ char smem[];
    constexpr int TILEA = 256 * 256;     // 64 KB
    constexpr int TILEB = 128 * 256;     // 32 KB
    constexpr int STAGE = TILEA + TILEB; // 96 KB
    const uint32_t sb = smem_u32(smem);
    const int tid = threadIdx.x, wid = tid >> 5, lane = tid & 31;
    const int wm = wid & 3, wn = wid >> 2;

    A += (long)blockIdx.z * sA;
    B += (long)blockIdx.z * sB;
    C += (long)blockIdx.z * sC;

    const size_t row0 = (size_t)blockIdx.y * 256;
    const size_t col0 = (size_t)blockIdx.x * 128;
    const __half* baseA = A + row0 * lda;
    const __half* baseB = B + col0;          // [K][N]: advance rows by k

    auto load_stage = [&](int s) {
        const uint32_t st = sb + (uint32_t)(s & 1) * STAGE;
        const int ko = s * 128;
        #pragma unroll
        for (int j = 0; j < 16; j++) {
            int c = tid + j * 256;
            int row = c >> 4, seg = c & 15;
            uint32_t dst = st + row * 256 + ((seg ^ (row & 7)) << 4);
            cpasync16(dst, (const char*)(baseA + ko + (size_t)row * lda) + seg * 16);
        }
        #pragma unroll
        for (int j = 0; j < 8; j++) {
            int c = tid + j * 256;
            int row = c >> 4, seg = c & 15;
            uint32_t dst = st + TILEA + row * 256 + ((seg ^ (row & 7)) << 4);
            cpasync16(dst, (const char*)(baseB + (size_t)(ko + row) * ldb) + seg * 16);
        }
    };

    float acc[4][8][4] = {};
    const int S = K >> 7;

    load_stage(0); cp_commit();
    for (int s = 0; s < S; s++) {
        cp_wait0();
        __syncthreads();
        if (s + 1 < S) { load_stage(s + 1); cp_commit(); }

        const uint32_t st = sb + (uint32_t)(s & 1) * STAGE;
        const uint32_t tA = st, tB = st + TILEA;

        #pragma unroll
        for (int kg = 0; kg < 8; kg++) {
            uint32_t af[4][4];
            {
                int arow = wm * 64 + (lane & 15);
                int ak8 = kg * 2 + (lane >> 4);
                #pragma unroll
                for (int im = 0; im < 4; im++) {
                    int r = arow + im * 16;
                    uint32_t off = r * 256 + ((ak8 ^ (r & 7)) << 4);
                    ldsm4(af[im][0], af[im][1], af[im][2], af[im][3], tA + off);
                }
            }
            int brow = kg * 16 + (lane & 7) + (lane & 8);
            #pragma unroll
            for (int g = 0; g < 4; g++) {
                int seg = wn * 8 + g * 2 + (lane >> 4);
                uint32_t off = brow * 256 + ((seg ^ (brow & 7)) << 4);
                uint32_t b0, b1, b2, b3;
                ldsm4t(b0, b1, b2, b3, tB + off);
                #pragma unroll
                for (int im = 0; im < 4; im++) {
                    mma16816(acc[im][2 * g],     af[im], b0, b1);
                    mma16816(acc[im][2 * g + 1], af[im], b2, b3);
                }
            }
        }
    }

    const int mode = (EPI == 6) ? ((col0 >= QKV) ? 2 : (col0 >= QK2 ? 1 : 0)) : 3;
    #pragma unroll
    for (int im = 0; im < 4; im++) {
        #pragma unroll
        for (int in = 0; in < 8; in++) {
            size_t m0 = row0 + wm * 64 + im * 16 + (lane >> 2);
            size_t n  = col0 + wn * 64 + in * 8 + (lane & 3) * 2;
            #pragma unroll
            for (int half = 0; half < 2; half++) {
                size_t m = m0 + half * 8;
                float v0 = acc[im][in][half * 2 + 0];
                float v1 = acc[im][in][half * 2 + 1];
                if (mode == 3) {
                    *(float2*)&C[m * ldc + n] = make_float2(v0, v1);
                } else if (mode == 0) {
                    v0 += bias[n]; v1 += bias[n + 1];
                    *(__half2*)&Hqk[m * QK2 + n] = __floats2half2_rn(v0, v1);
                } else if (mode == 1) {
                    v0 += bias[n]; v1 += bias[n + 1];
                    size_t head = (n - QK2) >> 7, d = (n - QK2) & 127;
                    *(__half2*)&V[(head * LL + m) * DD + d] = __floats2half2_rn(v0, v1);
                } else {
                    v0 += bias[n]; v1 += bias[n + 1];
                    __half2 h = __floats2half2_rn(gelu_f(v0), gelu_f(v1));
                    *(__half2*)&C2[m * ldc2 + (n - QK2)] = h;
                }
            }
        }
    }
}

// ---------------- split-K reduce: out = x + gate*(p0+p1+p2+b2) ----------------
__global__ void reduce_out(const float* __restrict__ x, const float* __restrict__ b2,
                           float* __restrict__ out) {
    size_t i = ((size_t)blockIdx.x * 256 + threadIdx.x) * 4;
    int n = (int)(i % HID);
    float4 p0 = *(const float4*)&g_part[i];
    float4 p1 = *(const float4*)&g_part[(size_t)LL * HID + i];
    float4 p2 = *(const float4*)&g_part[(size_t)2 * LL * HID + i];
    float4 xb = *(const float4*)&x[i];
    float4 bb = *(const float4*)&b2[n];
    float4 gg = *(const float4*)&g_mod[2 * HID + n];
    float4 o;
    o.x = xb.x + gg.x * (p0.x + p1.x + p2.x + bb.x);
    o.y = xb.y + gg.y * (p0.y + p1.y + p2.y + bb.y);
    o.z = xb.z + gg.z * (p0.z + p1.z + p2.z + bb.z);
    o.w = xb.w + gg.w * (p0.w + p1.w + p2.w + bb.w);
    *(float4*)&out[i] = o;
}

// ---------------- fused flash attention ----------------
__global__ void __launch_bounds__(256, 1) flash_attn(
    const __half* __restrict__ Qg, const __half* __restrict__ Kg,
    const __half* __restrict__ Vg, __half* __restrict__ O)
{
    extern __shared__ char smem[];
    const uint32_t sb = smem_u32(smem);
    const int tid = threadIdx.x, wid = tid >> 5, lane = tid & 31;
    const int qb = blockIdx.x, head = blockIdx.y;
    constexpr uint32_t KOFF = 32768, VOFF = 98304;

    const __half* Qh = Qg + ((size_t)head * LL + (size_t)qb * 128) * DD;
    const __half* Kh = Kg + (size_t)head * LL * DD;
    const __half* Vh = Vg + (size_t)head * LL * DD;

    auto load_tile = [&](uint32_t dst, const __half* g) {
        #pragma unroll
        for (int i = 0; i < 8; i++) {
            int c = tid + i * 256;
            int row = c >> 4, ds = c & 15;
            uint32_t off = (uint32_t)(ds >> 3) * 16384 + row * 128 + (((ds & 7) ^ (row & 7)) << 4);
            cpasync16(dst + off, (const char*)g + (size_t)row * 256 + ds * 16);
        }
    };

    load_tile(sb, Qh); cp_commit();
    load_tile(sb + KOFF, Kh); load_tile(sb + VOFF, Vh); cp_commit();
    cp_wait1();
    __syncthreads();

    uint32_t qfr[8][4];
    {
        int r = wid * 16 + (lane & 15);
        #pragma unroll
        for (int ks = 0; ks < 8; ks++) {
            int seg = (ks & 3) * 2 + (lane >> 4);
            uint32_t addr = sb + (uint32_t)(ks >> 2) * 16384 + r * 128 + ((seg ^ (r & 7)) << 4);
            ldsm4(qfr[ks][0], qfr[ks][1], qfr[ks][2], qfr[ks][3], addr);
        }
    }

    float oacc[16][4] = {};
    float m0 = -1e30f, m1 = -1e30f, l0 = 0.f, l1 = 0.f;

    for (int j = 0; j < 16; j++) {
        const int buf = j & 1;
        if (j + 1 < 16) {
            load_tile(sb + KOFF + (buf ^ 1) * 32768, Kh + (size_t)(j + 1) * 128 * DD);
            load_tile(sb + VOFF + (buf ^ 1) * 32768, Vh + (size_t)(j + 1) * 128 * DD);
            cp_commit(); cp_wait1();
        } else cp_wait0();
        __syncthreads();

        float sacc[16][4] = {};
        const uint32_t tK = sb + KOFF + buf * 32768;
        #pragma unroll
        for (int ks = 0; ks < 8; ks++) {
            #pragma unroll
            for (int g = 0; g < 8; g++) {
                int r = g * 16 + (lane & 7) + ((lane >> 4) << 3);
                int seg = (ks & 3) * 2 + ((lane >> 3) & 1);
                uint32_t addr = tK + (uint32_t)(ks >> 2) * 16384 + r * 128 + ((seg ^ (r & 7)) << 4);
                uint32_t b0, b1, b2, b3;
                ldsm4(b0, b1, b2, b3, addr);
                mma16816(sacc[2 * g],     qfr[ks], b0, b1);
                mma16816(sacc[2 * g + 1], qfr[ks], b2, b3);
            }
        }

        float tm0 = -1e30f, tm1 = -1e30f;
        #pragma unroll
        for (int t = 0; t < 16; t++) {
            tm0 = fmaxf(tm0, fmaxf(sacc[t][0], sacc[t][1]));
            tm1 = fmaxf(tm1, fmaxf(sacc[t][2], sacc[t][3]));
        }
        tm0 = fmaxf(tm0, __shfl_xor_sync(~0u, tm0, 1));
        tm0 = fmaxf(tm0, __shfl_xor_sync(~0u, tm0, 2));
        tm1 = fmaxf(tm1, __shfl_xor_sync(~0u, tm1, 1));
        tm1 = fmaxf(tm1, __shfl_xor_sync(~0u, tm1, 2));
        float nm0 = fmaxf(m0, tm0), nm1 = fmaxf(m1, tm1);
        float f0 = exp2f((m0 - nm0) * LOG2E), f1 = exp2f((m1 - nm1) * LOG2E);
        m0 = nm0; m1 = nm1;

        uint32_t pP[8][4];
        float rs0 = 0.f, rs1 = 0.f;
        #pragma unroll
        for (int t = 0; t < 8; t++) {
            float p00 = exp2f((sacc[2*t][0]   - nm0) * LOG2E);
            float p01 = exp2f((sacc[2*t][1]   - nm0) * LOG2E);
            float p02 = exp2f((sacc[2*t][2]   - nm1) * LOG2E);
            float p03 = exp2f((sacc[2*t][3]   - nm1) * LOG2E);
            float p10 = exp2f((sacc[2*t+1][0] - nm0) * LOG2E);
            float p11 = exp2f((sacc[2*t+1][1] - nm0) * LOG2E);
            float p12 = exp2f((sacc[2*t+1][2] - nm1) * LOG2E);
            float p13 = exp2f((sacc[2*t+1][3] - nm1) * LOG2E);
            rs0 += p00 + p01 + p10 + p11;
            rs1 += p02 + p03 + p12 + p13;
            __half2 h;
            h = __floats2half2_rn(p00, p01); pP[t][0] = *(uint32_t*)&h;
            h = __floats2half2_rn(p02, p03); pP[t][1] = *(uint32_t*)&h;
            h = __floats2half2_rn(p10, p11); pP[t][2] = *(uint32_t*)&h;
            h = __floats2half2_rn(p12, p13); pP[t][3] = *(uint32_t*)&h;
        }
        rs0 += __shfl_xor_sync(~0u, rs0, 1); rs0 += __shfl_xor_sync(~0u, rs0, 2);
        rs1 += __shfl_xor_sync(~0u, rs1, 1); rs1 += __shfl_xor_sync(~0u, rs1, 2);
        l0 = l0 * f0 + rs0; l1 = l1 * f1 + rs1;
        #pragma unroll
        for (int t = 0; t < 16; t++) {
            oacc[t][0] *= f0; oacc[t][1] *= f0;
            oacc[t][2] *= f1; oacc[t][3] *= f1;
        }

        const uint32_t tV = sb + VOFF + buf * 32768;
        #pragma unroll
        for (int t = 0; t < 8; t++) {
            #pragma unroll
            for (int g = 0; g < 8; g++) {
                int r = t * 16 + (lane & 7) + (lane & 8);
                int seg = (g & 3) * 2 + (lane >> 4);
                uint32_t addr = tV + (uint32_t)(g >> 2) * 16384 + r * 128 + ((seg ^ (r & 7)) << 4);
                uint32_t b0, b1, b2, b3;
                ldsm4t(b0, b1, b2, b3, addr);
                mma16816(oacc[2 * g],     pP[t], b0, b1);
                mma16816(oacc[2 * g + 1], pP[t], b2, b3);
            }
        }
        __syncthreads();
    }

    float inv0 = 1.f / l0, inv1 = 1.f / l1;
    size_t m = (size_t)qb * 128 + wid * 16 + (lane >> 2);
    size_t col0 = (size_t)head * 128 + (lane & 3) * 2;
    #pragma unroll
    for (int t = 0; t < 16; t++) {
        __half2 h0 = __floats2half2_rn(oacc[t][0] * inv0, oacc[t][1] * inv0);
        __half2 h1 = __floats2half2_rn(oacc[t][2] * inv1, oacc[t][3] * inv1);
        *(__half2*)&O[m * NN2 + col0 + t * 8]       = h0;
        *(__half2*)&O[(m + 8) * NN2 + col0 + t * 8] = h1;
    }
}

// ---------------- vectorized fp32 -> fp16 cast (same layout) ----------------
__global__ void cast_half(const float* __restrict__ in, __half* __restrict__ o, size_t n8) {
    size_t i = (size_t)blockIdx.x * 256 + threadIdx.x;
    if (i >= n8) return;
    float4 a = *(const float4*)&in[i * 8];
    float4 b = *(const float4*)&in[i * 8 + 4];
    __half2 h[4] = { __floats2half2_rn(a.x, a.y), __floats2half2_rn(a.z, a.w),
                     __floats2half2_rn(b.x, b.y), __floats2half2_rn(b.z, b.w) };
    *(uint2*)&o[i * 8]     = make_uint2(*(uint32_t*)&h[0], *(uint32_t*)&h[1]);
    *(uint2*)&o[i * 8 + 4] = make_uint2(*(uint32_t*)&h[2], *(uint32_t*)&h[3]);
}

// ---------------- mod = silu(vec) @ mod_w + mod_b  (k-split partials) ----------------
__global__ void mod_gemv(const float* __restrict__ vec,
                         const float* __restrict__ mod_w) {
    __shared__ float sv[HID / MSPLIT];
    int tid = threadIdx.x;
    int ks = blockIdx.y;
    int k0 = ks * (HID / MSPLIT);
    for (int i = tid; i < HID / MSPLIT; i += blockDim.x) {
        float a = vec[k0 + i];
        sv[i] = a / (1.f + __expf(-a));
    }
    __syncthreads();
    int j = blockIdx.x * blockDim.x + tid;
    float acc = 0.f;
    #pragma unroll 4
    for (int k = 0; k < HID / MSPLIT; k++)
        acc += sv[k] * mod_w[(size_t)(k0 + k) * (3 * HID) + j];
    g_modp[ks][j] = acc;
}
__global__ void mod_reduce(const float* __restrict__ mod_b) {
    int j = blockIdx.x * 256 + threadIdx.x;
    float s = mod_b[j];
    #pragma unroll
    for (int k = 0; k < MSPLIT; k++) s += g_modp[k][j];
    g_mod[j] = s;
}

// ---------------- layernorm + modulation -> fp16 ----------------
__global__ void ln_mod_kernel(const float* __restrict__ x,
                              const float* __restrict__ gamma,
                              const float* __restrict__ beta) {
    __shared__ float red[32];
    int l = blockIdx.x;
    const float* xr = x + (size_t)l * HID;
    float s = 0.f, s2 = 0.f;
    for (int i = threadIdx.x; i < HID; i += 256) {
        float v = xr[i];
        s += v; s2 += v * v;
    }
    int lane = threadIdx.x & 31, wid = threadIdx.x >> 5;
    #pragma unroll
    for (int o = 16; o; o >>= 1) { s += __shfl_down_sync(~0u, s, o); s2 += __shfl_down_sync(~0u, s2, o); }
    if (lane == 0) { red[wid] = s; red[wid + 8] = s2; }
    __syncthreads();
    float ts = 0.f, ts2 = 0.f;
    if (threadIdx.x < 8) { ts = red[threadIdx.x]; ts2 = red[threadIdx.x + 8]; }
    #pragma unroll
    for (int o = 4; o; o >>= 1) { ts += __shfl_down_sync(0xff, ts, o); ts2 += __shfl_down_sync(0xff, ts2, o); }
    if (threadIdx.x == 0) { red[0] = ts; red[1] = ts2; }
    __syncthreads();
    float mu = red[0] / HID;
    float var = red[1] / HID - mu * mu;
    float rsig = rsqrtf(var + EPSF);
    for (int i = threadIdx.x; i < HID; i += 256) {
        float lnv = (xr[i] - mu) * rsig * gamma[i] + beta[i];
        float v = (1.f + g_mod[HID + i]) * lnv + g_mod[i];
        g_xf[(size_t)l * HID + i] = __float2half_rn(v);
    }
}

// ---------------- rmsnorm + rope (q,k) -> fp16 [h][l][d] ----------------
__global__ void qkv_prep(const float* __restrict__ pe,
                         const float* __restrict__ q_scale,
                         const float* __restrict__ k_scale) {
    int l = blockIdx.x, hd = blockIdx.y, which = blockIdx.z;
    size_t base = (size_t)l * QK2 + (size_t)which * HID + (size_t)hd * DD;
    int d = threadIdx.x;
    float t = __half2float(g_hqk[base + d]);
    size_t oi = ((size_t)hd * LL + l) * DD + d;
    const float* sc = which ? k_scale : q_scale;
    __shared__ float red[4];
    float v = t * t;
    #pragma unroll
    for (int o = 16; o; o >>= 1) v += __shfl_down_sync(~0u, v, o);
    if ((d & 31) == 0) red[d >> 5] = v;
    __syncthreads();
    float ss = red[0] + red[1] + red[2] + red[3];
    float r = rsqrtf(ss / DD + EPSF);
    __shared__ float s[DD];
    s[d] = t * r * sc[d];
    __syncthreads();
    int i = d >> 1, j = d & 1;
    const float* p = pe + (((size_t)l * (DD / 2) + i) * 2 + j) * 2;
    float out = p[0] * s[2 * i] + p[1] * s[2 * i + 1];
    if (which == 0) out *= 0.08838834764831845f;   // fold D^-0.5 into q
    if (which) g_kf[oi] = __float2half_rn(out);
    else       g_qf[oi] = __float2half_rn(out);
}

// ---------------- launcher ----------------
extern "C" void kernel_launch(void* const* d_in, const int* in_sizes, int n_in,
                              void* d_out, int out_size) {
    const float* x       = (const float*)d_in[0];
    const float* vec     = (const float*)d_in[1];
    const float* pe      = (const float*)d_in[2];
    const float* mod_w   = (const float*)d_in[3];
    const float* mod_b   = (const float*)d_in[4];
    const float* gamma   = (const float*)d_in[5];
    const float* beta    = (const float*)d_in[6];
    const float* w1      = (const float*)d_in[7];
    const float* b1      = (const float*)d_in[8];
    const float* q_scale = (const float*)d_in[9];
    const float* k_scale = (const float*)d_in[10];
    const float* w2      = (const float*)d_in[11];
    const float* b2      = (const float*)d_in[12];
    float* out = (float*)d_out;

    float *p_part;
    __half *p_xf, *p_w1f, *p_hq, *p_qf, *p_kf, *p_vf, *p_ocf, *p_w2f;
    cudaGetSymbolAddress((void**)&p_part, g_part);
    cudaGetSymbolAddress((void**)&p_xf, g_xf);
    cudaGetSymbolAddress((void**)&p_w1f, g_w1f);
    cudaGetSymbolAddress((void**)&p_hq, g_hqk);
    cudaGetSymbolAddress((void**)&p_qf, g_qf);
    cudaGetSymbolAddress((void**)&p_kf, g_kf);
    cudaGetSymbolAddress((void**)&p_vf, g_vf);
    cudaGetSymbolAddress((void**)&p_ocf, g_ocf);
    cudaGetSymbolAddress((void**)&p_w2f, g_w2f);

    const int SMEM = 2 * (256 + 128) * 256;   // 196608
    const int FSMEM = 163840;
    cudaFuncSetAttribute((const void*)hgemm<0>, cudaFuncAttributeMaxDynamicSharedMemorySize, SMEM);
    cudaFuncSetAttribute((const void*)hgemm<6>, cudaFuncAttributeMaxDynamicSharedMemorySize, SMEM);
    cudaFuncSetAttribute((const void*)flash_attn, cudaFuncAttributeMaxDynamicSharedMemorySize, FSMEM);

    // lazy-init side stream + events (handles only; captured graph identical every call)
    static cudaStream_t s1 = nullptr;
    static cudaEvent_t e_fork = nullptr, e_w1 = nullptr, e_w2 = nullptr;
    if (!s1) {
        cudaStreamCreate(&s1);
        cudaEventCreateWithFlags(&e_fork, cudaEventDisableTiming);
        cudaEventCreateWithFlags(&e_w1, cudaEventDisableTiming);
        cudaEventCreateWithFlags(&e_w2, cudaEventDisableTiming);
    }

    // fork side stream into capture
    cudaEventRecord(e_fork, 0);
    cudaStreamWaitEvent(s1, e_fork, 0);

    // side stream: weight casts
    cast_half<<<(unsigned)(((size_t)HID * NN1 / 8 + 255) / 256), 256, 0, s1>>>(w1, p_w1f, (size_t)HID * NN1 / 8);
    cudaEventRecord(e_w1, s1);
    cast_half<<<(unsigned)(((size_t)NN2 * HID / 8 + 255) / 256), 256, 0, s1>>>(w2, p_w2f, (size_t)NN2 * HID / 8);
    cudaEventRecord(e_w2, s1);

    // main stream
    mod_gemv<<<dim3((3 * HID) / 256, MSPLIT), 256>>>(vec, mod_w);
    mod_reduce<<<(3 * HID) / 256, 256>>>(mod_b);
    ln_mod_kernel<<<LL, 256>>>(x, gamma, beta);

    cudaStreamWaitEvent(0, e_w1, 0);
    // gemm1: q,k -> fp16 g_hqk; v -> g_vf; mlp -> gelu -> g_ocf (all fused)
    hgemm<6><<<dim3(NN1 / 128, LL / 256, 1), 256, SMEM>>>(
        p_xf, HID, 0, p_w1f, NN1, 0,
        nullptr, 0, 0, HID, b1, p_ocf, NN2, p_vf, p_hq);
    qkv_prep<<<dim3(LL, HH, 2), 128>>>(pe, q_scale, k_scale);
    flash_attn<<<dim3(LL / 128, HH), 256, FSMEM>>>(p_qf, p_kf, p_vf, p_ocf);

    cudaStreamWaitEvent(0, e_w2, 0);
    // gemm2 split-K=3: partials = oc @ w2
    hgemm<0><<<dim3(HID / 128, LL / 256, KSPLIT), 256, SMEM>>>(
        p_ocf, NN2, KCHUNK, p_w2f, HID, (long)KCHUNK * HID,
        p_part, HID, (long)LL * HID, KCHUNK, nullptr, nullptr, 0, nullptr, nullptr);
    reduce_out<<<((size_t)LL * HID / 4) / 256, 256>>>(x, b2, out);
}

// round 12
// speedup vs baseline: 10.4612x; 1.0016x over previous
#include <cuda_runtime.h>
#include <cuda_fp16.h>
#include <math.h>
#include <stdint.h>

// Problem constants
#define LL   2048
#define HH   24
#define DD   128
#define HID  3072
#define MLPD 12288
#define NN1  21504   // 3*HID + MLP
#define NN2  15360   // HID + MLP
#define QKV  9216    // 3*HID
#define QK2  6144    // 2*HID
#define EPSF 1e-6f
#define LOG2E 1.4426950408889634f
#define KSPLIT 3
#define KCHUNK (NN2 / KSPLIT)   // 5120
#define MSPLIT 4                // mod_gemv k-split

// ---------------- scratch (static device arrays; no allocs) ----------------
__device__ float g_mod[3 * HID];
__device__ float g_modp[MSPLIT][3 * HID];
__device__ __half g_xf[(size_t)LL * HID];              // x_mod fp16
__device__ __half g_w1f[(size_t)HID * NN1];            // w1 fp16 [K][N]
__device__ __half g_hqk[(size_t)LL * QK2];             // gemm1 q|k out fp16
__device__ __half g_qf[(size_t)HH * LL * DD];          // q (pre-scaled by D^-0.5)
__device__ __half g_kf[(size_t)HH * LL * DD];
__device__ __half g_vf[(size_t)HH * LL * DD];          // v fp16 [h][l][d]
__device__ __half g_ocf[(size_t)LL * NN2];             // attn | gelu(mlp) fp16
__device__ __half g_w2f[(size_t)NN2 * HID];            // w2 fp16 [K][N]
__device__ float  g_part[(size_t)KSPLIT * LL * HID];   // split-K partials

// ---------------- helpers ----------------
__device__ __forceinline__ uint32_t smem_u32(const void* p) {
    uint32_t a;
    asm("{ .reg .u64 t; cvta.to.shared.u64 t, %1; cvt.u32.u64 %0, t; }" : "=r"(a) : "l"(p));
    return a;
}
__device__ __forceinline__ void cpasync16(uint32_t dst, const void* src) {
    asm volatile("cp.async.cg.shared.global [%0], [%1], 16;" :: "r"(dst), "l"(src));
}
__device__ __forceinline__ void cp_commit() { asm volatile("cp.async.commit_group;"); }
__device__ __forceinline__ void cp_wait1()  { asm volatile("cp.async.wait_group 1;" ::: "memory"); }
__device__ __forceinline__ void cp_wait0()  { asm volatile("cp.async.wait_group 0;" ::: "memory"); }

__device__ __forceinline__ void ldsm4(uint32_t& r0, uint32_t& r1, uint32_t& r2, uint32_t& r3, uint32_t a) {
    asm volatile("ldmatrix.sync.aligned.m8n8.x4.shared.b16 {%0,%1,%2,%3}, [%4];"
                 : "=r"(r0), "=r"(r1), "=r"(r2), "=r"(r3) : "r"(a));
}
__device__ __forceinline__ void ldsm4t(uint32_t& r0, uint32_t& r1, uint32_t& r2, uint32_t& r3, uint32_t a) {
    asm volatile("ldmatrix.sync.aligned.m8n8.x4.trans.shared.b16 {%0,%1,%2,%3}, [%4];"
                 : "=r"(r0), "=r"(r1), "=r"(r2), "=r"(r3) : "r"(a));
}
__device__ __forceinline__ void mma16816(float* c, const uint32_t* a, uint32_t b0, uint32_t b1) {
    asm volatile(
        "mma.sync.aligned.m16n8k16.row.col.f32.f16.f16.f32 "
        "{%0,%1,%2,%3},{%4,%5,%6,%7},{%8,%9},{%0,%1,%2,%3};\n"
        : "+f"(c[0]), "+f"(c[1]), "+f"(c[2]), "+f"(c[3])
        : "r"(a[0]), "r"(a[1]), "r"(a[2]), "r"(a[3]), "r"(b0), "r"(b1));
}
__device__ __forceinline__ float gelu_f(float v) {
    float c = 0.7978845608028654f * (v + 0.044715f * v * v * v);
    return 0.5f * v * (1.f + tanhf(c));
}

// ---------------- fp16 HMMA GEMM ----------------
// A [M][K] row-major fp16; B [K][N] (k-major) fp16 via ldmatrix.trans.
// CTA tile 256(m) x 128(n); blockIdx.x -> M (fastest), blockIdx.y -> N.
// M-fastest rasterization: a wave covers all M tiles x few N tiles, so B
// streams from DRAM once and A stays L2-resident.
// EPI: 0 plain fp32 | 6 gemm1 mixed: n<QK2 -> +bias fp16 Hqk; [QK2,QKV) -> +bias fp16 V; >=QKV -> gelu(+bias) fp16 C2
template<int EPI>
__global__ void __launch_bounds__(256, 1) hgemm(
    const __half* __restrict__ A, size_t lda, long sA,
    const __half* __restrict__ B, size_t ldb, long sB,
    float* __restrict__ C, size_t ldc, long sC, int K,
    const float* __restrict__ bias,
    __half* __restrict__ C2, size_t ldc2,
    __half* __restrict__ V, __half* __restrict__ Hqk)
{
    extern __shared__ char smem[];
    constexpr int TILEA = 256 * 256;     // 64 KB
    constexpr int TILEB = 128 * 256;     // 32 KB
    constexpr int STAGE = TILEA + TILEB; // 96 KB
    const uint32_t sb = smem_u32(smem);
    const int tid = threadIdx.x, wid = tid >> 5, lane = tid & 31;
    const int wm = wid & 3, wn = wid >> 2;

    A += (long)blockIdx.z * sA;
    B += (long)blockIdx.z * sB;
    C += (long)blockIdx.z * sC;

    const size_t row0 = (size_t)blockIdx.x * 256;   // M-fastest
    const size_t col0 = (size_t)blockIdx.y * 128;
    const __half* baseA = A + row0 * lda;
    const __half* baseB = B + col0;          // [K][N]: advance rows by k

    auto load_stage = [&](int s) {
        const uint32_t st = sb + (uint32_t)(s & 1) * STAGE;
        const int ko = s * 128;
        #pragma unroll
        for (int j = 0; j < 16; j++) {
            int c = tid + j * 256;
            int row = c >> 4, seg = c & 15;
            uint32_t dst = st + row * 256 + ((seg ^ (row & 7)) << 4);
            cpasync16(dst, (const char*)(baseA + ko + (size_t)row * lda) + seg * 16);
        }
        #pragma unroll
        for (int j = 0; j < 8; j++) {
            int c = tid + j * 256;
            int row = c >> 4, seg = c & 15;
            uint32_t dst = st + TILEA + row * 256 + ((seg ^ (row & 7)) << 4);
            cpasync16(dst, (const char*)(baseB + (size_t)(ko + row) * ldb) + seg * 16);
        }
    };

    float acc[4][8][4] = {};
    const int S = K >> 7;

    load_stage(0); cp_commit();
    for (int s = 0; s < S; s++) {
        cp_wait0();
        __syncthreads();
        if (s + 1 < S) { load_stage(s + 1); cp_commit(); }

        const uint32_t st = sb + (uint32_t)(s & 1) * STAGE;
        const uint32_t tA = st, tB = st + TILEA;

        #pragma unroll
        for (int kg = 0; kg < 8; kg++) {
            uint32_t af[4][4];
            {
                int arow = wm * 64 + (lane & 15);
                int ak8 = kg * 2 + (lane >> 4);
                #pragma unroll
                for (int im = 0; im < 4; im++) {
                    int r = arow + im * 16;
                    uint32_t off = r * 256 + ((ak8 ^ (r & 7)) << 4);
                    ldsm4(af[im][0], af[im][1], af[im][2], af[im][3], tA + off);
                }
            }
            int brow = kg * 16 + (lane & 7) + (lane & 8);
            #pragma unroll
            for (int g = 0; g < 4; g++) {
                int seg = wn * 8 + g * 2 + (lane >> 4);
                uint32_t off = brow * 256 + ((seg ^ (brow & 7)) << 4);
                uint32_t b0, b1, b2, b3;
                ldsm4t(b0, b1, b2, b3, tB + off);
                #pragma unroll
                for (int im = 0; im < 4; im++) {
                    mma16816(acc[im][2 * g],     af[im], b0, b1);
                    mma16816(acc[im][2 * g + 1], af[im], b2, b3);
                }
            }
        }
    }

    const int mode = (EPI == 6) ? ((col0 >= QKV) ? 2 : (col0 >= QK2 ? 1 : 0)) : 3;
    #pragma unroll
    for (int im = 0; im < 4; im++) {
        #pragma unroll
        for (int in = 0; in < 8; in++) {
            size_t m0 = row0 + wm * 64 + im * 16 + (lane >> 2);
            size_t n  = col0 + wn * 64 + in * 8 + (lane & 3) * 2;
            #pragma unroll
            for (int half = 0; half < 2; half++) {
                size_t m = m0 + half * 8;
                float v0 = acc[im][in][half * 2 + 0];
                float v1 = acc[im][in][half * 2 + 1];
                if (mode == 3) {
                    *(float2*)&C[m * ldc + n] = make_float2(v0, v1);
                } else if (mode == 0) {
                    v0 += bias[n]; v1 += bias[n + 1];
                    *(__half2*)&Hqk[m * QK2 + n] = __floats2half2_rn(v0, v1);
                } else if (mode == 1) {
                    v0 += bias[n]; v1 += bias[n + 1];
                    size_t head = (n - QK2) >> 7, d = (n - QK2) & 127;
                    *(__half2*)&V[(head * LL + m) * DD + d] = __floats2half2_rn(v0, v1);
                } else {
                    v0 += bias[n]; v1 += bias[n + 1];
                    __half2 h = __floats2half2_rn(gelu_f(v0), gelu_f(v1));
                    *(__half2*)&C2[m * ldc2 + (n - QK2)] = h;
                }
            }
        }
    }
}

// ---------------- split-K reduce: out = x + gate*(p0+p1+p2+b2) ----------------
__global__ void reduce_out(const float* __restrict__ x, const float* __restrict__ b2,
                           float* __restrict__ out) {
    size_t i = ((size_t)blockIdx.x * 256 + threadIdx.x) * 4;
    int n = (int)(i % HID);
    float4 p0 = *(const float4*)&g_part[i];
    float4 p1 = *(const float4*)&g_part[(size_t)LL * HID + i];
    float4 p2 = *(const float4*)&g_part[(size_t)2 * LL * HID + i];
    float4 xb = *(const float4*)&x[i];
    float4 bb = *(const float4*)&b2[n];
    float4 gg = *(const float4*)&g_mod[2 * HID + n];
    float4 o;
    o.x = xb.x + gg.x * (p0.x + p1.x + p2.x + bb.x);
    o.y = xb.y + gg.y * (p0.y + p1.y + p2.y + bb.y);
    o.z = xb.z + gg.z * (p0.z + p1.z + p2.z + bb.z);
    o.w = xb.w + gg.w * (p0.w + p1.w + p2.w + bb.w);
    *(float4*)&out[i] = o;
}

// ---------------- fused flash attention ----------------
__global__ void __launch_bounds__(256, 1) flash_attn(
    const __half* __restrict__ Qg, const __half* __restrict__ Kg,
    const __half* __restrict__ Vg, __half* __restrict__ O)
{
    extern __shared__ char smem[];
    const uint32_t sb = smem_u32(smem);
    const int tid = threadIdx.x, wid = tid >> 5, lane = tid & 31;
    const int qb = blockIdx.x, head = blockIdx.y;
    constexpr uint32_t KOFF = 32768, VOFF = 98304;

    const __half* Qh = Qg + ((size_t)head * LL + (size_t)qb * 128) * DD;
    const __half* Kh = Kg + (size_t)head * LL * DD;
    const __half* Vh = Vg + (size_t)head * LL * DD;

    auto load_tile = [&](uint32_t dst, const __half* g) {
        #pragma unroll
        for (int i = 0; i < 8; i++) {
            int c = tid + i * 256;
            int row = c >> 4, ds = c & 15;
            uint32_t off = (uint32_t)(ds >> 3) * 16384 + row * 128 + (((ds & 7) ^ (row & 7)) << 4);
            cpasync16(dst + off, (const char*)g + (size_t)row * 256 + ds * 16);
        }
    };

    load_tile(sb, Qh); cp_commit();
    load_tile(sb + KOFF, Kh); load_tile(sb + VOFF, Vh); cp_commit();
    cp_wait1();
    __syncthreads();

    uint32_t qfr[8][4];
    {
        int r = wid * 16 + (lane & 15);
        #pragma unroll
        for (int ks = 0; ks < 8; ks++) {
            int seg = (ks & 3) * 2 + (lane >> 4);
            uint32_t addr = sb + (uint32_t)(ks >> 2) * 16384 + r * 128 + ((seg ^ (r & 7)) << 4);
            ldsm4(qfr[ks][0], qfr[ks][1], qfr[ks][2], qfr[ks][3], addr);
        }
    }

    float oacc[16][4] = {};
    float m0 = -1e30f, m1 = -1e30f, l0 = 0.f, l1 = 0.f;

    for (int j = 0; j < 16; j++) {
        const int buf = j & 1;
        if (j + 1 < 16) {
            load_tile(sb + KOFF + (buf ^ 1) * 32768, Kh + (size_t)(j + 1) * 128 * DD);
            load_tile(sb + VOFF + (buf ^ 1) * 32768, Vh + (size_t)(j + 1) * 128 * DD);
            cp_commit(); cp_wait1();
        } else cp_wait0();
        __syncthreads();

        float sacc[16][4] = {};
        const uint32_t tK = sb + KOFF + buf * 32768;
        #pragma unroll
        for (int ks = 0; ks < 8; ks++) {
            #pragma unroll
            for (int g = 0; g < 8; g++) {
                int r = g * 16 + (lane & 7) + ((lane >> 4) << 3);
                int seg = (ks & 3) * 2 + ((lane >> 3) & 1);
                uint32_t addr = tK + (uint32_t)(ks >> 2) * 16384 + r * 128 + ((seg ^ (r & 7)) << 4);
                uint32_t b0, b1, b2, b3;
                ldsm4(b0, b1, b2, b3, addr);
                mma16816(sacc[2 * g],     qfr[ks], b0, b1);
                mma16816(sacc[2 * g + 1], qfr[ks], b2, b3);
            }
        }

        float tm0 = -1e30f, tm1 = -1e30f;
        #pragma unroll
        for (int t = 0; t < 16; t++) {
            tm0 = fmaxf(tm0, fmaxf(sacc[t][0], sacc[t][1]));
            tm1 = fmaxf(tm1, fmaxf(sacc[t][2], sacc[t][3]));
        }
        tm0 = fmaxf(tm0, __shfl_xor_sync(~0u, tm0, 1));
        tm0 = fmaxf(tm0, __shfl_xor_sync(~0u, tm0, 2));
        tm1 = fmaxf(tm1, __shfl_xor_sync(~0u, tm1, 1));
        tm1 = fmaxf(tm1, __shfl_xor_sync(~0u, tm1, 2));
        float nm0 = fmaxf(m0, tm0), nm1 = fmaxf(m1, tm1);
        float f0 = exp2f((m0 - nm0) * LOG2E), f1 = exp2f((m1 - nm1) * LOG2E);
        m0 = nm0; m1 = nm1;

        uint32_t pP[8][4];
        float rs0 = 0.f, rs1 = 0.f;
        #pragma unroll
        for (int t = 0; t < 8; t++) {
            float p00 = exp2f((sacc[2*t][0]   - nm0) * LOG2E);
            float p01 = exp2f((sacc[2*t][1]   - nm0) * LOG2E);
            float p02 = exp2f((sacc[2*t][2]   - nm1) * LOG2E);
            float p03 = exp2f((sacc[2*t][3]   - nm1) * LOG2E);
            float p10 = exp2f((sacc[2*t+1][0] - nm0) * LOG2E);
            float p11 = exp2f((sacc[2*t+1][1] - nm0) * LOG2E);
            float p12 = exp2f((sacc[2*t+1][2] - nm1) * LOG2E);
            float p13 = exp2f((sacc[2*t+1][3] - nm1) * LOG2E);
            rs0 += p00 + p01 + p10 + p11;
            rs1 += p02 + p03 + p12 + p13;
            __half2 h;
            h = __floats2half2_rn(p00, p01); pP[t][0] = *(uint32_t*)&h;
            h = __floats2half2_rn(p02, p03); pP[t][1] = *(uint32_t*)&h;
            h = __floats2half2_rn(p10, p11); pP[t][2] = *(uint32_t*)&h;
            h = __floats2half2_rn(p12, p13); pP[t][3] = *(uint32_t*)&h;
        }
        rs0 += __shfl_xor_sync(~0u, rs0, 1); rs0 += __shfl_xor_sync(~0u, rs0, 2);
        rs1 += __shfl_xor_sync(~0u, rs1, 1); rs1 += __shfl_xor_sync(~0u, rs1, 2);
        l0 = l0 * f0 + rs0; l1 = l1 * f1 + rs1;
        #pragma unroll
        for (int t = 0; t < 16; t++) {
            oacc[t][0] *= f0; oacc[t][1] *= f0;
            oacc[t][2] *= f1; oacc[t][3] *= f1;
        }

        const uint32_t tV = sb + VOFF + buf * 32768;
        #pragma unroll
        for (int t = 0; t < 8; t++) {
            #pragma unroll
            for (int g = 0; g < 8; g++) {
                int r = t * 16 + (lane & 7) + (lane & 8);
                int seg = (g & 3) * 2 + (lane >> 4);
                uint32_t addr = tV + (uint32_t)(g >> 2) * 16384 + r * 128 + ((seg ^ (r & 7)) << 4);
                uint32_t b0, b1, b2, b3;
                ldsm4t(b0, b1, b2, b3, addr);
                mma16816(oacc[2 * g],     pP[t], b0, b1);
                mma16816(oacc[2 * g + 1], pP[t], b2, b3);
            }
        }
        __syncthreads();
    }

    float inv0 = 1.f / l0, inv1 = 1.f / l1;
    size_t m = (size_t)qb * 128 + wid * 16 + (lane >> 2);
    size_t col0 = (size_t)head * 128 + (lane & 3) * 2;
    #pragma unroll
    for (int t = 0; t < 16; t++) {
        __half2 h0 = __floats2half2_rn(oacc[t][0] * inv0, oacc[t][1] * inv0);
        __half2 h1 = __floats2half2_rn(oacc[t][2] * inv1, oacc[t][3] * inv1);
        *(__half2*)&O[m * NN2 + col0 + t * 8]       = h0;
        *(__half2*)&O[(m + 8) * NN2 + col0 + t * 8] = h1;
    }
}

// ---------------- vectorized fp32 -> fp16 cast (same layout) ----------------
__global__ void cast_half(const float* __restrict__ in, __half* __restrict__ o, size_t n8) {
    size_t i = (size_t)blockIdx.x * 256 + threadIdx.x;
    if (i >= n8) return;
    float4 a = *(const float4*)&in[i * 8];
    float4 b = *(const float4*)&in[i * 8 + 4];
    __half2 h[4] = { __floats2half2_rn(a.x, a.y), __floats2half2_rn(a.z, a.w),
                     __floats2half2_rn(b.x, b.y), __floats2half2_rn(b.z, b.w) };
    *(uint2*)&o[i * 8]     = make_uint2(*(uint32_t*)&h[0], *(uint32_t*)&h[1]);
    *(uint2*)&o[i * 8 + 4] = make_uint2(*(uint32_t*)&h[2], *(uint32_t*)&h[3]);
}

// ---------------- mod = silu(vec) @ mod_w + mod_b  (k-split partials) ----------------
__global__ void mod_gemv(const float* __restrict__ vec,
                         const float* __restrict__ mod_w) {
    __shared__ float sv[HID / MSPLIT];
    int tid = threadIdx.x;
    int ks = blockIdx.y;
    int k0 = ks * (HID / MSPLIT);
    for (int i = tid; i < HID / MSPLIT; i += blockDim.x) {
        float a = vec[k0 + i];
        sv[i] = a / (1.f + __expf(-a));
    }
    __syncthreads();
    int j = blockIdx.x * blockDim.x + tid;
    float acc = 0.f;
    #pragma unroll 4
    for (int k = 0; k < HID / MSPLIT; k++)
        acc += sv[k] * mod_w[(size_t)(k0 + k) * (3 * HID) + j];
    g_modp[ks][j] = acc;
}
__global__ void mod_reduce(const float* __restrict__ mod_b) {
    int j = blockIdx.x * 256 + threadIdx.x;
    float s = mod_b[j];
    #pragma unroll
    for (int k = 0; k < MSPLIT; k++) s += g_modp[k][j];
    g_mod[j] = s;
}

// ---------------- layernorm + modulation -> fp16 ----------------
__global__ void ln_mod_kernel(const float* __restrict__ x,
                              const float* __restrict__ gamma,
                              const float* __restrict__ beta) {
    __shared__ float red[32];
    int l = blockIdx.x;
    const float* xr = x + (size_t)l * HID;
    float s = 0.f, s2 = 0.f;
    for (int i = threadIdx.x; i < HID; i += 256) {
        float v = xr[i];
        s += v; s2 += v * v;
    }
    int lane = threadIdx.x & 31, wid = threadIdx.x >> 5;
    #pragma unroll
    for (int o = 16; o; o >>= 1) { s += __shfl_down_sync(~0u, s, o); s2 += __shfl_down_sync(~0u, s2, o); }
    if (lane == 0) { red[wid] = s; red[wid + 8] = s2; }
    __syncthreads();
    float ts = 0.f, ts2 = 0.f;
    if (threadIdx.x < 8) { ts = red[threadIdx.x]; ts2 = red[threadIdx.x + 8]; }
    #pragma unroll
    for (int o = 4; o; o >>= 1) { ts += __shfl_down_sync(0xff, ts, o); ts2 += __shfl_down_sync(0xff, ts2, o); }
    if (threadIdx.x == 0) { red[0] = ts; red[1] = ts2; }
    __syncthreads();
    float mu = red[0] / HID;
    float var = red[1] / HID - mu * mu;
    float rsig = rsqrtf(var + EPSF);
    for (int i = threadIdx.x; i < HID; i += 256) {
        float lnv = (xr[i] - mu) * rsig * gamma[i] + beta[i];
        float v = (1.f + g_mod[HID + i]) * lnv + g_mod[i];
        g_xf[(size_t)l * HID + i] = __float2half_rn(v);
    }
}

// ---------------- rmsnorm + rope (q,k) -> fp16 [h][l][d] ----------------
__global__ void qkv_prep(const float* __restrict__ pe,
                         const float* __restrict__ q_scale,
                         const float* __restrict__ k_scale) {
    int l = blockIdx.x, hd = blockIdx.y, which = blockIdx.z;
    size_t base = (size_t)l * QK2 + (size_t)which * HID + (size_t)hd * DD;
    int d = threadIdx.x;
    float t = __half2float(g_hqk[base + d]);
    size_t oi = ((size_t)hd * LL + l) * DD + d;
    const float* sc = which ? k_scale : q_scale;
    __shared__ float red[4];
    float v = t * t;
    #pragma unroll
    for (int o = 16; o; o >>= 1) v += __shfl_down_sync(~0u, v, o);
    if ((d & 31) == 0) red[d >> 5] = v;
    __syncthreads();
    float ss = red[0] + red[1] + red[2] + red[3];
    float r = rsqrtf(ss / DD + EPSF);
    __shared__ float s[DD];
    s[d] = t * r * sc[d];
    __syncthreads();
    int i = d >> 1, j = d & 1;
    const float* p = pe + (((size_t)l * (DD / 2) + i) * 2 + j) * 2;
    float out = p[0] * s[2 * i] + p[1] * s[2 * i + 1];
    if (which == 0) out *= 0.08838834764831845f;   // fold D^-0.5 into q
    if (which) g_kf[oi] = __float2half_rn(out);
    else       g_qf[oi] = __float2half_rn(out);
}

// ---------------- launcher ----------------
extern "C" void kernel_launch(void* const* d_in, const int* in_sizes, int n_in,
                              void* d_out, int out_size) {
    const float* x       = (const float*)d_in[0];
    const float* vec     = (const float*)d_in[1];
    const float* pe      = (const float*)d_in[2];
    const float* mod_w   = (const float*)d_in[3];
    const float* mod_b   = (const float*)d_in[4];
    const float* gamma   = (const float*)d_in[5];
    const float* beta    = (const float*)d_in[6];
    const float* w1      = (const float*)d_in[7];
    const float* b1      = (const float*)d_in[8];
    const float* q_scale = (const float*)d_in[9];
    const float* k_scale = (const float*)d_in[10];
    const float* w2      = (const float*)d_in[11];
    const float* b2      = (const float*)d_in[12];
    float* out = (float*)d_out;

    float *p_part;
    __half *p_xf, *p_w1f, *p_hq, *p_qf, *p_kf, *p_vf, *p_ocf, *p_w2f;
    cudaGetSymbolAddress((void**)&p_part, g_part);
    cudaGetSymbolAddress((void**)&p_xf, g_xf);
    cudaGetSymbolAddress((void**)&p_w1f, g_w1f);
    cudaGetSymbolAddress((void**)&p_hq, g_hqk);
    cudaGetSymbolAddress((void**)&p_qf, g_qf);
    cudaGetSymbolAddress((void**)&p_kf, g_kf);
    cudaGetSymbolAddress((void**)&p_vf, g_vf);
    cudaGetSymbolAddress((void**)&p_ocf, g_ocf);
    cudaGetSymbolAddress((void**)&p_w2f, g_w2f);

    const int SMEM = 2 * (256 + 128) * 256;   // 196608
    const int FSMEM = 163840;
    cudaFuncSetAttribute((const void*)hgemm<0>, cudaFuncAttributeMaxDynamicSharedMemorySize, SMEM);
    cudaFuncSetAttribute((const void*)hgemm<6>, cudaFuncAttributeMaxDynamicSharedMemorySize, SMEM);
    cudaFuncSetAttribute((const void*)flash_attn, cudaFuncAttributeMaxDynamicSharedMemorySize, FSMEM);

    // lazy-init side stream + events (handles only; captured graph identical every call)
    static cudaStream_t s1 = nullptr;
    static cudaEvent_t e_fork = nullptr, e_w1 = nullptr, e_w2 = nullptr;
    if (!s1) {
        cudaStreamCreate(&s1);
        cudaEventCreateWithFlags(&e_fork, cudaEventDisableTiming);
        cudaEventCreateWithFlags(&e_w1, cudaEventDisableTiming);
        cudaEventCreateWithFlags(&e_w2, cudaEventDisableTiming);
    }

    // fork side stream into capture
    cudaEventRecord(e_fork, 0);
    cudaStreamWaitEvent(s1, e_fork, 0);

    // side stream: weight casts
    cast_half<<<(unsigned)(((size_t)HID * NN1 / 8 + 255) / 256), 256, 0, s1>>>(w1, p_w1f, (size_t)HID * NN1 / 8);
    cudaEventRecord(e_w1, s1);
    cast_half<<<(unsigned)(((size_t)NN2 * HID / 8 + 255) / 256), 256, 0, s1>>>(w2, p_w2f, (size_t)NN2 * HID / 8);
    cudaEventRecord(e_w2, s1);

    // main stream
    mod_gemv<<<dim3((3 * HID) / 256, MSPLIT), 256>>>(vec, mod_w);
    mod_reduce<<<(3 * HID) / 256, 256>>>(mod_b);
    ln_mod_kernel<<<LL, 256>>>(x, gamma, beta);

    cudaStreamWaitEvent(0, e_w1, 0);
    // gemm1: q,k -> fp16 g_hqk; v -> g_vf; mlp -> gelu -> g_ocf (all fused)
    hgemm<6><<<dim3(LL / 256, NN1 / 128, 1), 256, SMEM>>>(
        p_xf, HID, 0, p_w1f, NN1, 0,
        nullptr, 0, 0, HID, b1, p_ocf, NN2, p_vf, p_hq);
    qkv_prep<<<dim3(LL, HH, 2), 128>>>(pe, q_scale, k_scale);
    flash_attn<<<dim3(LL / 128, HH), 256, FSMEM>>>(p_qf, p_kf, p_vf, p_ocf);

    cudaStreamWaitEvent(0, e_w2, 0);
    // gemm2 split-K=3: partials = oc @ w2
    hgemm<0><<<dim3(LL / 256, HID / 128, KSPLIT), 256, SMEM>>>(
        p_ocf, NN2, KCHUNK, p_w2f, HID, (long)KCHUNK * HID,
        p_part, HID, (long)LL * HID, KCHUNK, nullptr, nullptr, 0, nullptr, nullptr);
    reduce_out<<<((size_t)LL * HID / 4) / 256, 256>>>(x, b2, out);
}

// round 13
// speedup vs baseline: 10.5520x; 1.0087x over previous
#include <cuda_runtime.h>
#include <cuda_fp16.h>
#include <math.h>
#include <stdint.h>

// Problem constants
#define LL   2048
#define HH   24
#define DD   128
#define HID  3072
#define MLPD 12288
#define NN1  21504   // 3*HID + MLP
#define NN2  15360   // HID + MLP
#define QKV  9216    // 3*HID
#define QK2  6144    // 2*HID
#define EPSF 1e-6f
#define LOG2E 1.4426950408889634f
#define KSPLIT 3
#define KCHUNK (NN2 / KSPLIT)   // 5120
#define MSPLIT 4                // mod_gemv k-split

// ---------------- scratch (static device arrays; no allocs) ----------------
__device__ float g_mod[3 * HID];
__device__ float g_modp[MSPLIT][3 * HID];
__device__ __half g_xf[(size_t)LL * HID];              // x_mod fp16
__device__ __half g_w1f[(size_t)HID * NN1];            // w1 fp16 [K][N]
__device__ __half g_hqk[(size_t)LL * QK2];             // gemm1 q|k out fp16
__device__ __half g_qf[(size_t)HH * LL * DD];          // q (pre-scaled by D^-0.5)
__device__ __half g_kf[(size_t)HH * LL * DD];
__device__ __half g_vf[(size_t)HH * LL * DD];          // v fp16 [h][l][d]
__device__ __half g_ocf[(size_t)LL * NN2];             // attn | gelu(mlp) fp16
__device__ __half g_w2f[(size_t)NN2 * HID];            // w2 fp16 [K][N]
__device__ float  g_part[(size_t)KSPLIT * LL * HID];   // split-K partials

// ---------------- helpers ----------------
__device__ __forceinline__ uint32_t smem_u32(const void* p) {
    uint32_t a;
    asm("{ .reg .u64 t; cvta.to.shared.u64 t, %1; cvt.u32.u64 %0, t; }" : "=r"(a) : "l"(p));
    return a;
}
__device__ __forceinline__ void cpasync16(uint32_t dst, const void* src) {
    asm volatile("cp.async.cg.shared.global [%0], [%1], 16;" :: "r"(dst), "l"(src));
}
__device__ __forceinline__ void cp_commit() { asm volatile("cp.async.commit_group;"); }
__device__ __forceinline__ void cp_wait1()  { asm volatile("cp.async.wait_group 1;" ::: "memory"); }
__device__ __forceinline__ void cp_wait0()  { asm volatile("cp.async.wait_group 0;" ::: "memory"); }

__device__ __forceinline__ void ldsm4(uint32_t& r0, uint32_t& r1, uint32_t& r2, uint32_t& r3, uint32_t a) {
    asm volatile("ldmatrix.sync.aligned.m8n8.x4.shared.b16 {%0,%1,%2,%3}, [%4];"
                 : "=r"(r0), "=r"(r1), "=r"(r2), "=r"(r3) : "r"(a));
}
__device__ __forceinline__ void ldsm4t(uint32_t& r0, uint32_t& r1, uint32_t& r2, uint32_t& r3, uint32_t a) {
    asm volatile("ldmatrix.sync.aligned.m8n8.x4.trans.shared.b16 {%0,%1,%2,%3}, [%4];"
                 : "=r"(r0), "=r"(r1), "=r"(r2), "=r"(r3) : "r"(a));
}
__device__ __forceinline__ void mma16816(float* c, const uint32_t* a, uint32_t b0, uint32_t b1) {
    asm volatile(
        "mma.sync.aligned.m16n8k16.row.col.f32.f16.f16.f32 "
        "{%0,%1,%2,%3},{%4,%5,%6,%7},{%8,%9},{%0,%1,%2,%3};\n"
        : "+f"(c[0]), "+f"(c[1]), "+f"(c[2]), "+f"(c[3])
        : "r"(a[0]), "r"(a[1]), "r"(a[2]), "r"(a[3]), "r"(b0), "r"(b1));
}
__device__ __forceinline__ float gelu_f(float v) {
    float c = 0.7978845608028654f * (v + 0.044715f * v * v * v);
    return 0.5f * v * (1.f + tanhf(c));
}

// ---------------- fp16 HMMA GEMM ----------------
// A [M][K] row-major fp16; B [K][N] (k-major) fp16 via ldmatrix.trans.
// CTA tile 256(m) x 128(n), 512 threads = 16 warps (4m x 4n, warp tile 64x32).
// K-chunk 128, double-buffered cp.async, swizzled smem.
// EPI: 0 plain fp32 | 6 gemm1 mixed: n<QK2 -> +bias fp16 Hqk; [QK2,QKV) -> +bias fp16 V; >=QKV -> gelu(+bias) fp16 C2
template<int EPI>
__global__ void __launch_bounds__(512, 1) hgemm(
    const __half* __restrict__ A, size_t lda, long sA,
    const __half* __restrict__ B, size_t ldb, long sB,
    float* __restrict__ C, size_t ldc, long sC, int K,
    const float* __restrict__ bias,
    __half* __restrict__ C2, size_t ldc2,
    __half* __restrict__ V, __half* __restrict__ Hqk)
{
    extern __shared__ char smem[];
    constexpr int TILEA = 256 * 256;     // 64 KB
    constexpr int TILEB = 128 * 256;     // 32 KB
    constexpr int STAGE = TILEA + TILEB; // 96 KB
    const uint32_t sb = smem_u32(smem);
    const int tid = threadIdx.x, wid = tid >> 5, lane = tid & 31;
    const int wm = wid & 3, wn = wid >> 2;    // 4m x 4n

    A += (long)blockIdx.z * sA;
    B += (long)blockIdx.z * sB;
    C += (long)blockIdx.z * sC;

    const size_t row0 = (size_t)blockIdx.x * 256;
    const size_t col0 = (size_t)blockIdx.y * 128;
    const __half* baseA = A + row0 * lda;
    const __half* baseB = B + col0;          // [K][N]: advance rows by k

    auto load_stage = [&](int s) {
        const uint32_t st = sb + (uint32_t)(s & 1) * STAGE;
        const int ko = s * 128;
        #pragma unroll
        for (int j = 0; j < 8; j++) {
            int c = tid + j * 512;
            int row = c >> 4, seg = c & 15;
            uint32_t dst = st + row * 256 + ((seg ^ (row & 7)) << 4);
            cpasync16(dst, (const char*)(baseA + ko + (size_t)row * lda) + seg * 16);
        }
        #pragma unroll
        for (int j = 0; j < 4; j++) {
            int c = tid + j * 512;
            int row = c >> 4, seg = c & 15;
            uint32_t dst = st + TILEA + row * 256 + ((seg ^ (row & 7)) << 4);
            cpasync16(dst, (const char*)(baseB + (size_t)(ko + row) * ldb) + seg * 16);
        }
    };

    float acc[4][4][4] = {};
    const int S = K >> 7;

    load_stage(0); cp_commit();
    for (int s = 0; s < S; s++) {
        cp_wait0();
        __syncthreads();
        if (s + 1 < S) { load_stage(s + 1); cp_commit(); }

        const uint32_t st = sb + (uint32_t)(s & 1) * STAGE;
        const uint32_t tA = st, tB = st + TILEA;

        #pragma unroll
        for (int kg = 0; kg < 8; kg++) {
            uint32_t af[4][4];
            {
                int arow = wm * 64 + (lane & 15);
                int ak8 = kg * 2 + (lane >> 4);
                #pragma unroll
                for (int im = 0; im < 4; im++) {
                    int r = arow + im * 16;
                    uint32_t off = r * 256 + ((ak8 ^ (r & 7)) << 4);
                    ldsm4(af[im][0], af[im][1], af[im][2], af[im][3], tA + off);
                }
            }
            int brow = kg * 16 + (lane & 7) + (lane & 8);
            #pragma unroll
            for (int g = 0; g < 2; g++) {
                int seg = wn * 4 + g * 2 + (lane >> 4);
                uint32_t off = brow * 256 + ((seg ^ (brow & 7)) << 4);
                uint32_t b0, b1, b2, b3;
                ldsm4t(b0, b1, b2, b3, tB + off);
                #pragma unroll
                for (int im = 0; im < 4; im++) {
                    mma16816(acc[im][2 * g],     af[im], b0, b1);
                    mma16816(acc[im][2 * g + 1], af[im], b2, b3);
                }
            }
        }
    }

    const int mode = (EPI == 6) ? ((col0 >= QKV) ? 2 : (col0 >= QK2 ? 1 : 0)) : 3;
    #pragma unroll
    for (int im = 0; im < 4; im++) {
        #pragma unroll
        for (int in = 0; in < 4; in++) {
            size_t m0 = row0 + wm * 64 + im * 16 + (lane >> 2);
            size_t n  = col0 + wn * 32 + in * 8 + (lane & 3) * 2;
            #pragma unroll
            for (int half = 0; half < 2; half++) {
                size_t m = m0 + half * 8;
                float v0 = acc[im][in][half * 2 + 0];
                float v1 = acc[im][in][half * 2 + 1];
                if (mode == 3) {
                    *(float2*)&C[m * ldc + n] = make_float2(v0, v1);
                } else if (mode == 0) {
                    v0 += bias[n]; v1 += bias[n + 1];
                    *(__half2*)&Hqk[m * QK2 + n] = __floats2half2_rn(v0, v1);
                } else if (mode == 1) {
                    v0 += bias[n]; v1 += bias[n + 1];
                    size_t head = (n - QK2) >> 7, d = (n - QK2) & 127;
                    *(__half2*)&V[(head * LL + m) * DD + d] = __floats2half2_rn(v0, v1);
                } else {
                    v0 += bias[n]; v1 += bias[n + 1];
                    __half2 h = __floats2half2_rn(gelu_f(v0), gelu_f(v1));
                    *(__half2*)&C2[m * ldc2 + (n - QK2)] = h;
                }
            }
        }
    }
}

// ---------------- split-K reduce: out = x + gate*(p0+p1+p2+b2) ----------------
__global__ void reduce_out(const float* __restrict__ x, const float* __restrict__ b2,
                           float* __restrict__ out) {
    size_t i = ((size_t)blockIdx.x * 256 + threadIdx.x) * 4;
    int n = (int)(i % HID);
    float4 p0 = *(const float4*)&g_part[i];
    float4 p1 = *(const float4*)&g_part[(size_t)LL * HID + i];
    float4 p2 = *(const float4*)&g_part[(size_t)2 * LL * HID + i];
    float4 xb = *(const float4*)&x[i];
    float4 bb = *(const float4*)&b2[n];
    float4 gg = *(const float4*)&g_mod[2 * HID + n];
    float4 o;
    o.x = xb.x + gg.x * (p0.x + p1.x + p2.x + bb.x);
    o.y = xb.y + gg.y * (p0.y + p1.y + p2.y + bb.y);
    o.z = xb.z + gg.z * (p0.z + p1.z + p2.z + bb.z);
    o.w = xb.w + gg.w * (p0.w + p1.w + p2.w + bb.w);
    *(float4*)&out[i] = o;
}

// ---------------- fused flash attention ----------------
__global__ void __launch_bounds__(256, 1) flash_attn(
    const __half* __restrict__ Qg, const __half* __restrict__ Kg,
    const __half* __restrict__ Vg, __half* __restrict__ O)
{
    extern __shared__ char smem[];
    const uint32_t sb = smem_u32(smem);
    const int tid = threadIdx.x, wid = tid >> 5, lane = tid & 31;
    const int qb = blockIdx.x, head = blockIdx.y;
    constexpr uint32_t KOFF = 32768, VOFF = 98304;

    const __half* Qh = Qg + ((size_t)head * LL + (size_t)qb * 128) * DD;
    const __half* Kh = Kg + (size_t)head * LL * DD;
    const __half* Vh = Vg + (size_t)head * LL * DD;

    auto load_tile = [&](uint32_t dst, const __half* g) {
        #pragma unroll
        for (int i = 0; i < 8; i++) {
            int c = tid + i * 256;
            int row = c >> 4, ds = c & 15;
            uint32_t off = (uint32_t)(ds >> 3) * 16384 + row * 128 + (((ds & 7) ^ (row & 7)) << 4);
            cpasync16(dst + off, (const char*)g + (size_t)row * 256 + ds * 16);
        }
    };

    load_tile(sb, Qh); cp_commit();
    load_tile(sb + KOFF, Kh); load_tile(sb + VOFF, Vh); cp_commit();
    cp_wait1();
    __syncthreads();

    uint32_t qfr[8][4];
    {
        int r = wid * 16 + (lane & 15);
        #pragma unroll
        for (int ks = 0; ks < 8; ks++) {
            int seg = (ks & 3) * 2 + (lane >> 4);
            uint32_t addr = sb + (uint32_t)(ks >> 2) * 16384 + r * 128 + ((seg ^ (r & 7)) << 4);
            ldsm4(qfr[ks][0], qfr[ks][1], qfr[ks][2], qfr[ks][3], addr);
        }
    }

    float oacc[16][4] = {};
    float m0 = -1e30f, m1 = -1e30f, l0 = 0.f, l1 = 0.f;

    for (int j = 0; j < 16; j++) {
        const int buf = j & 1;
        if (j + 1 < 16) {
            load_tile(sb + KOFF + (buf ^ 1) * 32768, Kh + (size_t)(j + 1) * 128 * DD);
            load_tile(sb + VOFF + (buf ^ 1) * 32768, Vh + (size_t)(j + 1) * 128 * DD);
            cp_commit(); cp_wait1();
        } else cp_wait0();
        __syncthreads();

        float sacc[16][4] = {};
        const uint32_t tK = sb + KOFF + buf * 32768;
        #pragma unroll
        for (int ks = 0; ks < 8; ks++) {
            #pragma unroll
            for (int g = 0; g < 8; g++) {
                int r = g * 16 + (lane & 7) + ((lane >> 4) << 3);
                int seg = (ks & 3) * 2 + ((lane >> 3) & 1);
                uint32_t addr = tK + (uint32_t)(ks >> 2) * 16384 + r * 128 + ((seg ^ (r & 7)) << 4);
                uint32_t b0, b1, b2, b3;
                ldsm4(b0, b1, b2, b3, addr);
                mma16816(sacc[2 * g],     qfr[ks], b0, b1);
                mma16816(sacc[2 * g + 1], qfr[ks], b2, b3);
            }
        }

        float tm0 = -1e30f, tm1 = -1e30f;
        #pragma unroll
        for (int t = 0; t < 16; t++) {
            tm0 = fmaxf(tm0, fmaxf(sacc[t][0], sacc[t][1]));
            tm1 = fmaxf(tm1, fmaxf(sacc[t][2], sacc[t][3]));
        }
        tm0 = fmaxf(tm0, __shfl_xor_sync(~0u, tm0, 1));
        tm0 = fmaxf(tm0, __shfl_xor_sync(~0u, tm0, 2));
        tm1 = fmaxf(tm1, __shfl_xor_sync(~0u, tm1, 1));
        tm1 = fmaxf(tm1, __shfl_xor_sync(~0u, tm1, 2));
        float nm0 = fmaxf(m0, tm0), nm1 = fmaxf(m1, tm1);
        float f0 = exp2f((m0 - nm0) * LOG2E), f1 = exp2f((m1 - nm1) * LOG2E);
        m0 = nm0; m1 = nm1;

        uint32_t pP[8][4];
        float rs0 = 0.f, rs1 = 0.f;
        #pragma unroll
        for (int t = 0; t < 8; t++) {
            float p00 = exp2f((sacc[2*t][0]   - nm0) * LOG2E);
            float p01 = exp2f((sacc[2*t][1]   - nm0) * LOG2E);
            float p02 = exp2f((sacc[2*t][2]   - nm1) * LOG2E);
            float p03 = exp2f((sacc[2*t][3]   - nm1) * LOG2E);
            float p10 = exp2f((sacc[2*t+1][0] - nm0) * LOG2E);
            float p11 = exp2f((sacc[2*t+1][1] - nm0) * LOG2E);
            float p12 = exp2f((sacc[2*t+1][2] - nm1) * LOG2E);
            float p13 = exp2f((sacc[2*t+1][3] - nm1) * LOG2E);
            rs0 += p00 + p01 + p10 + p11;
            rs1 += p02 + p03 + p12 + p13;
            __half2 h;
            h = __floats2half2_rn(p00, p01); pP[t][0] = *(uint32_t*)&h;
            h = __floats2half2_rn(p02, p03); pP[t][1] = *(uint32_t*)&h;
            h = __floats2half2_rn(p10, p11); pP[t][2] = *(uint32_t*)&h;
            h = __floats2half2_rn(p12, p13); pP[t][3] = *(uint32_t*)&h;
        }
        rs0 += __shfl_xor_sync(~0u, rs0, 1); rs0 += __shfl_xor_sync(~0u, rs0, 2);
        rs1 += __shfl_xor_sync(~0u, rs1, 1); rs1 += __shfl_xor_sync(~0u, rs1, 2);
        l0 = l0 * f0 + rs0; l1 = l1 * f1 + rs1;
        #pragma unroll
        for (int t = 0; t < 16; t++) {
            oacc[t][0] *= f0; oacc[t][1] *= f0;
            oacc[t][2] *= f1; oacc[t][3] *= f1;
        }

        const uint32_t tV = sb + VOFF + buf * 32768;
        #pragma unroll
        for (int t = 0; t < 8; t++) {
            #pragma unroll
            for (int g = 0; g < 8; g++) {
                int r = t * 16 + (lane & 7) + (lane & 8);
                int seg = (g & 3) * 2 + (lane >> 4);
                uint32_t addr = tV + (uint32_t)(g >> 2) * 16384 + r * 128 + ((seg ^ (r & 7)) << 4);
                uint32_t b0, b1, b2, b3;
                ldsm4t(b0, b1, b2, b3, addr);
                mma16816(oacc[2 * g],     pP[t], b0, b1);
                mma16816(oacc[2 * g + 1], pP[t], b2, b3);
            }
        }
        __syncthreads();
    }

    float inv0 = 1.f / l0, inv1 = 1.f / l1;
    size_t m = (size_t)qb * 128 + wid * 16 + (lane >> 2);
    size_t col0 = (size_t)head * 128 + (lane & 3) * 2;
    #pragma unroll
    for (int t = 0; t < 16; t++) {
        __half2 h0 = __floats2half2_rn(oacc[t][0] * inv0, oacc[t][1] * inv0);
        __half2 h1 = __floats2half2_rn(oacc[t][2] * inv1, oacc[t][3] * inv1);
        *(__half2*)&O[m * NN2 + col0 + t * 8]       = h0;
        *(__half2*)&O[(m + 8) * NN2 + col0 + t * 8] = h1;
    }
}

// ---------------- vectorized fp32 -> fp16 cast (same layout) ----------------
__global__ void cast_half(const float* __restrict__ in, __half* __restrict__ o, size_t n8) {
    size_t i = (size_t)blockIdx.x * 256 + threadIdx.x;
    if (i >= n8) return;
    float4 a = *(const float4*)&in[i * 8];
    float4 b = *(const float4*)&in[i * 8 + 4];
    __half2 h[4] = { __floats2half2_rn(a.x, a.y), __floats2half2_rn(a.z, a.w),
                     __floats2half2_rn(b.x, b.y), __floats2half2_rn(b.z, b.w) };
    *(uint2*)&o[i * 8]     = make_uint2(*(uint32_t*)&h[0], *(uint32_t*)&h[1]);
    *(uint2*)&o[i * 8 + 4] = make_uint2(*(uint32_t*)&h[2], *(uint32_t*)&h[3]);
}

// ---------------- mod = silu(vec) @ mod_w + mod_b  (k-split partials) ----------------
__global__ void mod_gemv(const float* __restrict__ vec,
                         const float* __restrict__ mod_w) {
    __shared__ float sv[HID / MSPLIT];
    int tid = threadIdx.x;
    int ks = blockIdx.y;
    int k0 = ks * (HID / MSPLIT);
    for (int i = tid; i < HID / MSPLIT; i += blockDim.x) {
        float a = vec[k0 + i];
        sv[i] = a / (1.f + __expf(-a));
    }
    __syncthreads();
    int j = blockIdx.x * blockDim.x + tid;
    float acc = 0.f;
    #pragma unroll 4
    for (int k = 0; k < HID / MSPLIT; k++)
        acc += sv[k] * mod_w[(size_t)(k0 + k) * (3 * HID) + j];
    g_modp[ks][j] = acc;
}
__global__ void mod_reduce(const float* __restrict__ mod_b) {
    int j = blockIdx.x * 256 + threadIdx.x;
    float s = mod_b[j];
    #pragma unroll
    for (int k = 0; k < MSPLIT; k++) s += g_modp[k][j];
    g_mod[j] = s;
}

// ---------------- layernorm + modulation -> fp16 ----------------
__global__ void ln_mod_kernel(const float* __restrict__ x,
                              const float* __restrict__ gamma,
                              const float* __restrict__ beta) {
    __shared__ float red[32];
    int l = blockIdx.x;
    const float* xr = x + (size_t)l * HID;
    float s = 0.f, s2 = 0.f;
    for (int i = threadIdx.x; i < HID; i += 256) {
        float v = xr[i];
        s += v; s2 += v * v;
    }
    int lane = threadIdx.x & 31, wid = threadIdx.x >> 5;
    #pragma unroll
    for (int o = 16; o; o >>= 1) { s += __shfl_down_sync(~0u, s, o); s2 += __shfl_down_sync(~0u, s2, o); }
    if (lane == 0) { red[wid] = s; red[wid + 8] = s2; }
    __syncthreads();
    float ts = 0.f, ts2 = 0.f;
    if (threadIdx.x < 8) { ts = red[threadIdx.x]; ts2 = red[threadIdx.x + 8]; }
    #pragma unroll
    for (int o = 4; o; o >>= 1) { ts += __shfl_down_sync(0xff, ts, o); ts2 += __shfl_down_sync(0xff, ts2, o); }
    if (threadIdx.x == 0) { red[0] = ts; red[1] = ts2; }
    __syncthreads();
    float mu = red[0] / HID;
    float var = red[1] / HID - mu * mu;
    float rsig = rsqrtf(var + EPSF);
    for (int i = threadIdx.x; i < HID; i += 256) {
        float lnv = (xr[i] - mu) * rsig * gamma[i] + beta[i];
        float v = (1.f + g_mod[HID + i]) * lnv + g_mod[i];
        g_xf[(size_t)l * HID + i] = __float2half_rn(v);
    }
}

// ---------------- rmsnorm + rope (q,k) -> fp16 [h][l][d] ----------------
__global__ void qkv_prep(const float* __restrict__ pe,
                         const float* __restrict__ q_scale,
                         const float* __restrict__ k_scale) {
    int l = blockIdx.x, hd = blockIdx.y, which = blockIdx.z;
    size_t base = (size_t)l * QK2 + (size_t)which * HID + (size_t)hd * DD;
    int d = threadIdx.x;
    float t = __half2float(g_hqk[base + d]);
    size_t oi = ((size_t)hd * LL + l) * DD + d;
    const float* sc = which ? k_scale : q_scale;
    __shared__ float red[4];
    float v = t * t;
    #pragma unroll
    for (int o = 16; o; o >>= 1) v += __shfl_down_sync(~0u, v, o);
    if ((d & 31) == 0) red[d >> 5] = v;
    __syncthreads();
    float ss = red[0] + red[1] + red[2] + red[3];
    float r = rsqrtf(ss / DD + EPSF);
    __shared__ float s[DD];
    s[d] = t * r * sc[d];
    __syncthreads();
    int i = d >> 1, j = d & 1;
    const float* p = pe + (((size_t)l * (DD / 2) + i) * 2 + j) * 2;
    float out = p[0] * s[2 * i] + p[1] * s[2 * i + 1];
    if (which == 0) out *= 0.08838834764831845f;   // fold D^-0.5 into q
    if (which) g_kf[oi] = __float2half_rn(out);
    else       g_qf[oi] = __float2half_rn(out);
}

// ---------------- launcher ----------------
extern "C" void kernel_launch(void* const* d_in, const int* in_sizes, int n_in,
                              void* d_out, int out_size) {
    const float* x       = (const float*)d_in[0];
    const float* vec     = (const float*)d_in[1];
    const float* pe      = (const float*)d_in[2];
    const float* mod_w   = (const float*)d_in[3];
    const float* mod_b   = (const float*)d_in[4];
    const float* gamma   = (const float*)d_in[5];
    const float* beta    = (const float*)d_in[6];
    const float* w1      = (const float*)d_in[7];
    const float* b1      = (const float*)d_in[8];
    const float* q_scale = (const float*)d_in[9];
    const float* k_scale = (const float*)d_in[10];
    const float* w2      = (const float*)d_in[11];
    const float* b2      = (const float*)d_in[12];
    float* out = (float*)d_out;

    float *p_part;
    __half *p_xf, *p_w1f, *p_hq, *p_qf, *p_kf, *p_vf, *p_ocf, *p_w2f;
    cudaGetSymbolAddress((void**)&p_part, g_part);
    cudaGetSymbolAddress((void**)&p_xf, g_xf);
    cudaGetSymbolAddress((void**)&p_w1f, g_w1f);
    cudaGetSymbolAddress((void**)&p_hq, g_hqk);
    cudaGetSymbolAddress((void**)&p_qf, g_qf);
    cudaGetSymbolAddress((void**)&p_kf, g_kf);
    cudaGetSymbolAddress((void**)&p_vf, g_vf);
    cudaGetSymbolAddress((void**)&p_ocf, g_ocf);
    cudaGetSymbolAddress((void**)&p_w2f, g_w2f);

    const int SMEM = 2 * (256 + 128) * 256;   // 196608
    const int FSMEM = 163840;
    cudaFuncSetAttribute((const void*)hgemm<0>, cudaFuncAttributeMaxDynamicSharedMemorySize, SMEM);
    cudaFuncSetAttribute((const void*)hgemm<6>, cudaFuncAttributeMaxDynamicSharedMemorySize, SMEM);
    cudaFuncSetAttribute((const void*)flash_attn, cudaFuncAttributeMaxDynamicSharedMemorySize, FSMEM);

    // lazy-init side stream + events (handles only; captured graph identical every call)
    static cudaStream_t s1 = nullptr;
    static cudaEvent_t e_fork = nullptr, e_w1 = nullptr, e_w2 = nullptr;
    if (!s1) {
        cudaStreamCreate(&s1);
        cudaEventCreateWithFlags(&e_fork, cudaEventDisableTiming);
        cudaEventCreateWithFlags(&e_w1, cudaEventDisableTiming);
        cudaEventCreateWithFlags(&e_w2, cudaEventDisableTiming);
    }

    // fork side stream into capture
    cudaEventRecord(e_fork, 0);
    cudaStreamWaitEvent(s1, e_fork, 0);

    // side stream: weight casts
    cast_half<<<(unsigned)(((size_t)HID * NN1 / 8 + 255) / 256), 256, 0, s1>>>(w1, p_w1f, (size_t)HID * NN1 / 8);
    cudaEventRecord(e_w1, s1);
    cast_half<<<(unsigned)(((size_t)NN2 * HID / 8 + 255) / 256), 256, 0, s1>>>(w2, p_w2f, (size_t)NN2 * HID / 8);
    cudaEventRecord(e_w2, s1);

    // main stream
    mod_gemv<<<dim3((3 * HID) / 256, MSPLIT), 256>>>(vec, mod_w);
    mod_reduce<<<(3 * HID) / 256, 256>>>(mod_b);
    ln_mod_kernel<<<LL, 256>>>(x, gamma, beta);

    cudaStreamWaitEvent(0, e_w1, 0);
    // gemm1: q,k -> fp16 g_hqk; v -> g_vf; mlp -> gelu -> g_ocf (all fused)
    hgemm<6><<<dim3(LL / 256, NN1 / 128, 1), 512, SMEM>>>(
        p_xf, HID, 0, p_w1f, NN1, 0,
        nullptr, 0, 0, HID, b1, p_ocf, NN2, p_vf, p_hq);
    qkv_prep<<<dim3(LL, HH, 2), 128>>>(pe, q_scale, k_scale);
    flash_attn<<<dim3(LL / 128, HH), 256, FSMEM>>>(p_qf, p_kf, p_vf, p_ocf);

    cudaStreamWaitEvent(0, e_w2, 0);
    // gemm2 split-K=3: partials = oc @ w2
    hgemm<0><<<dim3(LL / 256, HID / 128, KSPLIT), 512, SMEM>>>(
        p_ocf, NN2, KCHUNK, p_w2f, HID, (long)KCHUNK * HID,
        p_part, HID, (long)LL * HID, KCHUNK, nullptr, nullptr, 0, nullptr, nullptr);
    reduce_out<<<((size_t)LL * HID / 4) / 256, 256>>>(x, b2, out);
}